// round 10
// baseline (speedup 1.0000x reference)
#include <cuda_runtime.h>
#include <cuda_fp16.h>
#include <math.h>
#include <stdint.h>

// Problem constants
#define BQ 2
#define LQ 2048
#define HQ 1024
#define NHQ 8
#define DQKQ 128
#define DVQ 256
#define VDIMQ 2048
#define MROWS (BQ*LQ)   // 4096
#define CHK 128         // retention chunk size
#define NCH (LQ/CHK)    // 16 chunks per sequence

#define QSCALE 0.08838834764831843f          // 128^-0.5
#define RF (-0.20762050593045852f)           // -2*log2(10000)/128

// ---------------------------------------------------------------------------
// Scratch (device globals)
// ---------------------------------------------------------------------------
__device__ float g_G[MROWS*VDIMQ];
__device__ float g_O[MROWS*VDIMQ];
__device__ float g_A[16*NCH*DQKQ*DVQ];            // per-chunk KV outer products

__device__ __half g_hs_hi[MROWS*HQ],  g_hs_lo[MROWS*HQ];
__device__ __half g_O_hi[MROWS*VDIMQ], g_O_lo[MROWS*VDIMQ];
__device__ __half g_Qhi[MROWS*HQ],    g_Qlo[MROWS*HQ];
__device__ __half g_Khi[MROWS*HQ];
__device__ __half g_Kdec[MROWS*HQ];               // K * lam^(CHK - r%CHK)
__device__ __half g_Vhi[MROWS*VDIMQ];
__device__ __half g_Shi[16*NCH*DQKQ*DVQ];
__device__ __half g_Slo[16*NCH*DQKQ*DVQ];
// fp16 weights, SAME layout as input ([K][N] row-major)
__device__ __half g_Wq16[HQ*HQ];
__device__ __half g_Wk16[HQ*HQ];
__device__ __half g_Wv16[HQ*VDIMQ];
__device__ __half g_Wg16[HQ*VDIMQ];
__device__ __half g_Wo16[VDIMQ*HQ];

// ---------------------------------------------------------------------------
// PTX helpers
// ---------------------------------------------------------------------------
__device__ __forceinline__ uint32_t smem_u32(const void* p) {
    uint32_t a;
    asm("{ .reg .u64 t; cvta.to.shared.u64 t, %1; cvt.u32.u64 %0, t; }"
        : "=r"(a) : "l"(p));
    return a;
}
__device__ __forceinline__ void ldgsts16(uint32_t dst, const void* src) {
    asm volatile("cp.async.cg.shared.global [%0], [%1], 16;" :: "r"(dst), "l"(src));
}
__device__ __forceinline__ void cp_commit() {
    asm volatile("cp.async.commit_group;" ::: "memory");
}
template<int N_>
__device__ __forceinline__ void cp_wait() {
    asm volatile("cp.async.wait_group %0;" :: "n"(N_) : "memory");
}
__device__ __forceinline__ void ldsm4(uint32_t* r, uint32_t addr) {
    asm volatile("ldmatrix.sync.aligned.m8n8.x4.shared.b16 {%0,%1,%2,%3}, [%4];"
        : "=r"(r[0]), "=r"(r[1]), "=r"(r[2]), "=r"(r[3]) : "r"(addr));
}
__device__ __forceinline__ void ldsm4t(uint32_t* r, uint32_t addr) {
    asm volatile("ldmatrix.sync.aligned.m8n8.x4.trans.shared.b16 {%0,%1,%2,%3}, [%4];"
        : "=r"(r[0]), "=r"(r[1]), "=r"(r[2]), "=r"(r[3]) : "r"(addr));
}
__device__ __forceinline__ void sts32(uint32_t addr, uint32_t v) {
    asm volatile("st.shared.b32 [%0], %1;" :: "r"(addr), "r"(v) : "memory");
}
__device__ __forceinline__ void mma_fp16(float* c, const uint32_t* a, const uint32_t* b) {
    asm volatile("mma.sync.aligned.m16n8k16.row.col.f32.f16.f16.f32 "
        "{%0,%1,%2,%3}, {%4,%5,%6,%7}, {%8,%9}, {%0,%1,%2,%3};"
        : "+f"(c[0]), "+f"(c[1]), "+f"(c[2]), "+f"(c[3])
        : "r"(a[0]), "r"(a[1]), "r"(a[2]), "r"(a[3]), "r"(b[0]), "r"(b[1]));
}
__device__ __forceinline__ uint32_t pack_h2(float a, float b) {
    __half2 t = __floats2half2_rn(a, b);
    return *(uint32_t*)&t;
}

// Swizzles: row stride in bytes; 16B chunk xor'd by (r&7)
#define SW128R(r, c) ((uint32_t)((r) * 128u + ((uint32_t)((c) ^ ((r) & 7)) << 4)))
#define SW256(r, c)  ((uint32_t)((r) * 256u + ((uint32_t)((c) ^ ((r) & 7)) << 4)))
#define SW512(r, c)  ((uint32_t)((r) * 512u + ((uint32_t)((c) ^ ((r) & 7)) << 4)))

// GEMM: CTA 128x256, K-chunk 64. Stage: Ahi 16K | Alo 16K | B (64k x 256n) 32K.
#define GST_AHI 0
#define GST_ALO 16384
#define GST_B   32768
#define G_STAGE 65536
#define TCG_SMEM (3 * G_STAGE)

// ---------------------------------------------------------------------------
// hs split -> fp16 hi/lo
// ---------------------------------------------------------------------------
__global__ void __launch_bounds__(256) split_kernel(const float* __restrict__ x,
                                                    __half* __restrict__ hi,
                                                    __half* __restrict__ lo,
                                                    int n4)
{
    int i = blockIdx.x * 256 + threadIdx.x;
    if (i >= n4) return;
    float4 v = ((const float4*)x)[i];
    __half h0 = __float2half(v.x), h1 = __float2half(v.y);
    __half h2 = __float2half(v.z), h3 = __float2half(v.w);
    __half l0 = __float2half(v.x - __half2float(h0));
    __half l1 = __float2half(v.y - __half2float(h1));
    __half l2 = __float2half(v.z - __half2float(h2));
    __half l3 = __float2half(v.w - __half2float(h3));
    ((__half2*)hi)[2*i]   = __half2(h0, h1);
    ((__half2*)hi)[2*i+1] = __half2(h2, h3);
    ((__half2*)lo)[2*i]   = __half2(l0, l1);
    ((__half2*)lo)[2*i+1] = __half2(l2, l3);
}

// ---------------------------------------------------------------------------
// Weight convert fp32 -> fp16 (same layout). One launch, 5 segments.
// Segment element starts (in units of 4 floats): 0, 256K, 512K, 1M, 1.5M; end 2M.
// ---------------------------------------------------------------------------
struct CvtPtrs { const float* src[5]; __half* dst[5]; int start4[6]; };

__global__ void __launch_bounds__(256) convert_multi(CvtPtrs cp)
{
    int f = blockIdx.x * 256 + threadIdx.x;    // index in float4 units
    int i = 0;
    #pragma unroll
    for (int j = 1; j < 5; j++) if (f >= cp.start4[j]) i = j;
    int local = f - cp.start4[i];
    float4 v = ((const float4*)cp.src[i])[local];
    __half2* d = (__half2*)cp.dst[i];
    d[2*local]   = __floats2half2_rn(v.x, v.y);
    d[2*local+1] = __floats2half2_rn(v.z, v.w);
}

// ---------------------------------------------------------------------------
// GEMM mainloop: CTA 128x256, 8 warps (64x64 warp tiles), K-chunk 64,
// 3-stage cp.async. A hi/lo row-major [M][K]; B fp16 [K][N] row-major,
// loaded rows=k and consumed via ldmatrix.trans.
// ---------------------------------------------------------------------------
struct GemmOps {
    const __half *Ah, *Al, *Bw;
    int K, Nstride, row0, ncol0;
};

__device__ __forceinline__ void gemm_mainloop(const GemmOps& op, uint32_t sbase,
                                              float acc[4][8][4])
{
    const int tid  = threadIdx.x;
    const int wid  = tid >> 5;
    const int lane = tid & 31;
    const int wm   = (wid & 1) * 64;
    const int wn   = (wid >> 1) * 64;
    const int K    = op.K;
    const int nchunks = K >> 6;

    auto load_chunk = [&](uint32_t sb, int k0) {
        #pragma unroll
        for (int t = 0; t < 4; t++) {          // A hi+lo: 128r x 8c
            int idx = tid + t * 256;           // 0..1023
            int r   = idx >> 3;
            int c   = idx & 7;
            uint32_t soff = SW128R(r, c);
            size_t aoff = (size_t)(op.row0 + r) * K + k0 + c * 8;
            ldgsts16(sb + GST_AHI + soff, op.Ah + aoff);
            ldgsts16(sb + GST_ALO + soff, op.Al + aoff);
        }
        #pragma unroll
        for (int t = 0; t < 8; t++) {          // B: 64 k-rows x 32 chunks
            int idx = tid + t * 256;           // 0..2047
            int r   = idx >> 5;
            int c   = idx & 31;
            ldgsts16(sb + GST_B + SW512(r, c),
                     op.Bw + (size_t)(k0 + r) * op.Nstride + op.ncol0 + c * 8);
        }
        cp_commit();
    };

    load_chunk(sbase, 0);
    if (nchunks > 1) load_chunk(sbase + G_STAGE, 64);

    uint32_t stage_of[3] = { sbase, sbase + G_STAGE, sbase + 2 * G_STAGE };

    for (int cch = 0; cch < nchunks; cch++) {
        const uint32_t sb = stage_of[cch % 3];
        if (cch + 2 < nchunks) {
            load_chunk(stage_of[(cch + 2) % 3], (cch + 2) * 64);
            cp_wait<2>();
        } else if (cch + 1 < nchunks) {
            cp_wait<1>();
        } else {
            cp_wait<0>();
        }
        __syncthreads();

        #pragma unroll
        for (int ks = 0; ks < 4; ks++) {
            uint32_t ahi[4][4], alo[4][4];
            #pragma unroll
            for (int mi = 0; mi < 4; mi++) {
                int r = wm + mi * 16 + (lane & 15);
                int c = ks * 2 + (lane >> 4);
                uint32_t ad = sb + GST_AHI + SW128R(r, c);
                ldsm4(ahi[mi], ad);
                ldsm4(alo[mi], ad + (GST_ALO - GST_AHI));
            }
            uint32_t bf[8][2];
            #pragma unroll
            for (int np = 0; np < 4; np++) {
                int row = ks * 16 + ((lane >> 3) & 1) * 8 + (lane & 7);
                int cn  = (wn + np * 16 + (lane >> 4) * 8) >> 3;
                uint32_t rh[4];
                ldsm4t(rh, sb + GST_B + SW512(row, cn));
                bf[2*np][0] = rh[0]; bf[2*np][1] = rh[1];
                bf[2*np+1][0] = rh[2]; bf[2*np+1][1] = rh[3];
            }
            #pragma unroll
            for (int mi = 0; mi < 4; mi++)
                #pragma unroll
                for (int nt = 0; nt < 8; nt++) {
                    mma_fp16(acc[mi][nt], ahi[mi], bf[nt]);
                    mma_fp16(acc[mi][nt], alo[mi], bf[nt]);
                }
        }
        __syncthreads();
    }
}

// ---------------------------------------------------------------------------
// Mega QKVG GEMM: grid (24, 32). cb<4: Q | cb<8: K (+Kdec) | cb<16: V | else G
// ---------------------------------------------------------------------------
__global__ void __launch_bounds__(256) qkvg_gemm()
{
    extern __shared__ char smem[];
    const uint32_t sbase = smem_u32(smem);
    const int tid  = threadIdx.x;
    const int wid  = tid >> 5;
    const int lane = tid & 31;
    const int row0 = blockIdx.y * 128;
    const int cb   = blockIdx.x;
    const int wm   = (wid & 1) * 64;
    const int wn   = (wid >> 1) * 64;

    int mode, lcol0, nstride;
    const __half* Bw;
    if (cb < 4)       { mode = 0; lcol0 = cb * 256;        Bw = g_Wq16; nstride = HQ; }
    else if (cb < 8)  { mode = 1; lcol0 = (cb - 4) * 256;  Bw = g_Wk16; nstride = HQ; }
    else if (cb < 16) { mode = 2; lcol0 = (cb - 8) * 256;  Bw = g_Wv16; nstride = VDIMQ; }
    else              { mode = 3; lcol0 = (cb - 16) * 256; Bw = g_Wg16; nstride = VDIMQ; }

    float acc[4][8][4];
    #pragma unroll
    for (int mi = 0; mi < 4; mi++)
        #pragma unroll
        for (int nt = 0; nt < 8; nt++)
            #pragma unroll
            for (int e = 0; e < 4; e++) acc[mi][nt][e] = 0.0f;

    GemmOps op{ g_hs_hi, g_hs_lo, Bw, HQ, nstride, row0, lcol0 };
    gemm_mainloop(op, sbase, acc);

    #pragma unroll
    for (int mi = 0; mi < 4; mi++) {
        const int row = row0 + wm + mi * 16 + (lane >> 2);
        #pragma unroll
        for (int nt = 0; nt < 8; nt++) {
            const int col = lcol0 + wn + nt * 8 + 2 * (lane & 3);
            float v0 = acc[mi][nt][0], v1 = acc[mi][nt][1];
            float v2 = acc[mi][nt][2], v3 = acc[mi][nt][3];
            if (mode <= 1) {   // Q or K: scale + RoPE
                if (mode == 0) { v0 *= QSCALE; v1 *= QSCALE; v2 *= QSCALE; v3 *= QSCALE; }
                const int p = (col & 127) >> 1;
                const float inv = exp2f((float)p * RF);
                float s0, c0f, s1, c1f;
                sincosf((float)(row & (LQ - 1)) * inv, &s0, &c0f);
                sincosf((float)((row + 8) & (LQ - 1)) * inv, &s1, &c1f);
                float x0 = v0, x1 = v1;
                v0 = x0 * c0f - x1 * s0;
                v1 = x1 * c0f + x0 * s0;
                x0 = v2; x1 = v3;
                v2 = x0 * c1f - x1 * s1;
                v3 = x1 * c1f + x0 * s1;
                if (mode == 0) {   // Q: fp16 hi/lo
                    __half h0 = __float2half(v0), h1 = __float2half(v1);
                    __half h2 = __float2half(v2), h3 = __float2half(v3);
                    __half l0 = __float2half(v0 - __half2float(h0));
                    __half l1 = __float2half(v1 - __half2float(h1));
                    __half l2 = __float2half(v2 - __half2float(h2));
                    __half l3 = __float2half(v3 - __half2float(h3));
                    *(__half2*)(g_Qhi + (size_t)row * HQ + col)       = __half2(h0, h1);
                    *(__half2*)(g_Qhi + (size_t)(row + 8) * HQ + col) = __half2(h2, h3);
                    *(__half2*)(g_Qlo + (size_t)row * HQ + col)       = __half2(l0, l1);
                    *(__half2*)(g_Qlo + (size_t)(row + 8) * HQ + col) = __half2(l2, l3);
                } else {           // K: hi + decayed copy (head = col>>7)
                    float sdecK = log2f(1.0f - exp2f(-5.0f - (float)(col >> 7)));
                    *(__half2*)(g_Khi + (size_t)row * HQ + col)       = __floats2half2_rn(v0, v1);
                    *(__half2*)(g_Khi + (size_t)(row + 8) * HQ + col) = __floats2half2_rn(v2, v3);
                    float p0 = exp2f(sdecK * (float)(CHK - (row & (CHK - 1))));
                    float p1 = exp2f(sdecK * (float)(CHK - ((row + 8) & (CHK - 1))));
                    *(__half2*)(g_Kdec + (size_t)row * HQ + col)       = __floats2half2_rn(v0 * p0, v1 * p0);
                    *(__half2*)(g_Kdec + (size_t)(row + 8) * HQ + col) = __floats2half2_rn(v2 * p1, v3 * p1);
                }
            } else if (mode == 2) {
                *(__half2*)(g_Vhi + (size_t)row * VDIMQ + col)       = __floats2half2_rn(v0, v1);
                *(__half2*)(g_Vhi + (size_t)(row + 8) * VDIMQ + col) = __floats2half2_rn(v2, v3);
            } else {
                *(float2*)(g_G + (size_t)row * VDIMQ + col)       = make_float2(v0, v1);
                *(float2*)(g_G + (size_t)(row + 8) * VDIMQ + col) = make_float2(v2, v3);
            }
        }
    }
}

// ---------------------------------------------------------------------------
// Wo GEMM: fp32 out. K=2048, N=1024. grid (4, 32).
// ---------------------------------------------------------------------------
__global__ void __launch_bounds__(256) wo_gemm(float* __restrict__ C)
{
    extern __shared__ char smem[];
    const uint32_t sbase = smem_u32(smem);
    const int tid  = threadIdx.x;
    const int wid  = tid >> 5;
    const int lane = tid & 31;
    const int row0 = blockIdx.y * 128;
    const int col0 = blockIdx.x * 256;
    const int wm   = (wid & 1) * 64;
    const int wn   = (wid >> 1) * 64;

    float acc[4][8][4];
    #pragma unroll
    for (int mi = 0; mi < 4; mi++)
        #pragma unroll
        for (int nt = 0; nt < 8; nt++)
            #pragma unroll
            for (int e = 0; e < 4; e++) acc[mi][nt][e] = 0.0f;

    GemmOps op{ g_O_hi, g_O_lo, g_Wo16, VDIMQ, HQ, row0, col0 };
    gemm_mainloop(op, sbase, acc);

    #pragma unroll
    for (int mi = 0; mi < 4; mi++) {
        const int row = row0 + wm + mi * 16 + (lane >> 2);
        #pragma unroll
        for (int nt = 0; nt < 8; nt++) {
            const int col = col0 + wn + nt * 8 + 2 * (lane & 3);
            *(float2*)(C + (size_t)row * HQ + col) =
                make_float2(acc[mi][nt][0], acc[mi][nt][1]);
            *(float2*)(C + (size_t)(row + 8) * HQ + col) =
                make_float2(acc[mi][nt][2], acc[mi][nt][3]);
        }
    }
}

// ---------------------------------------------------------------------------
// Attention Kernel A: per-chunk outer product  A_c = Kdec_c^T V_c
// ---------------------------------------------------------------------------
#define ATTA_SMEM 98304

__global__ void __launch_bounds__(512) chunk_state_kernel()
{
    extern __shared__ char smem[];
    const uint32_t SB   = smem_u32(smem);
    const uint32_t kbuf = SB;            // [128 r][128 d1] fp16 SW256
    const uint32_t vbuf = SB + 32768;    // [128 r][256 d2] fp16 SW512

    const int ch = blockIdx.x, bh = blockIdx.y;
    const int b = bh >> 3, h = bh & 7;
    const int tid = threadIdx.x, wid = tid >> 5, lane = tid & 31;
    const int trow = ch * CHK;

    const __half* Kd_g = g_Kdec + (size_t)(b * LQ + trow) * HQ + h * DQKQ;
    const __half* Vh_g = g_Vhi + (size_t)(b * LQ + trow) * VDIMQ + h * DVQ;

    #pragma unroll
    for (int t = 0; t < 4; t++) {
        int idx = tid + t * 512;
        int r = idx >> 4, cc = idx & 15;
        ldgsts16(kbuf + SW256(r, cc), Kd_g + (size_t)r * HQ + cc * 8);
    }
    #pragma unroll
    for (int t = 0; t < 8; t++) {
        int idx = tid + t * 512;
        int r = idx >> 5, cc = idx & 31;
        ldgsts16(vbuf + SW512(r, cc), Vh_g + (size_t)r * VDIMQ + cc * 8);
    }
    cp_commit();
    cp_wait<0>();
    __syncthreads();

    const int wm = (wid & 3) * 32;
    const int wn = (wid >> 2) * 64;

    float acc[2][8][4];
    #pragma unroll
    for (int mi = 0; mi < 2; mi++)
        #pragma unroll
        for (int nt = 0; nt < 8; nt++)
            #pragma unroll
            for (int e = 0; e < 4; e++) acc[mi][nt][e] = 0.0f;

    #pragma unroll
    for (int ks = 0; ks < 8; ks++) {
        uint32_t af[2][4];
        #pragma unroll
        for (int mi = 0; mi < 2; mi++) {
            int m0 = wm + mi * 16;
            int r_src = ks * 16 + ((lane >> 4) << 3) + (lane & 7);
            int d_off = (m0 >> 3) + ((lane >> 3) & 1);
            ldsm4t(af[mi], kbuf + SW256(r_src, d_off));
        }
        uint32_t bf[8][2];
        #pragma unroll
        for (int np = 0; np < 4; np++) {
            int row = ks * 16 + ((lane >> 3) & 1) * 8 + (lane & 7);
            int cn  = (wn + np * 16 + (lane >> 4) * 8) >> 3;
            uint32_t rh[4];
            ldsm4t(rh, vbuf + SW512(row, cn));
            bf[2*np][0] = rh[0]; bf[2*np][1] = rh[1];
            bf[2*np+1][0] = rh[2]; bf[2*np+1][1] = rh[3];
        }
        #pragma unroll
        for (int mi = 0; mi < 2; mi++)
            #pragma unroll
            for (int nt = 0; nt < 8; nt++)
                mma_fp16(acc[mi][nt], af[mi], bf[nt]);
    }

    float* Ag = g_A + ((size_t)(bh * NCH + ch) << 15);
    #pragma unroll
    for (int mi = 0; mi < 2; mi++) {
        int d1 = wm + mi * 16 + (lane >> 2);
        #pragma unroll
        for (int nt = 0; nt < 8; nt++) {
            int d2 = wn + nt * 8 + 2 * (lane & 3);
            *(float2*)(Ag + (size_t)d1 * DVQ + d2) =
                make_float2(acc[mi][nt][0], acc[mi][nt][1]);
            *(float2*)(Ag + (size_t)(d1 + 8) * DVQ + d2) =
                make_float2(acc[mi][nt][2], acc[mi][nt][3]);
        }
    }
}

// ---------------------------------------------------------------------------
// Attention Kernel B: per-element decay scan over chunks -> states S_c (hi/lo)
// ---------------------------------------------------------------------------
__global__ void __launch_bounds__(512) scan_kernel()
{
    const int e  = blockIdx.x * 512 + threadIdx.x;
    const int bh = blockIdx.y;
    const int h  = bh & 7;
    const float sdec = log2f(1.0f - exp2f(-5.0f - (float)h));
    const float lamC = exp2f(sdec * (float)CHK);

    const size_t base = (size_t)bh * NCH << 15;
    float S = 0.0f;
    #pragma unroll
    for (int c = 0; c < NCH; c++) {
        size_t off = base + ((size_t)c << 15) + e;
        __half hi = __float2half(S);
        g_Shi[off] = hi;
        g_Slo[off] = __float2half(S - __half2float(hi));
        S = S * lamC + g_A[off];
    }
}

// ---------------------------------------------------------------------------
// Attention Kernel C: per (chunk, bh, dv-half) output.
// ---------------------------------------------------------------------------
#define ATTC_SMEM 229376

__global__ void __launch_bounds__(512) attn_chunk_kernel()
{
    extern __shared__ char smem[];
    const uint32_t SB  = smem_u32(smem);
    const uint32_t sQh = SB;
    const uint32_t sQl = SB + 32768;
    const uint32_t sK  = SB + 65536;
    const uint32_t sSh = SB + 98304;
    const uint32_t sSl = SB + 131072;
    const uint32_t sV  = SB + 163840;
    const uint32_t sPl = SB + 196608;
    const uint32_t sPh = sK;

    const int vh = blockIdx.x;
    const int ch = blockIdx.y;
    const int bh = blockIdx.z;
    const int b = bh >> 3, h = bh & 7;
    const int tid = threadIdx.x, wid = tid >> 5, lane = tid & 31;
    const int trow = ch * CHK;
    const float sdec = log2f(1.0f - exp2f(-5.0f - (float)h));

    const __half* Qh_g = g_Qhi + (size_t)(b * LQ + trow) * HQ + h * DQKQ;
    const __half* Ql_g = g_Qlo + (size_t)(b * LQ + trow) * HQ + h * DQKQ;
    const __half* Kh_g = g_Khi + (size_t)(b * LQ + trow) * HQ + h * DQKQ;
    const __half* Vh_g = g_Vhi + (size_t)(b * LQ + trow) * VDIMQ + h * DVQ + vh * 128;
    const __half* Sh_g = g_Shi + ((size_t)(bh * NCH + ch) << 15) + vh * 128;
    const __half* Sl_g = g_Slo + ((size_t)(bh * NCH + ch) << 15) + vh * 128;

    #pragma unroll
    for (int t = 0; t < 4; t++) {
        int idx = tid + t * 512;
        int r = idx >> 4, cc = idx & 15;
        ldgsts16(sQh + SW256(r, cc), Qh_g + (size_t)r * HQ + cc * 8);
        ldgsts16(sQl + SW256(r, cc), Ql_g + (size_t)r * HQ + cc * 8);
        ldgsts16(sK  + SW256(r, cc), Kh_g + (size_t)r * HQ + cc * 8);
    }
    cp_commit();
    #pragma unroll
    for (int t = 0; t < 4; t++) {
        int idx = tid + t * 512;
        int r = idx >> 4, cc = idx & 15;
        ldgsts16(sSh + SW256(r, cc), Sh_g + (size_t)r * DVQ + cc * 8);
        ldgsts16(sSl + SW256(r, cc), Sl_g + (size_t)r * DVQ + cc * 8);
        ldgsts16(sV  + SW256(r, cc), Vh_g + (size_t)r * VDIMQ + cc * 8);
    }
    cp_commit();

    const int wm = (wid & 3) * 32;
    const int wn = (wid >> 2) * 32;

    cp_wait<1>();
    __syncthreads();

    // ---- P = Q K^T (128x128), 2 terms ----
    float sacc[2][4][4];
    #pragma unroll
    for (int mi = 0; mi < 2; mi++)
        #pragma unroll
        for (int ni = 0; ni < 4; ni++)
            #pragma unroll
            for (int e = 0; e < 4; e++) sacc[mi][ni][e] = 0.0f;

    #pragma unroll
    for (int ks = 0; ks < 8; ks++) {
        uint32_t qh[2][4], ql[2][4];
        #pragma unroll
        for (int mi = 0; mi < 2; mi++) {
            int r = wm + mi * 16 + (lane & 15);
            int cc = ks * 2 + (lane >> 4);
            uint32_t ad = sQh + SW256(r, cc);
            ldsm4(qh[mi], ad);
            ldsm4(ql[mi], ad + 32768);
        }
        uint32_t kb[4][2];
        #pragma unroll
        for (int j = 0; j < 2; j++) {
            int m4 = lane >> 3;
            int n  = wn + j * 16 + ((m4 >> 1) << 3) + (lane & 7);
            int cc = ks * 2 + (m4 & 1);
            uint32_t rh[4];
            ldsm4(rh, sK + SW256(n, cc));
            kb[2*j][0] = rh[0]; kb[2*j][1] = rh[1];
            kb[2*j+1][0] = rh[2]; kb[2*j+1][1] = rh[3];
        }
        #pragma unroll
        for (int mi = 0; mi < 2; mi++)
            #pragma unroll
            for (int ni = 0; ni < 4; ni++) {
                mma_fp16(sacc[mi][ni], qh[mi], kb[ni]);
                mma_fp16(sacc[mi][ni], ql[mi], kb[ni]);
            }
    }
    __syncthreads();

    // ---- decay + causal + split -> store P hi/lo ----
    #pragma unroll
    for (int mi = 0; mi < 2; mi++) {
        int r0 = wm + mi * 16 + (lane >> 2);
        #pragma unroll
        for (int ni = 0; ni < 4; ni++) {
            int j0 = wn + ni * 8 + 2 * (lane & 3);
            float d00 = (r0 >= j0)         ? exp2f(sdec * (float)(r0 - j0))     : 0.0f;
            float d01 = (r0 >= j0 + 1)     ? exp2f(sdec * (float)(r0 - j0 - 1)) : 0.0f;
            float d10 = (r0 + 8 >= j0)     ? exp2f(sdec * (float)(r0 + 8 - j0))     : 0.0f;
            float d11 = (r0 + 8 >= j0 + 1) ? exp2f(sdec * (float)(r0 + 8 - j0 - 1)) : 0.0f;
            float v0 = sacc[mi][ni][0] * d00, v1 = sacc[mi][ni][1] * d01;
            float v2 = sacc[mi][ni][2] * d10, v3 = sacc[mi][ni][3] * d11;
            float h0 = __half2float(__float2half(v0));
            float h1 = __half2float(__float2half(v1));
            float h2 = __half2float(__float2half(v2));
            float h3 = __half2float(__float2half(v3));
            int cc = j0 >> 3;
            int off = (j0 & 7) * 2;
            sts32(sPh + SW256(r0, cc) + off,     pack_h2(v0, v1));
            sts32(sPl + SW256(r0, cc) + off,     pack_h2(v0 - h0, v1 - h1));
            sts32(sPh + SW256(r0 + 8, cc) + off, pack_h2(v2, v3));
            sts32(sPl + SW256(r0 + 8, cc) + off, pack_h2(v2 - h2, v3 - h3));
        }
    }
    cp_wait<0>();
    __syncthreads();

    // ---- X = Q @ S (128x128), 3 terms ----
    float xacc[2][4][4];
    #pragma unroll
    for (int mi = 0; mi < 2; mi++)
        #pragma unroll
        for (int ni = 0; ni < 4; ni++)
            #pragma unroll
            for (int e = 0; e < 4; e++) xacc[mi][ni][e] = 0.0f;

    #pragma unroll
    for (int ks = 0; ks < 8; ks++) {
        uint32_t qh[2][4], ql[2][4];
        #pragma unroll
        for (int mi = 0; mi < 2; mi++) {
            int r = wm + mi * 16 + (lane & 15);
            int cc = ks * 2 + (lane >> 4);
            uint32_t ad = sQh + SW256(r, cc);
            ldsm4(qh[mi], ad);
            ldsm4(ql[mi], ad + 32768);
        }
        uint32_t sbh[4][2], sbl[4][2];
        #pragma unroll
        for (int np = 0; np < 2; np++) {
            int row = ks * 16 + ((lane >> 3) & 1) * 8 + (lane & 7);
            int cn  = (wn + np * 16 + (lane >> 4) * 8) >> 3;
            uint32_t rh[4], rl[4];
            ldsm4t(rh, sSh + SW256(row, cn));
            ldsm4t(rl, sSl + SW256(row, cn));
            sbh[2*np][0] = rh[0]; sbh[2*np][1] = rh[1];
            sbh[2*np+1][0] = rh[2]; sbh[2*np+1][1] = rh[3];
            sbl[2*np][0] = rl[0]; sbl[2*np][1] = rl[1];
            sbl[2*np+1][0] = rl[2]; sbl[2*np+1][1] = rl[3];
        }
        #pragma unroll
        for (int mi = 0; mi < 2; mi++)
            #pragma unroll
            for (int ni = 0; ni < 4; ni++) {
                mma_fp16(xacc[mi][ni], qh[mi], sbh[ni]);
                mma_fp16(xacc[mi][ni], ql[mi], sbh[ni]);
                mma_fp16(xacc[mi][ni], qh[mi], sbl[ni]);
            }
    }

    // ---- O_intra = P @ V (128x128), 2 terms ----
    float oacc[2][4][4];
    #pragma unroll
    for (int mi = 0; mi < 2; mi++)
        #pragma unroll
        for (int ni = 0; ni < 4; ni++)
            #pragma unroll
            for (int e = 0; e < 4; e++) oacc[mi][ni][e] = 0.0f;

    #pragma unroll
    for (int ks = 0; ks < 8; ks++) {
        uint32_t ph[2][4], pl[2][4];
        #pragma unroll
        for (int mi = 0; mi < 2; mi++) {
            int r = wm + mi * 16 + (lane & 15);
            int cc = ks * 2 + (lane >> 4);
            ldsm4(ph[mi], sPh + SW256(r, cc));
            ldsm4(pl[mi], sPl + SW256(r, cc));
        }
        uint32_t vb[4][2];
        #pragma unroll
        for (int np = 0; np < 2; np++) {
            int row = ks * 16 + ((lane >> 3) & 1) * 8 + (lane & 7);
            int cn  = (wn + np * 16 + (lane >> 4) * 8) >> 3;
            uint32_t rh[4];
            ldsm4t(rh, sV + SW256(row, cn));
            vb[2*np][0] = rh[0]; vb[2*np][1] = rh[1];
            vb[2*np+1][0] = rh[2]; vb[2*np+1][1] = rh[3];
        }
        #pragma unroll
        for (int mi = 0; mi < 2; mi++)
            #pragma unroll
            for (int ni = 0; ni < 4; ni++) {
                mma_fp16(oacc[mi][ni], ph[mi], vb[ni]);
                mma_fp16(oacc[mi][ni], pl[mi], vb[ni]);
            }
    }

    // ---- combine + write O ----
    float* Og = g_O + (size_t)(b * LQ + trow) * VDIMQ + h * DVQ + vh * 128;
    #pragma unroll
    for (int mi = 0; mi < 2; mi++) {
        int r0 = wm + mi * 16 + (lane >> 2);
        float lam0 = exp2f(sdec * (float)r0);
        float lam1 = exp2f(sdec * (float)(r0 + 8));
        #pragma unroll
        for (int ni = 0; ni < 4; ni++) {
            int col = wn + ni * 8 + 2 * (lane & 3);
            *(float2*)(Og + (size_t)r0 * VDIMQ + col) =
                make_float2(oacc[mi][ni][0] + lam0 * xacc[mi][ni][0],
                            oacc[mi][ni][1] + lam0 * xacc[mi][ni][1]);
            *(float2*)(Og + (size_t)(r0 + 8) * VDIMQ + col) =
                make_float2(oacc[mi][ni][2] + lam1 * xacc[mi][ni][2],
                            oacc[mi][ni][3] + lam1 * xacc[mi][ni][3]);
        }
    }
}

// ---------------------------------------------------------------------------
// Fused RMSNorm + swish gate + split -> fp16 hi/lo
// ---------------------------------------------------------------------------
__global__ void __launch_bounds__(256) normgate_split_kernel(const float* __restrict__ gw)
{
    const int warp = (blockIdx.x << 3) + (threadIdx.x >> 5);
    const int lane = threadIdx.x & 31;
    const size_t base = (size_t)(warp >> 3) * VDIMQ + (size_t)(warp & 7) * DVQ;
    const float* Op = g_O + base;
    const float* Gp = g_G + base;
    __half* Oh = g_O_hi + base;
    __half* Ol = g_O_lo + base;

    const int d0 = lane * 4;
    const int d1 = 128 + lane * 4;
    float4 o0 = *(const float4*)(Op + d0);
    float4 o1 = *(const float4*)(Op + d1);

    float ss = o0.x*o0.x + o0.y*o0.y + o0.z*o0.z + o0.w*o0.w
             + o1.x*o1.x + o1.y*o1.y + o1.z*o1.z + o1.w*o1.w;
    #pragma unroll
    for (int off = 16; off > 0; off >>= 1)
        ss += __shfl_xor_sync(0xFFFFFFFFu, ss, off);

    const float r = rsqrtf(ss * (1.0f / 256.0f) + 1e-5f);

    float4 g0 = *(const float4*)(Gp + d0);
    float4 g1 = *(const float4*)(Gp + d1);
    float4 w0 = *(const float4*)(gw + d0);
    float4 w1 = *(const float4*)(gw + d1);

    float v[8];
    v[0] = o0.x * r * w0.x * (g0.x / (1.0f + expf(-g0.x)));
    v[1] = o0.y * r * w0.y * (g0.y / (1.0f + expf(-g0.y)));
    v[2] = o0.z * r * w0.z * (g0.z / (1.0f + expf(-g0.z)));
    v[3] = o0.w * r * w0.w * (g0.w / (1.0f + expf(-g0.w)));
    v[4] = o1.x * r * w1.x * (g1.x / (1.0f + expf(-g1.x)));
    v[5] = o1.y * r * w1.y * (g1.y / (1.0f + expf(-g1.y)));
    v[6] = o1.z * r * w1.z * (g1.z / (1.0f + expf(-g1.z)));
    v[7] = o1.w * r * w1.w * (g1.w / (1.0f + expf(-g1.w)));

    __half h[8], l[8];
    #pragma unroll
    for (int i = 0; i < 8; i++) {
        h[i] = __float2half(v[i]);
        l[i] = __float2half(v[i] - __half2float(h[i]));
    }
    *(__half2*)(Oh + d0)     = __half2(h[0], h[1]);
    *(__half2*)(Oh + d0 + 2) = __half2(h[2], h[3]);
    *(__half2*)(Oh + d1)     = __half2(h[4], h[5]);
    *(__half2*)(Oh + d1 + 2) = __half2(h[6], h[7]);
    *(__half2*)(Ol + d0)     = __half2(l[0], l[1]);
    *(__half2*)(Ol + d0 + 2) = __half2(l[2], l[3]);
    *(__half2*)(Ol + d1)     = __half2(l[4], l[5]);
    *(__half2*)(Ol + d1 + 2) = __half2(l[6], l[7]);
}

// ---------------------------------------------------------------------------
// kernel_launch
// ---------------------------------------------------------------------------
extern "C" void kernel_launch(void* const* d_in, const int* in_sizes, int n_in,
                              void* d_out, int out_size)
{
    const float* hs = (const float*)d_in[0];
    const float* Wq = (const float*)d_in[1];
    const float* Wk = (const float*)d_in[2];
    const float* Wv = (const float*)d_in[3];
    const float* Wg = (const float*)d_in[4];
    const float* Wo = (const float*)d_in[5];
    const float* gw = (const float*)d_in[6];
    float* out = (float*)d_out;

    __half *hsh, *hsl;
    __half *qw, *kw, *vw, *gwt, *ow;
    cudaGetSymbolAddress((void**)&hsh, g_hs_hi);
    cudaGetSymbolAddress((void**)&hsl, g_hs_lo);
    cudaGetSymbolAddress((void**)&qw, g_Wq16);
    cudaGetSymbolAddress((void**)&kw, g_Wk16);
    cudaGetSymbolAddress((void**)&vw, g_Wv16);
    cudaGetSymbolAddress((void**)&gwt, g_Wg16);
    cudaGetSymbolAddress((void**)&ow, g_Wo16);

    cudaFuncSetAttribute(qkvg_gemm, cudaFuncAttributeMaxDynamicSharedMemorySize, TCG_SMEM);
    cudaFuncSetAttribute(wo_gemm,   cudaFuncAttributeMaxDynamicSharedMemorySize, TCG_SMEM);
    cudaFuncSetAttribute(chunk_state_kernel, cudaFuncAttributeMaxDynamicSharedMemorySize, ATTA_SMEM);
    cudaFuncSetAttribute(attn_chunk_kernel,  cudaFuncAttributeMaxDynamicSharedMemorySize, ATTC_SMEM);

    dim3 blk(256);

    // 1) prep: hs split + weight fp32->fp16 conversion (same layout)
    split_kernel<<<(MROWS*HQ/4 + 255)/256, blk>>>(hs, hsh, hsl, MROWS*HQ/4);
    CvtPtrs cp;
    cp.src[0] = Wq; cp.dst[0] = qw;
    cp.src[1] = Wk; cp.dst[1] = kw;
    cp.src[2] = Wv; cp.dst[2] = vw;
    cp.src[3] = Wg; cp.dst[3] = gwt;
    cp.src[4] = Wo; cp.dst[4] = ow;
    cp.start4[0] = 0;
    cp.start4[1] = HQ*HQ/4;            // 262144
    cp.start4[2] = 2*HQ*HQ/4;          // 524288
    cp.start4[3] = (2*HQ*HQ + HQ*VDIMQ)/4;        // 1048576
    cp.start4[4] = (2*HQ*HQ + 2*HQ*VDIMQ)/4;      // 1572864
    cp.start4[5] = (2*HQ*HQ + 2*HQ*VDIMQ + VDIMQ*HQ)/4;  // 2097152
    convert_multi<<<cp.start4[5]/256, blk>>>(cp);

    // 2) mega QKVG projection (CTA 128x256)
    qkvg_gemm<<<dim3(24, MROWS/128), blk, TCG_SMEM>>>();

    // 3) chunked-recurrent retention
    chunk_state_kernel<<<dim3(NCH, 16), 512, ATTA_SMEM>>>();
    scan_kernel<<<dim3(64, 16), 512>>>();
    attn_chunk_kernel<<<dim3(2, NCH, 16), 512, ATTC_SMEM>>>();

    // 4) fused RMSNorm + swish gate + split
    normgate_split_kernel<<<4096, blk>>>(gw);

    // 5) output projection (CTA 128x256)
    wo_gemm<<<dim3(HQ/256, MROWS/128), blk, TCG_SMEM>>>(out);
}

// round 11
// speedup vs baseline: 1.1051x; 1.1051x over previous
#include <cuda_runtime.h>
#include <cuda_fp16.h>
#include <math.h>
#include <stdint.h>

// Problem constants
#define BQ 2
#define LQ 2048
#define HQ 1024
#define NHQ 8
#define DQKQ 128
#define DVQ 256
#define VDIMQ 2048
#define MROWS (BQ*LQ)   // 4096
#define CHK 128         // retention chunk size
#define NCH (LQ/CHK)    // 16 chunks per sequence

#define QSCALE 0.08838834764831843f          // 128^-0.5
#define RF (-0.20762050593045852f)           // -2*log2(10000)/128

// ---------------------------------------------------------------------------
// Scratch (device globals)
// ---------------------------------------------------------------------------
__device__ float g_G[MROWS*VDIMQ];
__device__ float g_O[MROWS*VDIMQ];
__device__ float g_A[16*NCH*DQKQ*DVQ];            // per-chunk KV outer products
__device__ float2 g_rope[LQ*64];                  // (cos, sin) per (t, pair)

__device__ __half g_hs_hi[MROWS*HQ],  g_hs_lo[MROWS*HQ];
__device__ __half g_O_hi[MROWS*VDIMQ], g_O_lo[MROWS*VDIMQ];
__device__ __half g_Qhi[MROWS*HQ],    g_Qlo[MROWS*HQ];
__device__ __half g_Khi[MROWS*HQ];
__device__ __half g_Kdec[MROWS*HQ];               // K * lam^(CHK - r%CHK)
__device__ __half g_Vhi[MROWS*VDIMQ];
__device__ __half g_Shi[16*NCH*DQKQ*DVQ];         // chunk-entry states hi
__device__ __half g_Slo[16*NCH*DQKQ*DVQ];         // chunk-entry states lo
__device__ __half g_WqT[HQ*HQ];
__device__ __half g_WkT[HQ*HQ];
__device__ __half g_WvT[VDIMQ*HQ];
__device__ __half g_WgT[VDIMQ*HQ];
__device__ __half g_WoT[HQ*VDIMQ];

// ---------------------------------------------------------------------------
// PTX helpers
// ---------------------------------------------------------------------------
__device__ __forceinline__ uint32_t smem_u32(const void* p) {
    uint32_t a;
    asm("{ .reg .u64 t; cvta.to.shared.u64 t, %1; cvt.u32.u64 %0, t; }"
        : "=r"(a) : "l"(p));
    return a;
}
__device__ __forceinline__ void ldgsts16(uint32_t dst, const void* src) {
    asm volatile("cp.async.cg.shared.global [%0], [%1], 16;" :: "r"(dst), "l"(src));
}
__device__ __forceinline__ void cp_commit() {
    asm volatile("cp.async.commit_group;" ::: "memory");
}
template<int N_>
__device__ __forceinline__ void cp_wait() {
    asm volatile("cp.async.wait_group %0;" :: "n"(N_) : "memory");
}
__device__ __forceinline__ void ldsm4(uint32_t* r, uint32_t addr) {
    asm volatile("ldmatrix.sync.aligned.m8n8.x4.shared.b16 {%0,%1,%2,%3}, [%4];"
        : "=r"(r[0]), "=r"(r[1]), "=r"(r[2]), "=r"(r[3]) : "r"(addr));
}
__device__ __forceinline__ void ldsm4t(uint32_t* r, uint32_t addr) {
    asm volatile("ldmatrix.sync.aligned.m8n8.x4.trans.shared.b16 {%0,%1,%2,%3}, [%4];"
        : "=r"(r[0]), "=r"(r[1]), "=r"(r[2]), "=r"(r[3]) : "r"(addr));
}
__device__ __forceinline__ void sts32(uint32_t addr, uint32_t v) {
    asm volatile("st.shared.b32 [%0], %1;" :: "r"(addr), "r"(v) : "memory");
}
__device__ __forceinline__ void mma_fp16(float* c, const uint32_t* a, const uint32_t* b) {
    asm volatile("mma.sync.aligned.m16n8k16.row.col.f32.f16.f16.f32 "
        "{%0,%1,%2,%3}, {%4,%5,%6,%7}, {%8,%9}, {%0,%1,%2,%3};"
        : "+f"(c[0]), "+f"(c[1]), "+f"(c[2]), "+f"(c[3])
        : "r"(a[0]), "r"(a[1]), "r"(a[2]), "r"(a[3]), "r"(b[0]), "r"(b[1]));
}
__device__ __forceinline__ uint32_t pack_h2(float a, float b) {
    __half2 t = __floats2half2_rn(a, b);
    return *(uint32_t*)&t;
}

// Swizzles: row stride in bytes; 16B chunk xor'd by (r&7)
#define SW128R(r, c) ((uint32_t)((r) * 128u + ((uint32_t)((c) ^ ((r) & 7)) << 4)))
#define SW256(r, c)  ((uint32_t)((r) * 256u + ((uint32_t)((c) ^ ((r) & 7)) << 4)))
#define SW512(r, c)  ((uint32_t)((r) * 512u + ((uint32_t)((c) ^ ((r) & 7)) << 4)))

// GEMM: K-chunk 64; tiles Ahi|Alo|Bhi of 128x64 fp16 = 16KB each; 3 stages
#define GST_AHI 0
#define GST_ALO 16384
#define GST_BHI 32768
#define G_STAGE 49152
#define TCG_SMEM (3 * G_STAGE)

// ---------------------------------------------------------------------------
// hs split -> fp16 hi/lo
// ---------------------------------------------------------------------------
__global__ void __launch_bounds__(256) split_kernel(const float* __restrict__ x,
                                                    __half* __restrict__ hi,
                                                    __half* __restrict__ lo,
                                                    int n4)
{
    int i = blockIdx.x * 256 + threadIdx.x;
    if (i >= n4) return;
    float4 v = ((const float4*)x)[i];
    __half h0 = __float2half(v.x), h1 = __float2half(v.y);
    __half h2 = __float2half(v.z), h3 = __float2half(v.w);
    __half l0 = __float2half(v.x - __half2float(h0));
    __half l1 = __float2half(v.y - __half2float(h1));
    __half l2 = __float2half(v.z - __half2float(h2));
    __half l3 = __float2half(v.w - __half2float(h3));
    ((__half2*)hi)[2*i]   = __half2(h0, h1);
    ((__half2*)hi)[2*i+1] = __half2(h2, h3);
    ((__half2*)lo)[2*i]   = __half2(l0, l1);
    ((__half2*)lo)[2*i+1] = __half2(l2, l3);
}

// ---------------------------------------------------------------------------
// RoPE table: g_rope[t*64 + p] = (cos, sin) of t * base^(-2p/128).
// Same sincosf math as before -> identical numerics, computed once.
// ---------------------------------------------------------------------------
__global__ void __launch_bounds__(256) rope_table_kernel()
{
    int i = blockIdx.x * 256 + threadIdx.x;    // 0..131071
    int t = i >> 6, p = i & 63;
    float inv = exp2f((float)p * RF);
    float s, c;
    sincosf((float)t * inv, &s, &c);
    g_rope[i] = make_float2(c, s);
}

// ---------------------------------------------------------------------------
// Merged weight transpose (fp16): one launch for all 5 weights.
// ---------------------------------------------------------------------------
struct TDesc { const float* W; __half* hi; int K, N, start; };
struct TDescs { TDesc d[5]; };

__global__ void __launch_bounds__(256) transpose_multi(TDescs ds)
{
    __shared__ float s[32][33];
    int t = blockIdx.x;
    int i = 0;
    #pragma unroll
    for (int j = 1; j < 5; j++) if (t >= ds.d[j].start) i = j;
    const float* W = ds.d[i].W;
    __half* Th = ds.d[i].hi;
    const int K = ds.d[i].K, N = ds.d[i].N;
    int lt = t - ds.d[i].start;
    int ncols = N >> 5;
    int k0 = (lt / ncols) * 32;
    int n0 = (lt % ncols) * 32;

    const int tx = threadIdx.x & 31;
    const int ty = threadIdx.x >> 5;
    #pragma unroll
    for (int q = 0; q < 4; q++)
        s[ty + 8*q][tx] = W[(size_t)(k0 + ty + 8*q) * N + n0 + tx];
    __syncthreads();
    #pragma unroll
    for (int q = 0; q < 4; q++) {
        float v = s[tx][ty + 8*q];
        Th[(size_t)(n0 + ty + 8*q) * K + k0 + tx] = __float2half(v);
    }
}

// ---------------------------------------------------------------------------
// GEMM mainloop: 128x128 tile, 8 warps (64x32), K-chunk 64, 3-stage pipeline.
// 2-term fp16: A hi/lo, B hi (pre-transposed K-major).
// ---------------------------------------------------------------------------
struct GemmOps {
    const __half *Ah, *Al, *Bh;
    int K, row0, bcol0;
};

__device__ __forceinline__ void gemm_mainloop(const GemmOps& op, uint32_t sbase,
                                              float acc[4][4][4])
{
    const int tid  = threadIdx.x;
    const int wid  = tid >> 5;
    const int lane = tid & 31;
    const int wm   = (wid & 1) * 64;
    const int wn   = (wid >> 1) * 32;
    const int K    = op.K;
    const int nchunks = K >> 6;

    auto load_chunk = [&](uint32_t sb, int k0) {
        #pragma unroll
        for (int t = 0; t < 4; t++) {
            int idx = tid + t * 256;
            int r   = idx >> 3;
            int c   = idx & 7;
            uint32_t soff = SW128R(r, c);
            size_t aoff = (size_t)(op.row0 + r) * K + k0 + c * 8;
            size_t boff = (size_t)(op.bcol0 + r) * K + k0 + c * 8;
            ldgsts16(sb + GST_AHI + soff, op.Ah + aoff);
            ldgsts16(sb + GST_ALO + soff, op.Al + aoff);
            ldgsts16(sb + GST_BHI + soff, op.Bh + boff);
        }
        cp_commit();
    };

    load_chunk(sbase, 0);
    if (nchunks > 1) load_chunk(sbase + G_STAGE, 64);

    uint32_t stage_of[3] = { sbase, sbase + G_STAGE, sbase + 2 * G_STAGE };

    for (int cch = 0; cch < nchunks; cch++) {
        const uint32_t sb = stage_of[cch % 3];
        if (cch + 2 < nchunks) {
            load_chunk(stage_of[(cch + 2) % 3], (cch + 2) * 64);
            cp_wait<2>();
        } else if (cch + 1 < nchunks) {
            cp_wait<1>();
        } else {
            cp_wait<0>();
        }
        __syncthreads();

        #pragma unroll
        for (int ks = 0; ks < 4; ks++) {
            uint32_t ahi[4][4], alo[4][4];
            #pragma unroll
            for (int mi = 0; mi < 4; mi++) {
                int r = wm + mi * 16 + (lane & 15);
                int c = ks * 2 + (lane >> 4);
                uint32_t ad = sb + GST_AHI + SW128R(r, c);
                ldsm4(ahi[mi], ad);
                ldsm4(alo[mi], ad + (GST_ALO - GST_AHI));
            }
            uint32_t bhi[4][2];
            #pragma unroll
            for (int j = 0; j < 2; j++) {
                int m4 = lane >> 3;
                int n  = wn + j * 16 + ((m4 >> 1) << 3) + (lane & 7);
                int c  = ks * 2 + (m4 & 1);
                uint32_t rh[4];
                ldsm4(rh, sb + GST_BHI + SW128R(n, c));
                bhi[2*j][0] = rh[0]; bhi[2*j][1] = rh[1];
                bhi[2*j+1][0] = rh[2]; bhi[2*j+1][1] = rh[3];
            }
            #pragma unroll
            for (int mi = 0; mi < 4; mi++)
                #pragma unroll
                for (int ni = 0; ni < 4; ni++) {
                    mma_fp16(acc[mi][ni], ahi[mi], bhi[ni]);
                    mma_fp16(acc[mi][ni], alo[mi], bhi[ni]);
                }
        }
        __syncthreads();
    }
}

// ---------------------------------------------------------------------------
// Mega QKVG GEMM: grid (48, 32). cb<8: Q | cb<16: K (+Kdec) | cb<32: V | else G
// ---------------------------------------------------------------------------
__global__ void __launch_bounds__(256) qkvg_gemm()
{
    extern __shared__ char smem[];
    const uint32_t sbase = smem_u32(smem);
    const int tid  = threadIdx.x;
    const int wid  = tid >> 5;
    const int lane = tid & 31;
    const int row0 = blockIdx.y * 128;
    const int cb   = blockIdx.x;
    const int wm   = (wid & 1) * 64;
    const int wn   = (wid >> 1) * 32;

    int mode, lcol0;
    const __half* Bh;
    if (cb < 8)       { mode = 0; lcol0 = cb * 128;        Bh = g_WqT; }
    else if (cb < 16) { mode = 1; lcol0 = (cb - 8) * 128;  Bh = g_WkT; }
    else if (cb < 32) { mode = 2; lcol0 = (cb - 16) * 128; Bh = g_WvT; }
    else              { mode = 3; lcol0 = (cb - 32) * 128; Bh = g_WgT; }

    float acc[4][4][4];
    #pragma unroll
    for (int mi = 0; mi < 4; mi++)
        #pragma unroll
        for (int ni = 0; ni < 4; ni++)
            #pragma unroll
            for (int e = 0; e < 4; e++) acc[mi][ni][e] = 0.0f;

    GemmOps op{ g_hs_hi, g_hs_lo, Bh, HQ, row0, lcol0 };
    gemm_mainloop(op, sbase, acc);

    // K decay scale (constant per CTA for mode 1: head = cb-8)
    float sdecK = 0.0f;
    if (mode == 1) sdecK = log2f(1.0f - exp2f(-5.0f - (float)(cb - 8)));

    #pragma unroll
    for (int mi = 0; mi < 4; mi++) {
        const int row = row0 + wm + mi * 16 + (lane >> 2);
        #pragma unroll
        for (int ni = 0; ni < 4; ni++) {
            const int col = lcol0 + wn + ni * 8 + 2 * (lane & 3);
            float v0 = acc[mi][ni][0], v1 = acc[mi][ni][1];
            float v2 = acc[mi][ni][2], v3 = acc[mi][ni][3];
            if (mode <= 1) {   // Q or K: scale + RoPE (table lookup)
                if (mode == 0) { v0 *= QSCALE; v1 *= QSCALE; v2 *= QSCALE; v3 *= QSCALE; }
                const int p = (col & 127) >> 1;
                float2 cs0 = g_rope[(row & (LQ - 1)) * 64 + p];
                float2 cs1 = g_rope[((row + 8) & (LQ - 1)) * 64 + p];
                float x0 = v0, x1 = v1;
                v0 = x0 * cs0.x - x1 * cs0.y;
                v1 = x1 * cs0.x + x0 * cs0.y;
                x0 = v2; x1 = v3;
                v2 = x0 * cs1.x - x1 * cs1.y;
                v3 = x1 * cs1.x + x0 * cs1.y;
                if (mode == 0) {   // Q: fp16 hi/lo
                    __half h0 = __float2half(v0), h1 = __float2half(v1);
                    __half h2 = __float2half(v2), h3 = __float2half(v3);
                    __half l0 = __float2half(v0 - __half2float(h0));
                    __half l1 = __float2half(v1 - __half2float(h1));
                    __half l2 = __float2half(v2 - __half2float(h2));
                    __half l3 = __float2half(v3 - __half2float(h3));
                    *(__half2*)(g_Qhi + (size_t)row * HQ + col)       = __half2(h0, h1);
                    *(__half2*)(g_Qhi + (size_t)(row + 8) * HQ + col) = __half2(h2, h3);
                    *(__half2*)(g_Qlo + (size_t)row * HQ + col)       = __half2(l0, l1);
                    *(__half2*)(g_Qlo + (size_t)(row + 8) * HQ + col) = __half2(l2, l3);
                } else {           // K: hi + decayed copy
                    *(__half2*)(g_Khi + (size_t)row * HQ + col)       = __floats2half2_rn(v0, v1);
                    *(__half2*)(g_Khi + (size_t)(row + 8) * HQ + col) = __floats2half2_rn(v2, v3);
                    float p0 = exp2f(sdecK * (float)(CHK - (row & (CHK - 1))));
                    float p1 = exp2f(sdecK * (float)(CHK - ((row + 8) & (CHK - 1))));
                    *(__half2*)(g_Kdec + (size_t)row * HQ + col)       = __floats2half2_rn(v0 * p0, v1 * p0);
                    *(__half2*)(g_Kdec + (size_t)(row + 8) * HQ + col) = __floats2half2_rn(v2 * p1, v3 * p1);
                }
            } else if (mode == 2) {
                *(__half2*)(g_Vhi + (size_t)row * VDIMQ + col)       = __floats2half2_rn(v0, v1);
                *(__half2*)(g_Vhi + (size_t)(row + 8) * VDIMQ + col) = __floats2half2_rn(v2, v3);
            } else {
                *(float2*)(g_G + (size_t)row * VDIMQ + col)       = make_float2(v0, v1);
                *(float2*)(g_G + (size_t)(row + 8) * VDIMQ + col) = make_float2(v2, v3);
            }
        }
    }
}

// ---------------------------------------------------------------------------
// Wo GEMM: fp32 out. K=2048, N=1024.
// ---------------------------------------------------------------------------
__global__ void __launch_bounds__(256) wo_gemm(float* __restrict__ C)
{
    extern __shared__ char smem[];
    const uint32_t sbase = smem_u32(smem);
    const int tid  = threadIdx.x;
    const int wid  = tid >> 5;
    const int lane = tid & 31;
    const int row0 = blockIdx.y * 128;
    const int col0 = blockIdx.x * 128;
    const int wm   = (wid & 1) * 64;
    const int wn   = (wid >> 1) * 32;

    float acc[4][4][4];
    #pragma unroll
    for (int mi = 0; mi < 4; mi++)
        #pragma unroll
        for (int ni = 0; ni < 4; ni++)
            #pragma unroll
            for (int e = 0; e < 4; e++) acc[mi][ni][e] = 0.0f;

    GemmOps op{ g_O_hi, g_O_lo, g_WoT, VDIMQ, row0, col0 };
    gemm_mainloop(op, sbase, acc);

    #pragma unroll
    for (int mi = 0; mi < 4; mi++) {
        const int row = row0 + wm + mi * 16 + (lane >> 2);
        #pragma unroll
        for (int ni = 0; ni < 4; ni++) {
            const int col = col0 + wn + ni * 8 + 2 * (lane & 3);
            *(float2*)(C + (size_t)row * HQ + col) =
                make_float2(acc[mi][ni][0], acc[mi][ni][1]);
            *(float2*)(C + (size_t)(row + 8) * HQ + col) =
                make_float2(acc[mi][ni][2], acc[mi][ni][3]);
        }
    }
}

// ---------------------------------------------------------------------------
// Attention Kernel A: per-chunk outer product  A_c = Kdec_c^T V_c
// ---------------------------------------------------------------------------
#define ATTA_SMEM 98304

__global__ void __launch_bounds__(512) chunk_state_kernel()
{
    extern __shared__ char smem[];
    const uint32_t SB   = smem_u32(smem);
    const uint32_t kbuf = SB;            // [128 r][128 d1] fp16 SW256
    const uint32_t vbuf = SB + 32768;    // [128 r][256 d2] fp16 SW512

    const int ch = blockIdx.x, bh = blockIdx.y;
    const int b = bh >> 3, h = bh & 7;
    const int tid = threadIdx.x, wid = tid >> 5, lane = tid & 31;
    const int trow = ch * CHK;

    const __half* Kd_g = g_Kdec + (size_t)(b * LQ + trow) * HQ + h * DQKQ;
    const __half* Vh_g = g_Vhi + (size_t)(b * LQ + trow) * VDIMQ + h * DVQ;

    #pragma unroll
    for (int t = 0; t < 4; t++) {
        int idx = tid + t * 512;
        int r = idx >> 4, cc = idx & 15;
        ldgsts16(kbuf + SW256(r, cc), Kd_g + (size_t)r * HQ + cc * 8);
    }
    #pragma unroll
    for (int t = 0; t < 8; t++) {
        int idx = tid + t * 512;
        int r = idx >> 5, cc = idx & 31;
        ldgsts16(vbuf + SW512(r, cc), Vh_g + (size_t)r * VDIMQ + cc * 8);
    }
    cp_commit();
    cp_wait<0>();
    __syncthreads();

    const int wm = (wid & 3) * 32;
    const int wn = (wid >> 2) * 64;

    float acc[2][8][4];
    #pragma unroll
    for (int mi = 0; mi < 2; mi++)
        #pragma unroll
        for (int nt = 0; nt < 8; nt++)
            #pragma unroll
            for (int e = 0; e < 4; e++) acc[mi][nt][e] = 0.0f;

    #pragma unroll
    for (int ks = 0; ks < 8; ks++) {
        uint32_t af[2][4];
        #pragma unroll
        for (int mi = 0; mi < 2; mi++) {
            int m0 = wm + mi * 16;
            int r_src = ks * 16 + ((lane >> 4) << 3) + (lane & 7);
            int d_off = (m0 >> 3) + ((lane >> 3) & 1);
            ldsm4t(af[mi], kbuf + SW256(r_src, d_off));
        }
        uint32_t bf[8][2];
        #pragma unroll
        for (int np = 0; np < 4; np++) {
            int row = ks * 16 + ((lane >> 3) & 1) * 8 + (lane & 7);
            int cn  = (wn + np * 16 + (lane >> 4) * 8) >> 3;
            uint32_t rh[4];
            ldsm4t(rh, vbuf + SW512(row, cn));
            bf[2*np][0] = rh[0]; bf[2*np][1] = rh[1];
            bf[2*np+1][0] = rh[2]; bf[2*np+1][1] = rh[3];
        }
        #pragma unroll
        for (int mi = 0; mi < 2; mi++)
            #pragma unroll
            for (int nt = 0; nt < 8; nt++)
                mma_fp16(acc[mi][nt], af[mi], bf[nt]);
    }

    float* Ag = g_A + ((size_t)(bh * NCH + ch) << 15);
    #pragma unroll
    for (int mi = 0; mi < 2; mi++) {
        int d1 = wm + mi * 16 + (lane >> 2);
        #pragma unroll
        for (int nt = 0; nt < 8; nt++) {
            int d2 = wn + nt * 8 + 2 * (lane & 3);
            *(float2*)(Ag + (size_t)d1 * DVQ + d2) =
                make_float2(acc[mi][nt][0], acc[mi][nt][1]);
            *(float2*)(Ag + (size_t)(d1 + 8) * DVQ + d2) =
                make_float2(acc[mi][nt][2], acc[mi][nt][3]);
        }
    }
}

// ---------------------------------------------------------------------------
// Attention Kernel B: per-element decay scan over chunks -> states S_c (hi/lo)
// ---------------------------------------------------------------------------
__global__ void __launch_bounds__(512) scan_kernel()
{
    const int e  = blockIdx.x * 512 + threadIdx.x;
    const int bh = blockIdx.y;
    const int h  = bh & 7;
    const float sdec = log2f(1.0f - exp2f(-5.0f - (float)h));
    const float lamC = exp2f(sdec * (float)CHK);

    const size_t base = (size_t)bh * NCH << 15;
    float S = 0.0f;
    #pragma unroll
    for (int c = 0; c < NCH; c++) {
        size_t off = base + ((size_t)c << 15) + e;
        __half hi = __float2half(S);
        g_Shi[off] = hi;
        g_Slo[off] = __float2half(S - __half2float(hi));
        S = S * lamC + g_A[off];
    }
}

// ---------------------------------------------------------------------------
// Attention Kernel C: per (chunk, bh, dv-half) output.
// O = (QK^T ∘ decay) V + lam^r (Q S_c).  No atomics.
// ---------------------------------------------------------------------------
#define ATTC_SMEM 229376

__global__ void __launch_bounds__(512) attn_chunk_kernel()
{
    extern __shared__ char smem[];
    const uint32_t SB  = smem_u32(smem);
    const uint32_t sQh = SB;
    const uint32_t sQl = SB + 32768;
    const uint32_t sK  = SB + 65536;
    const uint32_t sSh = SB + 98304;
    const uint32_t sSl = SB + 131072;
    const uint32_t sV  = SB + 163840;
    const uint32_t sPl = SB + 196608;
    const uint32_t sPh = sK;            // aliased after K consumed

    const int vh = blockIdx.x;
    const int ch = blockIdx.y;
    const int bh = blockIdx.z;
    const int b = bh >> 3, h = bh & 7;
    const int tid = threadIdx.x, wid = tid >> 5, lane = tid & 31;
    const int trow = ch * CHK;
    const float sdec = log2f(1.0f - exp2f(-5.0f - (float)h));

    const __half* Qh_g = g_Qhi + (size_t)(b * LQ + trow) * HQ + h * DQKQ;
    const __half* Ql_g = g_Qlo + (size_t)(b * LQ + trow) * HQ + h * DQKQ;
    const __half* Kh_g = g_Khi + (size_t)(b * LQ + trow) * HQ + h * DQKQ;
    const __half* Vh_g = g_Vhi + (size_t)(b * LQ + trow) * VDIMQ + h * DVQ + vh * 128;
    const __half* Sh_g = g_Shi + ((size_t)(bh * NCH + ch) << 15) + vh * 128;
    const __half* Sl_g = g_Slo + ((size_t)(bh * NCH + ch) << 15) + vh * 128;

    #pragma unroll
    for (int t = 0; t < 4; t++) {
        int idx = tid + t * 512;
        int r = idx >> 4, cc = idx & 15;
        ldgsts16(sQh + SW256(r, cc), Qh_g + (size_t)r * HQ + cc * 8);
        ldgsts16(sQl + SW256(r, cc), Ql_g + (size_t)r * HQ + cc * 8);
        ldgsts16(sK  + SW256(r, cc), Kh_g + (size_t)r * HQ + cc * 8);
    }
    cp_commit();
    #pragma unroll
    for (int t = 0; t < 4; t++) {
        int idx = tid + t * 512;
        int r = idx >> 4, cc = idx & 15;
        ldgsts16(sSh + SW256(r, cc), Sh_g + (size_t)r * DVQ + cc * 8);
        ldgsts16(sSl + SW256(r, cc), Sl_g + (size_t)r * DVQ + cc * 8);
        ldgsts16(sV  + SW256(r, cc), Vh_g + (size_t)r * VDIMQ + cc * 8);
    }
    cp_commit();

    const int wm = (wid & 3) * 32;
    const int wn = (wid >> 2) * 32;

    cp_wait<1>();
    __syncthreads();

    // ---- P = Q K^T (128x128), 2 terms ----
    float sacc[2][4][4];
    #pragma unroll
    for (int mi = 0; mi < 2; mi++)
        #pragma unroll
        for (int ni = 0; ni < 4; ni++)
            #pragma unroll
            for (int e = 0; e < 4; e++) sacc[mi][ni][e] = 0.0f;

    #pragma unroll
    for (int ks = 0; ks < 8; ks++) {
        uint32_t qh[2][4], ql[2][4];
        #pragma unroll
        for (int mi = 0; mi < 2; mi++) {
            int r = wm + mi * 16 + (lane & 15);
            int cc = ks * 2 + (lane >> 4);
            uint32_t ad = sQh + SW256(r, cc);
            ldsm4(qh[mi], ad);
            ldsm4(ql[mi], ad + 32768);
        }
        uint32_t kb[4][2];
        #pragma unroll
        for (int j = 0; j < 2; j++) {
            int m4 = lane >> 3;
            int n  = wn + j * 16 + ((m4 >> 1) << 3) + (lane & 7);
            int cc = ks * 2 + (m4 & 1);
            uint32_t rh[4];
            ldsm4(rh, sK + SW256(n, cc));
            kb[2*j][0] = rh[0]; kb[2*j][1] = rh[1];
            kb[2*j+1][0] = rh[2]; kb[2*j+1][1] = rh[3];
        }
        #pragma unroll
        for (int mi = 0; mi < 2; mi++)
            #pragma unroll
            for (int ni = 0; ni < 4; ni++) {
                mma_fp16(sacc[mi][ni], qh[mi], kb[ni]);
                mma_fp16(sacc[mi][ni], ql[mi], kb[ni]);
            }
    }
    __syncthreads();

    // ---- decay + causal + split -> store P hi/lo ----
    #pragma unroll
    for (int mi = 0; mi < 2; mi++) {
        int r0 = wm + mi * 16 + (lane >> 2);
        #pragma unroll
        for (int ni = 0; ni < 4; ni++) {
            int j0 = wn + ni * 8 + 2 * (lane & 3);
            float d00 = (r0 >= j0)         ? exp2f(sdec * (float)(r0 - j0))     : 0.0f;
            float d01 = (r0 >= j0 + 1)     ? exp2f(sdec * (float)(r0 - j0 - 1)) : 0.0f;
            float d10 = (r0 + 8 >= j0)     ? exp2f(sdec * (float)(r0 + 8 - j0))     : 0.0f;
            float d11 = (r0 + 8 >= j0 + 1) ? exp2f(sdec * (float)(r0 + 8 - j0 - 1)) : 0.0f;
            float v0 = sacc[mi][ni][0] * d00, v1 = sacc[mi][ni][1] * d01;
            float v2 = sacc[mi][ni][2] * d10, v3 = sacc[mi][ni][3] * d11;
            float h0 = __half2float(__float2half(v0));
            float h1 = __half2float(__float2half(v1));
            float h2 = __half2float(__float2half(v2));
            float h3 = __half2float(__float2half(v3));
            int cc = j0 >> 3;
            int off = (j0 & 7) * 2;
            sts32(sPh + SW256(r0, cc) + off,     pack_h2(v0, v1));
            sts32(sPl + SW256(r0, cc) + off,     pack_h2(v0 - h0, v1 - h1));
            sts32(sPh + SW256(r0 + 8, cc) + off, pack_h2(v2, v3));
            sts32(sPl + SW256(r0 + 8, cc) + off, pack_h2(v2 - h2, v3 - h3));
        }
    }
    cp_wait<0>();
    __syncthreads();

    // ---- X = Q @ S (128x128), 3 terms ----
    float xacc[2][4][4];
    #pragma unroll
    for (int mi = 0; mi < 2; mi++)
        #pragma unroll
        for (int ni = 0; ni < 4; ni++)
            #pragma unroll
            for (int e = 0; e < 4; e++) xacc[mi][ni][e] = 0.0f;

    #pragma unroll
    for (int ks = 0; ks < 8; ks++) {
        uint32_t qh[2][4], ql[2][4];
        #pragma unroll
        for (int mi = 0; mi < 2; mi++) {
            int r = wm + mi * 16 + (lane & 15);
            int cc = ks * 2 + (lane >> 4);
            uint32_t ad = sQh + SW256(r, cc);
            ldsm4(qh[mi], ad);
            ldsm4(ql[mi], ad + 32768);
        }
        uint32_t sbh[4][2], sbl[4][2];
        #pragma unroll
        for (int np = 0; np < 2; np++) {
            int row = ks * 16 + ((lane >> 3) & 1) * 8 + (lane & 7);
            int cn  = (wn + np * 16 + (lane >> 4) * 8) >> 3;
            uint32_t rh[4], rl[4];
            ldsm4t(rh, sSh + SW256(row, cn));
            ldsm4t(rl, sSl + SW256(row, cn));
            sbh[2*np][0] = rh[0]; sbh[2*np][1] = rh[1];
            sbh[2*np+1][0] = rh[2]; sbh[2*np+1][1] = rh[3];
            sbl[2*np][0] = rl[0]; sbl[2*np][1] = rl[1];
            sbl[2*np+1][0] = rl[2]; sbl[2*np+1][1] = rl[3];
        }
        #pragma unroll
        for (int mi = 0; mi < 2; mi++)
            #pragma unroll
            for (int ni = 0; ni < 4; ni++) {
                mma_fp16(xacc[mi][ni], qh[mi], sbh[ni]);
                mma_fp16(xacc[mi][ni], ql[mi], sbh[ni]);
                mma_fp16(xacc[mi][ni], qh[mi], sbl[ni]);
            }
    }

    // ---- O_intra = P @ V (128x128), 2 terms ----
    float oacc[2][4][4];
    #pragma unroll
    for (int mi = 0; mi < 2; mi++)
        #pragma unroll
        for (int ni = 0; ni < 4; ni++)
            #pragma unroll
            for (int e = 0; e < 4; e++) oacc[mi][ni][e] = 0.0f;

    #pragma unroll
    for (int ks = 0; ks < 8; ks++) {
        uint32_t ph[2][4], pl[2][4];
        #pragma unroll
        for (int mi = 0; mi < 2; mi++) {
            int r = wm + mi * 16 + (lane & 15);
            int cc = ks * 2 + (lane >> 4);
            ldsm4(ph[mi], sPh + SW256(r, cc));
            ldsm4(pl[mi], sPl + SW256(r, cc));
        }
        uint32_t vb[4][2];
        #pragma unroll
        for (int np = 0; np < 2; np++) {
            int row = ks * 16 + ((lane >> 3) & 1) * 8 + (lane & 7);
            int cn  = (wn + np * 16 + (lane >> 4) * 8) >> 3;
            uint32_t rh[4];
            ldsm4t(rh, sV + SW256(row, cn));
            vb[2*np][0] = rh[0]; vb[2*np][1] = rh[1];
            vb[2*np+1][0] = rh[2]; vb[2*np+1][1] = rh[3];
        }
        #pragma unroll
        for (int mi = 0; mi < 2; mi++)
            #pragma unroll
            for (int ni = 0; ni < 4; ni++) {
                mma_fp16(oacc[mi][ni], ph[mi], vb[ni]);
                mma_fp16(oacc[mi][ni], pl[mi], vb[ni]);
            }
    }

    // ---- combine + write O ----
    float* Og = g_O + (size_t)(b * LQ + trow) * VDIMQ + h * DVQ + vh * 128;
    #pragma unroll
    for (int mi = 0; mi < 2; mi++) {
        int r0 = wm + mi * 16 + (lane >> 2);
        float lam0 = exp2f(sdec * (float)r0);
        float lam1 = exp2f(sdec * (float)(r0 + 8));
        #pragma unroll
        for (int ni = 0; ni < 4; ni++) {
            int col = wn + ni * 8 + 2 * (lane & 3);
            *(float2*)(Og + (size_t)r0 * VDIMQ + col) =
                make_float2(oacc[mi][ni][0] + lam0 * xacc[mi][ni][0],
                            oacc[mi][ni][1] + lam0 * xacc[mi][ni][1]);
            *(float2*)(Og + (size_t)(r0 + 8) * VDIMQ + col) =
                make_float2(oacc[mi][ni][2] + lam1 * xacc[mi][ni][2],
                            oacc[mi][ni][3] + lam1 * xacc[mi][ni][3]);
        }
    }
}

// ---------------------------------------------------------------------------
// Fused RMSNorm + swish gate + split -> fp16 hi/lo
// ---------------------------------------------------------------------------
__global__ void __launch_bounds__(256) normgate_split_kernel(const float* __restrict__ gw)
{
    const int warp = (blockIdx.x << 3) + (threadIdx.x >> 5);
    const int lane = threadIdx.x & 31;
    const size_t base = (size_t)(warp >> 3) * VDIMQ + (size_t)(warp & 7) * DVQ;
    const float* Op = g_O + base;
    const float* Gp = g_G + base;
    __half* Oh = g_O_hi + base;
    __half* Ol = g_O_lo + base;

    const int d0 = lane * 4;
    const int d1 = 128 + lane * 4;
    float4 o0 = *(const float4*)(Op + d0);
    float4 o1 = *(const float4*)(Op + d1);

    float ss = o0.x*o0.x + o0.y*o0.y + o0.z*o0.z + o0.w*o0.w
             + o1.x*o1.x + o1.y*o1.y + o1.z*o1.z + o1.w*o1.w;
    #pragma unroll
    for (int off = 16; off > 0; off >>= 1)
        ss += __shfl_xor_sync(0xFFFFFFFFu, ss, off);

    const float r = rsqrtf(ss * (1.0f / 256.0f) + 1e-5f);

    float4 g0 = *(const float4*)(Gp + d0);
    float4 g1 = *(const float4*)(Gp + d1);
    float4 w0 = *(const float4*)(gw + d0);
    float4 w1 = *(const float4*)(gw + d1);

    float v[8];
    v[0] = o0.x * r * w0.x * (g0.x / (1.0f + expf(-g0.x)));
    v[1] = o0.y * r * w0.y * (g0.y / (1.0f + expf(-g0.y)));
    v[2] = o0.z * r * w0.z * (g0.z / (1.0f + expf(-g0.z)));
    v[3] = o0.w * r * w0.w * (g0.w / (1.0f + expf(-g0.w)));
    v[4] = o1.x * r * w1.x * (g1.x / (1.0f + expf(-g1.x)));
    v[5] = o1.y * r * w1.y * (g1.y / (1.0f + expf(-g1.y)));
    v[6] = o1.z * r * w1.z * (g1.z / (1.0f + expf(-g1.z)));
    v[7] = o1.w * r * w1.w * (g1.w / (1.0f + expf(-g1.w)));

    __half h[8], l[8];
    #pragma unroll
    for (int i = 0; i < 8; i++) {
        h[i] = __float2half(v[i]);
        l[i] = __float2half(v[i] - __half2float(h[i]));
    }
    *(__half2*)(Oh + d0)     = __half2(h[0], h[1]);
    *(__half2*)(Oh + d0 + 2) = __half2(h[2], h[3]);
    *(__half2*)(Oh + d1)     = __half2(h[4], h[5]);
    *(__half2*)(Oh + d1 + 2) = __half2(h[6], h[7]);
    *(__half2*)(Ol + d0)     = __half2(l[0], l[1]);
    *(__half2*)(Ol + d0 + 2) = __half2(l[2], l[3]);
    *(__half2*)(Ol + d1)     = __half2(l[4], l[5]);
    *(__half2*)(Ol + d1 + 2) = __half2(l[6], l[7]);
}

// ---------------------------------------------------------------------------
// kernel_launch
// ---------------------------------------------------------------------------
extern "C" void kernel_launch(void* const* d_in, const int* in_sizes, int n_in,
                              void* d_out, int out_size)
{
    const float* hs = (const float*)d_in[0];
    const float* Wq = (const float*)d_in[1];
    const float* Wk = (const float*)d_in[2];
    const float* Wv = (const float*)d_in[3];
    const float* Wg = (const float*)d_in[4];
    const float* Wo = (const float*)d_in[5];
    const float* gw = (const float*)d_in[6];
    float* out = (float*)d_out;

    __half *hsh, *hsl;
    __half *qw, *kw, *vw, *gwt, *ow;
    cudaGetSymbolAddress((void**)&hsh, g_hs_hi);
    cudaGetSymbolAddress((void**)&hsl, g_hs_lo);
    cudaGetSymbolAddress((void**)&qw, g_WqT);
    cudaGetSymbolAddress((void**)&kw, g_WkT);
    cudaGetSymbolAddress((void**)&vw, g_WvT);
    cudaGetSymbolAddress((void**)&gwt, g_WgT);
    cudaGetSymbolAddress((void**)&ow, g_WoT);

    cudaFuncSetAttribute(qkvg_gemm, cudaFuncAttributeMaxDynamicSharedMemorySize, TCG_SMEM);
    cudaFuncSetAttribute(wo_gemm,   cudaFuncAttributeMaxDynamicSharedMemorySize, TCG_SMEM);
    cudaFuncSetAttribute(chunk_state_kernel, cudaFuncAttributeMaxDynamicSharedMemorySize, ATTA_SMEM);
    cudaFuncSetAttribute(attn_chunk_kernel,  cudaFuncAttributeMaxDynamicSharedMemorySize, ATTC_SMEM);

    dim3 blk(256);

    // 1) prep: hs split + RoPE table + weight transposes
    split_kernel<<<(MROWS*HQ/4 + 255)/256, blk>>>(hs, hsh, hsl, MROWS*HQ/4);
    rope_table_kernel<<<LQ*64/256, blk>>>();
    TDescs ds;
    ds.d[0] = { Wq, qw,  HQ,    HQ,    0    };
    ds.d[1] = { Wk, kw,  HQ,    HQ,    1024 };
    ds.d[2] = { Wv, vw,  HQ,    VDIMQ, 2048 };
    ds.d[3] = { Wg, gwt, HQ,    VDIMQ, 4096 };
    ds.d[4] = { Wo, ow,  VDIMQ, HQ,    6144 };
    transpose_multi<<<8192, blk>>>(ds);

    // 2) mega QKVG projection (emits Q hi/lo, K hi + Kdec, V hi, G)
    qkvg_gemm<<<dim3(48, MROWS/128), blk, TCG_SMEM>>>();

    // 3) chunked-recurrent retention: states -> scan -> outputs
    chunk_state_kernel<<<dim3(NCH, 16), 512, ATTA_SMEM>>>();
    scan_kernel<<<dim3(64, 16), 512>>>();
    attn_chunk_kernel<<<dim3(2, NCH, 16), 512, ATTC_SMEM>>>();

    // 4) fused RMSNorm + swish gate + split
    normgate_split_kernel<<<4096, blk>>>(gw);

    // 5) output projection
    wo_gemm<<<dim3(HQ/128, MROWS/128), blk, TCG_SMEM>>>(out);
}

// round 12
// speedup vs baseline: 1.2347x; 1.1173x over previous
#include <cuda_runtime.h>
#include <cuda_fp16.h>
#include <math.h>
#include <stdint.h>

// Problem constants
#define BQ 2
#define LQ 2048
#define HQ 1024
#define NHQ 8
#define DQKQ 128
#define DVQ 256
#define VDIMQ 2048
#define MROWS (BQ*LQ)   // 4096
#define CHK 128         // retention chunk size
#define NCH (LQ/CHK)    // 16 chunks per sequence

#define QSCALE 0.08838834764831843f          // 128^-0.5
#define RF (-0.20762050593045852f)           // -2*log2(10000)/128

// ---------------------------------------------------------------------------
// Scratch (device globals)
// ---------------------------------------------------------------------------
__device__ float g_G[MROWS*VDIMQ];
__device__ float g_O[MROWS*VDIMQ];
__device__ float g_A[16*NCH*DQKQ*DVQ];            // per-chunk KV outer products
__device__ float2 g_rope[LQ*64];                  // (cos, sin) per (t, pair)

__device__ __half g_hs_hi[MROWS*HQ],  g_hs_lo[MROWS*HQ];
__device__ __half g_O_hi[MROWS*VDIMQ], g_O_lo[MROWS*VDIMQ];
__device__ __half g_Qhi[MROWS*HQ],    g_Qlo[MROWS*HQ];
__device__ __half g_Khi[MROWS*HQ];
__device__ __half g_Kdec[MROWS*HQ];               // K * lam^(CHK - r%CHK)
__device__ __half g_Vhi[MROWS*VDIMQ];
__device__ __half g_Shi[16*NCH*DQKQ*DVQ];         // chunk-entry states hi
__device__ __half g_Slo[16*NCH*DQKQ*DVQ];         // chunk-entry states lo
__device__ __half g_WqT[HQ*HQ];
__device__ __half g_WkT[HQ*HQ];
__device__ __half g_WvT[VDIMQ*HQ];
__device__ __half g_WgT[VDIMQ*HQ];
__device__ __half g_WoT[HQ*VDIMQ];

// ---------------------------------------------------------------------------
// PTX helpers
// ---------------------------------------------------------------------------
__device__ __forceinline__ uint32_t smem_u32(const void* p) {
    uint32_t a;
    asm("{ .reg .u64 t; cvta.to.shared.u64 t, %1; cvt.u32.u64 %0, t; }"
        : "=r"(a) : "l"(p));
    return a;
}
__device__ __forceinline__ void ldgsts16(uint32_t dst, const void* src) {
    asm volatile("cp.async.cg.shared.global [%0], [%1], 16;" :: "r"(dst), "l"(src));
}
__device__ __forceinline__ void cp_commit() {
    asm volatile("cp.async.commit_group;" ::: "memory");
}
template<int N_>
__device__ __forceinline__ void cp_wait() {
    asm volatile("cp.async.wait_group %0;" :: "n"(N_) : "memory");
}
__device__ __forceinline__ void ldsm4(uint32_t* r, uint32_t addr) {
    asm volatile("ldmatrix.sync.aligned.m8n8.x4.shared.b16 {%0,%1,%2,%3}, [%4];"
        : "=r"(r[0]), "=r"(r[1]), "=r"(r[2]), "=r"(r[3]) : "r"(addr));
}
__device__ __forceinline__ void ldsm4t(uint32_t* r, uint32_t addr) {
    asm volatile("ldmatrix.sync.aligned.m8n8.x4.trans.shared.b16 {%0,%1,%2,%3}, [%4];"
        : "=r"(r[0]), "=r"(r[1]), "=r"(r[2]), "=r"(r[3]) : "r"(addr));
}
__device__ __forceinline__ void sts32(uint32_t addr, uint32_t v) {
    asm volatile("st.shared.b32 [%0], %1;" :: "r"(addr), "r"(v) : "memory");
}
__device__ __forceinline__ void mma_fp16(float* c, const uint32_t* a, const uint32_t* b) {
    asm volatile("mma.sync.aligned.m16n8k16.row.col.f32.f16.f16.f32 "
        "{%0,%1,%2,%3}, {%4,%5,%6,%7}, {%8,%9}, {%0,%1,%2,%3};"
        : "+f"(c[0]), "+f"(c[1]), "+f"(c[2]), "+f"(c[3])
        : "r"(a[0]), "r"(a[1]), "r"(a[2]), "r"(a[3]), "r"(b[0]), "r"(b[1]));
}
__device__ __forceinline__ uint32_t pack_h2(float a, float b) {
    __half2 t = __floats2half2_rn(a, b);
    return *(uint32_t*)&t;
}

// Swizzles: row stride in bytes; 16B chunk xor'd by (r&7)
#define SW128R(r, c) ((uint32_t)((r) * 128u + ((uint32_t)((c) ^ ((r) & 7)) << 4)))
#define SW256(r, c)  ((uint32_t)((r) * 256u + ((uint32_t)((c) ^ ((r) & 7)) << 4)))
#define SW512(r, c)  ((uint32_t)((r) * 512u + ((uint32_t)((c) ^ ((r) & 7)) << 4)))

// GEMM: K-chunk 64; tiles Ahi|Alo|Bhi of 128x64 fp16 = 16KB each; 2 stages
// (96KB/CTA -> 2 CTAs resident per SM for cross-CTA latency hiding)
#define GST_AHI 0
#define GST_ALO 16384
#define GST_BHI 32768
#define G_STAGE 49152
#define TCG_SMEM (2 * G_STAGE)

// ---------------------------------------------------------------------------
// hs split -> fp16 hi/lo
// ---------------------------------------------------------------------------
__global__ void __launch_bounds__(256) split_kernel(const float* __restrict__ x,
                                                    __half* __restrict__ hi,
                                                    __half* __restrict__ lo,
                                                    int n4)
{
    int i = blockIdx.x * 256 + threadIdx.x;
    if (i >= n4) return;
    float4 v = ((const float4*)x)[i];
    __half h0 = __float2half(v.x), h1 = __float2half(v.y);
    __half h2 = __float2half(v.z), h3 = __float2half(v.w);
    __half l0 = __float2half(v.x - __half2float(h0));
    __half l1 = __float2half(v.y - __half2float(h1));
    __half l2 = __float2half(v.z - __half2float(h2));
    __half l3 = __float2half(v.w - __half2float(h3));
    ((__half2*)hi)[2*i]   = __half2(h0, h1);
    ((__half2*)hi)[2*i+1] = __half2(h2, h3);
    ((__half2*)lo)[2*i]   = __half2(l0, l1);
    ((__half2*)lo)[2*i+1] = __half2(l2, l3);
}

// ---------------------------------------------------------------------------
// RoPE table: g_rope[t*64 + p] = (cos, sin) of t * base^(-2p/128).
// ---------------------------------------------------------------------------
__global__ void __launch_bounds__(256) rope_table_kernel()
{
    int i = blockIdx.x * 256 + threadIdx.x;    // 0..131071
    int t = i >> 6, p = i & 63;
    float inv = exp2f((float)p * RF);
    float s, c;
    sincosf((float)t * inv, &s, &c);
    g_rope[i] = make_float2(c, s);
}

// ---------------------------------------------------------------------------
// Merged weight transpose (fp16): one launch for all 5 weights.
// ---------------------------------------------------------------------------
struct TDesc { const float* W; __half* hi; int K, N, start; };
struct TDescs { TDesc d[5]; };

__global__ void __launch_bounds__(256) transpose_multi(TDescs ds)
{
    __shared__ float s[32][33];
    int t = blockIdx.x;
    int i = 0;
    #pragma unroll
    for (int j = 1; j < 5; j++) if (t >= ds.d[j].start) i = j;
    const float* W = ds.d[i].W;
    __half* Th = ds.d[i].hi;
    const int K = ds.d[i].K, N = ds.d[i].N;
    int lt = t - ds.d[i].start;
    int ncols = N >> 5;
    int k0 = (lt / ncols) * 32;
    int n0 = (lt % ncols) * 32;

    const int tx = threadIdx.x & 31;
    const int ty = threadIdx.x >> 5;
    #pragma unroll
    for (int q = 0; q < 4; q++)
        s[ty + 8*q][tx] = W[(size_t)(k0 + ty + 8*q) * N + n0 + tx];
    __syncthreads();
    #pragma unroll
    for (int q = 0; q < 4; q++) {
        float v = s[tx][ty + 8*q];
        Th[(size_t)(n0 + ty + 8*q) * K + k0 + tx] = __float2half(v);
    }
}

// ---------------------------------------------------------------------------
// GEMM mainloop: 128x128 tile, 8 warps (64x32), K-chunk 64, 2-stage pipeline.
// 2-term fp16: A hi/lo, B hi (pre-transposed K-major).
// ---------------------------------------------------------------------------
struct GemmOps {
    const __half *Ah, *Al, *Bh;
    int K, row0, bcol0;
};

__device__ __forceinline__ void gemm_mainloop(const GemmOps& op, uint32_t sbase,
                                              float acc[4][4][4])
{
    const int tid  = threadIdx.x;
    const int wid  = tid >> 5;
    const int lane = tid & 31;
    const int wm   = (wid & 1) * 64;
    const int wn   = (wid >> 1) * 32;
    const int K    = op.K;
    const int nchunks = K >> 6;

    auto load_chunk = [&](uint32_t sb, int k0) {
        #pragma unroll
        for (int t = 0; t < 4; t++) {
            int idx = tid + t * 256;
            int r   = idx >> 3;
            int c   = idx & 7;
            uint32_t soff = SW128R(r, c);
            size_t aoff = (size_t)(op.row0 + r) * K + k0 + c * 8;
            size_t boff = (size_t)(op.bcol0 + r) * K + k0 + c * 8;
            ldgsts16(sb + GST_AHI + soff, op.Ah + aoff);
            ldgsts16(sb + GST_ALO + soff, op.Al + aoff);
            ldgsts16(sb + GST_BHI + soff, op.Bh + boff);
        }
        cp_commit();
    };

    load_chunk(sbase, 0);
    if (nchunks > 1) load_chunk(sbase + G_STAGE, 64);

    for (int cch = 0; cch < nchunks; cch++) {
        const uint32_t sb = sbase + (uint32_t)(cch & 1) * G_STAGE;
        if (cch + 1 < nchunks) {
            cp_wait<1>();
        } else {
            cp_wait<0>();
        }
        __syncthreads();

        #pragma unroll
        for (int ks = 0; ks < 4; ks++) {
            uint32_t ahi[4][4], alo[4][4];
            #pragma unroll
            for (int mi = 0; mi < 4; mi++) {
                int r = wm + mi * 16 + (lane & 15);
                int c = ks * 2 + (lane >> 4);
                uint32_t ad = sb + GST_AHI + SW128R(r, c);
                ldsm4(ahi[mi], ad);
                ldsm4(alo[mi], ad + (GST_ALO - GST_AHI));
            }
            uint32_t bhi[4][2];
            #pragma unroll
            for (int j = 0; j < 2; j++) {
                int m4 = lane >> 3;
                int n  = wn + j * 16 + ((m4 >> 1) << 3) + (lane & 7);
                int c  = ks * 2 + (m4 & 1);
                uint32_t rh[4];
                ldsm4(rh, sb + GST_BHI + SW128R(n, c));
                bhi[2*j][0] = rh[0]; bhi[2*j][1] = rh[1];
                bhi[2*j+1][0] = rh[2]; bhi[2*j+1][1] = rh[3];
            }
            #pragma unroll
            for (int mi = 0; mi < 4; mi++)
                #pragma unroll
                for (int ni = 0; ni < 4; ni++) {
                    mma_fp16(acc[mi][ni], ahi[mi], bhi[ni]);
                    mma_fp16(acc[mi][ni], alo[mi], bhi[ni]);
                }
        }
        __syncthreads();
        if (cch + 2 < nchunks) load_chunk(sb, (cch + 2) * 64);
    }
}

// ---------------------------------------------------------------------------
// Mega QKVG GEMM: grid (48, 32). cb<8: Q | cb<16: K (+Kdec) | cb<32: V | else G
// ---------------------------------------------------------------------------
__global__ void __launch_bounds__(256, 2) qkvg_gemm()
{
    extern __shared__ char smem[];
    const uint32_t sbase = smem_u32(smem);
    const int tid  = threadIdx.x;
    const int wid  = tid >> 5;
    const int lane = tid & 31;
    const int row0 = blockIdx.y * 128;
    const int cb   = blockIdx.x;
    const int wm   = (wid & 1) * 64;
    const int wn   = (wid >> 1) * 32;

    int mode, lcol0;
    const __half* Bh;
    if (cb < 8)       { mode = 0; lcol0 = cb * 128;        Bh = g_WqT; }
    else if (cb < 16) { mode = 1; lcol0 = (cb - 8) * 128;  Bh = g_WkT; }
    else if (cb < 32) { mode = 2; lcol0 = (cb - 16) * 128; Bh = g_WvT; }
    else              { mode = 3; lcol0 = (cb - 32) * 128; Bh = g_WgT; }

    float acc[4][4][4];
    #pragma unroll
    for (int mi = 0; mi < 4; mi++)
        #pragma unroll
        for (int ni = 0; ni < 4; ni++)
            #pragma unroll
            for (int e = 0; e < 4; e++) acc[mi][ni][e] = 0.0f;

    GemmOps op{ g_hs_hi, g_hs_lo, Bh, HQ, row0, lcol0 };
    gemm_mainloop(op, sbase, acc);

    // K decay scale (constant per CTA for mode 1: head = cb-8)
    float sdecK = 0.0f;
    if (mode == 1) sdecK = log2f(1.0f - exp2f(-5.0f - (float)(cb - 8)));

    #pragma unroll
    for (int mi = 0; mi < 4; mi++) {
        const int row = row0 + wm + mi * 16 + (lane >> 2);
        #pragma unroll
        for (int ni = 0; ni < 4; ni++) {
            const int col = lcol0 + wn + ni * 8 + 2 * (lane & 3);
            float v0 = acc[mi][ni][0], v1 = acc[mi][ni][1];
            float v2 = acc[mi][ni][2], v3 = acc[mi][ni][3];
            if (mode <= 1) {   // Q or K: scale + RoPE (table lookup)
                if (mode == 0) { v0 *= QSCALE; v1 *= QSCALE; v2 *= QSCALE; v3 *= QSCALE; }
                const int p = (col & 127) >> 1;
                float2 cs0 = g_rope[(row & (LQ - 1)) * 64 + p];
                float2 cs1 = g_rope[((row + 8) & (LQ - 1)) * 64 + p];
                float x0 = v0, x1 = v1;
                v0 = x0 * cs0.x - x1 * cs0.y;
                v1 = x1 * cs0.x + x0 * cs0.y;
                x0 = v2; x1 = v3;
                v2 = x0 * cs1.x - x1 * cs1.y;
                v3 = x1 * cs1.x + x0 * cs1.y;
                if (mode == 0) {   // Q: fp16 hi/lo
                    __half h0 = __float2half(v0), h1 = __float2half(v1);
                    __half h2 = __float2half(v2), h3 = __float2half(v3);
                    __half l0 = __float2half(v0 - __half2float(h0));
                    __half l1 = __float2half(v1 - __half2float(h1));
                    __half l2 = __float2half(v2 - __half2float(h2));
                    __half l3 = __float2half(v3 - __half2float(h3));
                    *(__half2*)(g_Qhi + (size_t)row * HQ + col)       = __half2(h0, h1);
                    *(__half2*)(g_Qhi + (size_t)(row + 8) * HQ + col) = __half2(h2, h3);
                    *(__half2*)(g_Qlo + (size_t)row * HQ + col)       = __half2(l0, l1);
                    *(__half2*)(g_Qlo + (size_t)(row + 8) * HQ + col) = __half2(l2, l3);
                } else {           // K: hi + decayed copy
                    *(__half2*)(g_Khi + (size_t)row * HQ + col)       = __floats2half2_rn(v0, v1);
                    *(__half2*)(g_Khi + (size_t)(row + 8) * HQ + col) = __floats2half2_rn(v2, v3);
                    float p0 = exp2f(sdecK * (float)(CHK - (row & (CHK - 1))));
                    float p1 = exp2f(sdecK * (float)(CHK - ((row + 8) & (CHK - 1))));
                    *(__half2*)(g_Kdec + (size_t)row * HQ + col)       = __floats2half2_rn(v0 * p0, v1 * p0);
                    *(__half2*)(g_Kdec + (size_t)(row + 8) * HQ + col) = __floats2half2_rn(v2 * p1, v3 * p1);
                }
            } else if (mode == 2) {
                *(__half2*)(g_Vhi + (size_t)row * VDIMQ + col)       = __floats2half2_rn(v0, v1);
                *(__half2*)(g_Vhi + (size_t)(row + 8) * VDIMQ + col) = __floats2half2_rn(v2, v3);
            } else {
                *(float2*)(g_G + (size_t)row * VDIMQ + col)       = make_float2(v0, v1);
                *(float2*)(g_G + (size_t)(row + 8) * VDIMQ + col) = make_float2(v2, v3);
            }
        }
    }
}

// ---------------------------------------------------------------------------
// Wo GEMM: fp32 out. K=2048, N=1024.
// ---------------------------------------------------------------------------
__global__ void __launch_bounds__(256, 2) wo_gemm(float* __restrict__ C)
{
    extern __shared__ char smem[];
    const uint32_t sbase = smem_u32(smem);
    const int tid  = threadIdx.x;
    const int wid  = tid >> 5;
    const int lane = tid & 31;
    const int row0 = blockIdx.y * 128;
    const int col0 = blockIdx.x * 128;
    const int wm   = (wid & 1) * 64;
    const int wn   = (wid >> 1) * 32;

    float acc[4][4][4];
    #pragma unroll
    for (int mi = 0; mi < 4; mi++)
        #pragma unroll
        for (int ni = 0; ni < 4; ni++)
            #pragma unroll
            for (int e = 0; e < 4; e++) acc[mi][ni][e] = 0.0f;

    GemmOps op{ g_O_hi, g_O_lo, g_WoT, VDIMQ, row0, col0 };
    gemm_mainloop(op, sbase, acc);

    #pragma unroll
    for (int mi = 0; mi < 4; mi++) {
        const int row = row0 + wm + mi * 16 + (lane >> 2);
        #pragma unroll
        for (int ni = 0; ni < 4; ni++) {
            const int col = col0 + wn + ni * 8 + 2 * (lane & 3);
            *(float2*)(C + (size_t)row * HQ + col) =
                make_float2(acc[mi][ni][0], acc[mi][ni][1]);
            *(float2*)(C + (size_t)(row + 8) * HQ + col) =
                make_float2(acc[mi][ni][2], acc[mi][ni][3]);
        }
    }
}

// ---------------------------------------------------------------------------
// Attention Kernel A: per-chunk outer product  A_c = Kdec_c^T V_c
// ---------------------------------------------------------------------------
#define ATTA_SMEM 98304

__global__ void __launch_bounds__(512) chunk_state_kernel()
{
    extern __shared__ char smem[];
    const uint32_t SB   = smem_u32(smem);
    const uint32_t kbuf = SB;            // [128 r][128 d1] fp16 SW256
    const uint32_t vbuf = SB + 32768;    // [128 r][256 d2] fp16 SW512

    const int ch = blockIdx.x, bh = blockIdx.y;
    const int b = bh >> 3, h = bh & 7;
    const int tid = threadIdx.x, wid = tid >> 5, lane = tid & 31;
    const int trow = ch * CHK;

    const __half* Kd_g = g_Kdec + (size_t)(b * LQ + trow) * HQ + h * DQKQ;
    const __half* Vh_g = g_Vhi + (size_t)(b * LQ + trow) * VDIMQ + h * DVQ;

    #pragma unroll
    for (int t = 0; t < 4; t++) {
        int idx = tid + t * 512;
        int r = idx >> 4, cc = idx & 15;
        ldgsts16(kbuf + SW256(r, cc), Kd_g + (size_t)r * HQ + cc * 8);
    }
    #pragma unroll
    for (int t = 0; t < 8; t++) {
        int idx = tid + t * 512;
        int r = idx >> 5, cc = idx & 31;
        ldgsts16(vbuf + SW512(r, cc), Vh_g + (size_t)r * VDIMQ + cc * 8);
    }
    cp_commit();
    cp_wait<0>();
    __syncthreads();

    const int wm = (wid & 3) * 32;
    const int wn = (wid >> 2) * 64;

    float acc[2][8][4];
    #pragma unroll
    for (int mi = 0; mi < 2; mi++)
        #pragma unroll
        for (int nt = 0; nt < 8; nt++)
            #pragma unroll
            for (int e = 0; e < 4; e++) acc[mi][nt][e] = 0.0f;

    #pragma unroll
    for (int ks = 0; ks < 8; ks++) {
        uint32_t af[2][4];
        #pragma unroll
        for (int mi = 0; mi < 2; mi++) {
            int m0 = wm + mi * 16;
            int r_src = ks * 16 + ((lane >> 4) << 3) + (lane & 7);
            int d_off = (m0 >> 3) + ((lane >> 3) & 1);
            ldsm4t(af[mi], kbuf + SW256(r_src, d_off));
        }
        uint32_t bf[8][2];
        #pragma unroll
        for (int np = 0; np < 4; np++) {
            int row = ks * 16 + ((lane >> 3) & 1) * 8 + (lane & 7);
            int cn  = (wn + np * 16 + (lane >> 4) * 8) >> 3;
            uint32_t rh[4];
            ldsm4t(rh, vbuf + SW512(row, cn));
            bf[2*np][0] = rh[0]; bf[2*np][1] = rh[1];
            bf[2*np+1][0] = rh[2]; bf[2*np+1][1] = rh[3];
        }
        #pragma unroll
        for (int mi = 0; mi < 2; mi++)
            #pragma unroll
            for (int nt = 0; nt < 8; nt++)
                mma_fp16(acc[mi][nt], af[mi], bf[nt]);
    }

    float* Ag = g_A + ((size_t)(bh * NCH + ch) << 15);
    #pragma unroll
    for (int mi = 0; mi < 2; mi++) {
        int d1 = wm + mi * 16 + (lane >> 2);
        #pragma unroll
        for (int nt = 0; nt < 8; nt++) {
            int d2 = wn + nt * 8 + 2 * (lane & 3);
            *(float2*)(Ag + (size_t)d1 * DVQ + d2) =
                make_float2(acc[mi][nt][0], acc[mi][nt][1]);
            *(float2*)(Ag + (size_t)(d1 + 8) * DVQ + d2) =
                make_float2(acc[mi][nt][2], acc[mi][nt][3]);
        }
    }
}

// ---------------------------------------------------------------------------
// Attention Kernel B: per-element decay scan over chunks -> states S_c (hi/lo)
// ---------------------------------------------------------------------------
__global__ void __launch_bounds__(512) scan_kernel()
{
    const int e  = blockIdx.x * 512 + threadIdx.x;
    const int bh = blockIdx.y;
    const int h  = bh & 7;
    const float sdec = log2f(1.0f - exp2f(-5.0f - (float)h));
    const float lamC = exp2f(sdec * (float)CHK);

    const size_t base = (size_t)bh * NCH << 15;
    float S = 0.0f;
    #pragma unroll
    for (int c = 0; c < NCH; c++) {
        size_t off = base + ((size_t)c << 15) + e;
        __half hi = __float2half(S);
        g_Shi[off] = hi;
        g_Slo[off] = __float2half(S - __half2float(hi));
        S = S * lamC + g_A[off];
    }
}

// ---------------------------------------------------------------------------
// Attention Kernel C: per (chunk, bh, dv-half) output.
// O = (QK^T ∘ decay) V + lam^r (Q S_c).  No atomics.
// ---------------------------------------------------------------------------
#define ATTC_SMEM 229376

__global__ void __launch_bounds__(512) attn_chunk_kernel()
{
    extern __shared__ char smem[];
    const uint32_t SB  = smem_u32(smem);
    const uint32_t sQh = SB;
    const uint32_t sQl = SB + 32768;
    const uint32_t sK  = SB + 65536;
    const uint32_t sSh = SB + 98304;
    const uint32_t sSl = SB + 131072;
    const uint32_t sV  = SB + 163840;
    const uint32_t sPl = SB + 196608;
    const uint32_t sPh = sK;            // aliased after K consumed

    const int vh = blockIdx.x;
    const int ch = blockIdx.y;
    const int bh = blockIdx.z;
    const int b = bh >> 3, h = bh & 7;
    const int tid = threadIdx.x, wid = tid >> 5, lane = tid & 31;
    const int trow = ch * CHK;
    const float sdec = log2f(1.0f - exp2f(-5.0f - (float)h));

    const __half* Qh_g = g_Qhi + (size_t)(b * LQ + trow) * HQ + h * DQKQ;
    const __half* Ql_g = g_Qlo + (size_t)(b * LQ + trow) * HQ + h * DQKQ;
    const __half* Kh_g = g_Khi + (size_t)(b * LQ + trow) * HQ + h * DQKQ;
    const __half* Vh_g = g_Vhi + (size_t)(b * LQ + trow) * VDIMQ + h * DVQ + vh * 128;
    const __half* Sh_g = g_Shi + ((size_t)(bh * NCH + ch) << 15) + vh * 128;
    const __half* Sl_g = g_Slo + ((size_t)(bh * NCH + ch) << 15) + vh * 128;

    #pragma unroll
    for (int t = 0; t < 4; t++) {
        int idx = tid + t * 512;
        int r = idx >> 4, cc = idx & 15;
        ldgsts16(sQh + SW256(r, cc), Qh_g + (size_t)r * HQ + cc * 8);
        ldgsts16(sQl + SW256(r, cc), Ql_g + (size_t)r * HQ + cc * 8);
        ldgsts16(sK  + SW256(r, cc), Kh_g + (size_t)r * HQ + cc * 8);
    }
    cp_commit();
    #pragma unroll
    for (int t = 0; t < 4; t++) {
        int idx = tid + t * 512;
        int r = idx >> 4, cc = idx & 15;
        ldgsts16(sSh + SW256(r, cc), Sh_g + (size_t)r * DVQ + cc * 8);
        ldgsts16(sSl + SW256(r, cc), Sl_g + (size_t)r * DVQ + cc * 8);
        ldgsts16(sV  + SW256(r, cc), Vh_g + (size_t)r * VDIMQ + cc * 8);
    }
    cp_commit();

    const int wm = (wid & 3) * 32;
    const int wn = (wid >> 2) * 32;

    cp_wait<1>();
    __syncthreads();

    // ---- P = Q K^T (128x128), 2 terms ----
    float sacc[2][4][4];
    #pragma unroll
    for (int mi = 0; mi < 2; mi++)
        #pragma unroll
        for (int ni = 0; ni < 4; ni++)
            #pragma unroll
            for (int e = 0; e < 4; e++) sacc[mi][ni][e] = 0.0f;

    #pragma unroll
    for (int ks = 0; ks < 8; ks++) {
        uint32_t qh[2][4], ql[2][4];
        #pragma unroll
        for (int mi = 0; mi < 2; mi++) {
            int r = wm + mi * 16 + (lane & 15);
            int cc = ks * 2 + (lane >> 4);
            uint32_t ad = sQh + SW256(r, cc);
            ldsm4(qh[mi], ad);
            ldsm4(ql[mi], ad + 32768);
        }
        uint32_t kb[4][2];
        #pragma unroll
        for (int j = 0; j < 2; j++) {
            int m4 = lane >> 3;
            int n  = wn + j * 16 + ((m4 >> 1) << 3) + (lane & 7);
            int cc = ks * 2 + (m4 & 1);
            uint32_t rh[4];
            ldsm4(rh, sK + SW256(n, cc));
            kb[2*j][0] = rh[0]; kb[2*j][1] = rh[1];
            kb[2*j+1][0] = rh[2]; kb[2*j+1][1] = rh[3];
        }
        #pragma unroll
        for (int mi = 0; mi < 2; mi++)
            #pragma unroll
            for (int ni = 0; ni < 4; ni++) {
                mma_fp16(sacc[mi][ni], qh[mi], kb[ni]);
                mma_fp16(sacc[mi][ni], ql[mi], kb[ni]);
            }
    }
    __syncthreads();

    // ---- decay + causal + split -> store P hi/lo ----
    #pragma unroll
    for (int mi = 0; mi < 2; mi++) {
        int r0 = wm + mi * 16 + (lane >> 2);
        #pragma unroll
        for (int ni = 0; ni < 4; ni++) {
            int j0 = wn + ni * 8 + 2 * (lane & 3);
            float d00 = (r0 >= j0)         ? exp2f(sdec * (float)(r0 - j0))     : 0.0f;
            float d01 = (r0 >= j0 + 1)     ? exp2f(sdec * (float)(r0 - j0 - 1)) : 0.0f;
            float d10 = (r0 + 8 >= j0)     ? exp2f(sdec * (float)(r0 + 8 - j0))     : 0.0f;
            float d11 = (r0 + 8 >= j0 + 1) ? exp2f(sdec * (float)(r0 + 8 - j0 - 1)) : 0.0f;
            float v0 = sacc[mi][ni][0] * d00, v1 = sacc[mi][ni][1] * d01;
            float v2 = sacc[mi][ni][2] * d10, v3 = sacc[mi][ni][3] * d11;
            float h0 = __half2float(__float2half(v0));
            float h1 = __half2float(__float2half(v1));
            float h2 = __half2float(__float2half(v2));
            float h3 = __half2float(__float2half(v3));
            int cc = j0 >> 3;
            int off = (j0 & 7) * 2;
            sts32(sPh + SW256(r0, cc) + off,     pack_h2(v0, v1));
            sts32(sPl + SW256(r0, cc) + off,     pack_h2(v0 - h0, v1 - h1));
            sts32(sPh + SW256(r0 + 8, cc) + off, pack_h2(v2, v3));
            sts32(sPl + SW256(r0 + 8, cc) + off, pack_h2(v2 - h2, v3 - h3));
        }
    }
    cp_wait<0>();
    __syncthreads();

    // ---- X = Q @ S (128x128), 3 terms ----
    float xacc[2][4][4];
    #pragma unroll
    for (int mi = 0; mi < 2; mi++)
        #pragma unroll
        for (int ni = 0; ni < 4; ni++)
            #pragma unroll
            for (int e = 0; e < 4; e++) xacc[mi][ni][e] = 0.0f;

    #pragma unroll
    for (int ks = 0; ks < 8; ks++) {
        uint32_t qh[2][4], ql[2][4];
        #pragma unroll
        for (int mi = 0; mi < 2; mi++) {
            int r = wm + mi * 16 + (lane & 15);
            int cc = ks * 2 + (lane >> 4);
            uint32_t ad = sQh + SW256(r, cc);
            ldsm4(qh[mi], ad);
            ldsm4(ql[mi], ad + 32768);
        }
        uint32_t sbh[4][2], sbl[4][2];
        #pragma unroll
        for (int np = 0; np < 2; np++) {
            int row = ks * 16 + ((lane >> 3) & 1) * 8 + (lane & 7);
            int cn  = (wn + np * 16 + (lane >> 4) * 8) >> 3;
            uint32_t rh[4], rl[4];
            ldsm4t(rh, sSh + SW256(row, cn));
            ldsm4t(rl, sSl + SW256(row, cn));
            sbh[2*np][0] = rh[0]; sbh[2*np][1] = rh[1];
            sbh[2*np+1][0] = rh[2]; sbh[2*np+1][1] = rh[3];
            sbl[2*np][0] = rl[0]; sbl[2*np][1] = rl[1];
            sbl[2*np+1][0] = rl[2]; sbl[2*np+1][1] = rl[3];
        }
        #pragma unroll
        for (int mi = 0; mi < 2; mi++)
            #pragma unroll
            for (int ni = 0; ni < 4; ni++) {
                mma_fp16(xacc[mi][ni], qh[mi], sbh[ni]);
                mma_fp16(xacc[mi][ni], ql[mi], sbh[ni]);
                mma_fp16(xacc[mi][ni], qh[mi], sbl[ni]);
            }
    }

    // ---- O_intra = P @ V (128x128), 2 terms ----
    float oacc[2][4][4];
    #pragma unroll
    for (int mi = 0; mi < 2; mi++)
        #pragma unroll
        for (int ni = 0; ni < 4; ni++)
            #pragma unroll
            for (int e = 0; e < 4; e++) oacc[mi][ni][e] = 0.0f;

    #pragma unroll
    for (int ks = 0; ks < 8; ks++) {
        uint32_t ph[2][4], pl[2][4];
        #pragma unroll
        for (int mi = 0; mi < 2; mi++) {
            int r = wm + mi * 16 + (lane & 15);
            int cc = ks * 2 + (lane >> 4);
            ldsm4(ph[mi], sPh + SW256(r, cc));
            ldsm4(pl[mi], sPl + SW256(r, cc));
        }
        uint32_t vb[4][2];
        #pragma unroll
        for (int np = 0; np < 2; np++) {
            int row = ks * 16 + ((lane >> 3) & 1) * 8 + (lane & 7);
            int cn  = (wn + np * 16 + (lane >> 4) * 8) >> 3;
            uint32_t rh[4];
            ldsm4t(rh, sV + SW256(row, cn));
            vb[2*np][0] = rh[0]; vb[2*np][1] = rh[1];
            vb[2*np+1][0] = rh[2]; vb[2*np+1][1] = rh[3];
        }
        #pragma unroll
        for (int mi = 0; mi < 2; mi++)
            #pragma unroll
            for (int ni = 0; ni < 4; ni++) {
                mma_fp16(oacc[mi][ni], ph[mi], vb[ni]);
                mma_fp16(oacc[mi][ni], pl[mi], vb[ni]);
            }
    }

    // ---- combine + write O ----
    float* Og = g_O + (size_t)(b * LQ + trow) * VDIMQ + h * DVQ + vh * 128;
    #pragma unroll
    for (int mi = 0; mi < 2; mi++) {
        int r0 = wm + mi * 16 + (lane >> 2);
        float lam0 = exp2f(sdec * (float)r0);
        float lam1 = exp2f(sdec * (float)(r0 + 8));
        #pragma unroll
        for (int ni = 0; ni < 4; ni++) {
            int col = wn + ni * 8 + 2 * (lane & 3);
            *(float2*)(Og + (size_t)r0 * VDIMQ + col) =
                make_float2(oacc[mi][ni][0] + lam0 * xacc[mi][ni][0],
                            oacc[mi][ni][1] + lam0 * xacc[mi][ni][1]);
            *(float2*)(Og + (size_t)(r0 + 8) * VDIMQ + col) =
                make_float2(oacc[mi][ni][2] + lam1 * xacc[mi][ni][2],
                            oacc[mi][ni][3] + lam1 * xacc[mi][ni][3]);
        }
    }
}

// ---------------------------------------------------------------------------
// Fused RMSNorm + swish gate + split -> fp16 hi/lo
// ---------------------------------------------------------------------------
__global__ void __launch_bounds__(256) normgate_split_kernel(const float* __restrict__ gw)
{
    const int warp = (blockIdx.x << 3) + (threadIdx.x >> 5);
    const int lane = threadIdx.x & 31;
    const size_t base = (size_t)(warp >> 3) * VDIMQ + (size_t)(warp & 7) * DVQ;
    const float* Op = g_O + base;
    const float* Gp = g_G + base;
    __half* Oh = g_O_hi + base;
    __half* Ol = g_O_lo + base;

    const int d0 = lane * 4;
    const int d1 = 128 + lane * 4;
    float4 o0 = *(const float4*)(Op + d0);
    float4 o1 = *(const float4*)(Op + d1);

    float ss = o0.x*o0.x + o0.y*o0.y + o0.z*o0.z + o0.w*o0.w
             + o1.x*o1.x + o1.y*o1.y + o1.z*o1.z + o1.w*o1.w;
    #pragma unroll
    for (int off = 16; off > 0; off >>= 1)
        ss += __shfl_xor_sync(0xFFFFFFFFu, ss, off);

    const float r = rsqrtf(ss * (1.0f / 256.0f) + 1e-5f);

    float4 g0 = *(const float4*)(Gp + d0);
    float4 g1 = *(const float4*)(Gp + d1);
    float4 w0 = *(const float4*)(gw + d0);
    float4 w1 = *(const float4*)(gw + d1);

    float v[8];
    v[0] = o0.x * r * w0.x * (g0.x / (1.0f + expf(-g0.x)));
    v[1] = o0.y * r * w0.y * (g0.y / (1.0f + expf(-g0.y)));
    v[2] = o0.z * r * w0.z * (g0.z / (1.0f + expf(-g0.z)));
    v[3] = o0.w * r * w0.w * (g0.w / (1.0f + expf(-g0.w)));
    v[4] = o1.x * r * w1.x * (g1.x / (1.0f + expf(-g1.x)));
    v[5] = o1.y * r * w1.y * (g1.y / (1.0f + expf(-g1.y)));
    v[6] = o1.z * r * w1.z * (g1.z / (1.0f + expf(-g1.z)));
    v[7] = o1.w * r * w1.w * (g1.w / (1.0f + expf(-g1.w)));

    __half h[8], l[8];
    #pragma unroll
    for (int i = 0; i < 8; i++) {
        h[i] = __float2half(v[i]);
        l[i] = __float2half(v[i] - __half2float(h[i]));
    }
    *(__half2*)(Oh + d0)     = __half2(h[0], h[1]);
    *(__half2*)(Oh + d0 + 2) = __half2(h[2], h[3]);
    *(__half2*)(Oh + d1)     = __half2(h[4], h[5]);
    *(__half2*)(Oh + d1 + 2) = __half2(h[6], h[7]);
    *(__half2*)(Ol + d0)     = __half2(l[0], l[1]);
    *(__half2*)(Ol + d0 + 2) = __half2(l[2], l[3]);
    *(__half2*)(Ol + d1)     = __half2(l[4], l[5]);
    *(__half2*)(Ol + d1 + 2) = __half2(l[6], l[7]);
}

// ---------------------------------------------------------------------------
// kernel_launch
// ---------------------------------------------------------------------------
extern "C" void kernel_launch(void* const* d_in, const int* in_sizes, int n_in,
                              void* d_out, int out_size)
{
    const float* hs = (const float*)d_in[0];
    const float* Wq = (const float*)d_in[1];
    const float* Wk = (const float*)d_in[2];
    const float* Wv = (const float*)d_in[3];
    const float* Wg = (const float*)d_in[4];
    const float* Wo = (const float*)d_in[5];
    const float* gw = (const float*)d_in[6];
    float* out = (float*)d_out;

    __half *hsh, *hsl;
    __half *qw, *kw, *vw, *gwt, *ow;
    cudaGetSymbolAddress((void**)&hsh, g_hs_hi);
    cudaGetSymbolAddress((void**)&hsl, g_hs_lo);
    cudaGetSymbolAddress((void**)&qw, g_WqT);
    cudaGetSymbolAddress((void**)&kw, g_WkT);
    cudaGetSymbolAddress((void**)&vw, g_WvT);
    cudaGetSymbolAddress((void**)&gwt, g_WgT);
    cudaGetSymbolAddress((void**)&ow, g_WoT);

    cudaFuncSetAttribute(qkvg_gemm, cudaFuncAttributeMaxDynamicSharedMemorySize, TCG_SMEM);
    cudaFuncSetAttribute(wo_gemm,   cudaFuncAttributeMaxDynamicSharedMemorySize, TCG_SMEM);
    cudaFuncSetAttribute(chunk_state_kernel, cudaFuncAttributeMaxDynamicSharedMemorySize, ATTA_SMEM);
    cudaFuncSetAttribute(attn_chunk_kernel,  cudaFuncAttributeMaxDynamicSharedMemorySize, ATTC_SMEM);

    dim3 blk(256);

    // 1) prep: hs split + RoPE table + weight transposes
    split_kernel<<<(MROWS*HQ/4 + 255)/256, blk>>>(hs, hsh, hsl, MROWS*HQ/4);
    rope_table_kernel<<<LQ*64/256, blk>>>();
    TDescs ds;
    ds.d[0] = { Wq, qw,  HQ,    HQ,    0    };
    ds.d[1] = { Wk, kw,  HQ,    HQ,    1024 };
    ds.d[2] = { Wv, vw,  HQ,    VDIMQ, 2048 };
    ds.d[3] = { Wg, gwt, HQ,    VDIMQ, 4096 };
    ds.d[4] = { Wo, ow,  VDIMQ, HQ,    6144 };
    transpose_multi<<<8192, blk>>>(ds);

    // 2) mega QKVG projection (emits Q hi/lo, K hi + Kdec, V hi, G)
    qkvg_gemm<<<dim3(48, MROWS/128), blk, TCG_SMEM>>>();

    // 3) chunked-recurrent retention: states -> scan -> outputs
    chunk_state_kernel<<<dim3(NCH, 16), 512, ATTA_SMEM>>>();
    scan_kernel<<<dim3(64, 16), 512>>>();
    attn_chunk_kernel<<<dim3(2, NCH, 16), 512, ATTC_SMEM>>>();

    // 4) fused RMSNorm + swish gate + split
    normgate_split_kernel<<<4096, blk>>>(gw);

    // 5) output projection
    wo_gemm<<<dim3(HQ/128, MROWS/128), blk, TCG_SMEM>>>(out);
}

// round 14
// speedup vs baseline: 1.3141x; 1.0643x over previous
#include <cuda_runtime.h>
#include <cuda_fp16.h>
#include <math.h>
#include <stdint.h>

// Problem constants
#define BQ 2
#define LQ 2048
#define HQ 1024
#define NHQ 8
#define DQKQ 128
#define DVQ 256
#define VDIMQ 2048
#define MROWS (BQ*LQ)   // 4096
#define CHK 128         // retention chunk size
#define NCH (LQ/CHK)    // 16 chunks per sequence

#define QSCALE 0.08838834764831843f          // 128^-0.5
#define RF (-0.20762050593045852f)           // -2*log2(10000)/128

// ---------------------------------------------------------------------------
// Scratch (device globals)
// ---------------------------------------------------------------------------
__device__ float g_G[MROWS*VDIMQ];
__device__ float g_O[MROWS*VDIMQ];
__device__ float g_A[16*NCH*DQKQ*DVQ];            // per-chunk KV outer products
__device__ float2 g_rope[LQ*64];                  // (cos, sin) per (t, pair)

__device__ __half g_hs_hi[MROWS*HQ],  g_hs_lo[MROWS*HQ];
__device__ __half g_O_hi[MROWS*VDIMQ], g_O_lo[MROWS*VDIMQ];
__device__ __half g_Qhi[MROWS*HQ],    g_Qlo[MROWS*HQ];
__device__ __half g_Khi[MROWS*HQ];
__device__ __half g_Kdec[MROWS*HQ];               // K * lam^(CHK - r%CHK)
__device__ __half g_Vhi[MROWS*VDIMQ];
__device__ __half g_Shi[16*NCH*DQKQ*DVQ];         // chunk-entry states hi
__device__ __half g_Slo[16*NCH*DQKQ*DVQ];         // chunk-entry states lo
__device__ __half g_WqT[HQ*HQ];
__device__ __half g_WkT[HQ*HQ];
__device__ __half g_WvT[VDIMQ*HQ];
__device__ __half g_WgT[VDIMQ*HQ];
__device__ __half g_WoT[HQ*VDIMQ];

// ---------------------------------------------------------------------------
// PTX helpers
// ---------------------------------------------------------------------------
__device__ __forceinline__ uint32_t smem_u32(const void* p) {
    uint32_t a;
    asm("{ .reg .u64 t; cvta.to.shared.u64 t, %1; cvt.u32.u64 %0, t; }"
        : "=r"(a) : "l"(p));
    return a;
}
__device__ __forceinline__ void ldgsts16(uint32_t dst, const void* src) {
    asm volatile("cp.async.cg.shared.global [%0], [%1], 16;" :: "r"(dst), "l"(src));
}
__device__ __forceinline__ void cp_commit() {
    asm volatile("cp.async.commit_group;" ::: "memory");
}
template<int N_>
__device__ __forceinline__ void cp_wait() {
    asm volatile("cp.async.wait_group %0;" :: "n"(N_) : "memory");
}
__device__ __forceinline__ void ldsm4(uint32_t* r, uint32_t addr) {
    asm volatile("ldmatrix.sync.aligned.m8n8.x4.shared.b16 {%0,%1,%2,%3}, [%4];"
        : "=r"(r[0]), "=r"(r[1]), "=r"(r[2]), "=r"(r[3]) : "r"(addr));
}
__device__ __forceinline__ void ldsm4t(uint32_t* r, uint32_t addr) {
    asm volatile("ldmatrix.sync.aligned.m8n8.x4.trans.shared.b16 {%0,%1,%2,%3}, [%4];"
        : "=r"(r[0]), "=r"(r[1]), "=r"(r[2]), "=r"(r[3]) : "r"(addr));
}
__device__ __forceinline__ void sts32(uint32_t addr, uint32_t v) {
    asm volatile("st.shared.b32 [%0], %1;" :: "r"(addr), "r"(v) : "memory");
}
__device__ __forceinline__ void mma_fp16(float* c, const uint32_t* a, const uint32_t* b) {
    asm volatile("mma.sync.aligned.m16n8k16.row.col.f32.f16.f16.f32 "
        "{%0,%1,%2,%3}, {%4,%5,%6,%7}, {%8,%9}, {%0,%1,%2,%3};"
        : "+f"(c[0]), "+f"(c[1]), "+f"(c[2]), "+f"(c[3])
        : "r"(a[0]), "r"(a[1]), "r"(a[2]), "r"(a[3]), "r"(b[0]), "r"(b[1]));
}
__device__ __forceinline__ uint32_t pack_h2(float a, float b) {
    __half2 t = __floats2half2_rn(a, b);
    return *(uint32_t*)&t;
}

// Swizzles: row stride in bytes; 16B chunk xor'd by (r&7)
#define SW128R(r, c) ((uint32_t)((r) * 128u + ((uint32_t)((c) ^ ((r) & 7)) << 4)))
#define SW256(r, c)  ((uint32_t)((r) * 256u + ((uint32_t)((c) ^ ((r) & 7)) << 4)))
#define SW512(r, c)  ((uint32_t)((r) * 512u + ((uint32_t)((c) ^ ((r) & 7)) << 4)))

// GEMM tiles per operand: 128x64 fp16 = 16KB. 2-stage pipelines.
// 2-term stage: Ahi|Alo|Bhi = 48KB; 1-term stage: Ahi|Bhi = 32KB.
#define GST_ALO 16384
#define TCG_SMEM_2T (2 * 49152)
#define TCG_SMEM_1T (2 * 32768)

// ---------------------------------------------------------------------------
// hs split -> fp16 hi/lo
// ---------------------------------------------------------------------------
__global__ void __launch_bounds__(256) split_kernel(const float* __restrict__ x,
                                                    __half* __restrict__ hi,
                                                    __half* __restrict__ lo,
                                                    int n4)
{
    int i = blockIdx.x * 256 + threadIdx.x;
    if (i >= n4) return;
    float4 v = ((const float4*)x)[i];
    __half h0 = __float2half(v.x), h1 = __float2half(v.y);
    __half h2 = __float2half(v.z), h3 = __float2half(v.w);
    __half l0 = __float2half(v.x - __half2float(h0));
    __half l1 = __float2half(v.y - __half2float(h1));
    __half l2 = __float2half(v.z - __half2float(h2));
    __half l3 = __float2half(v.w - __half2float(h3));
    ((__half2*)hi)[2*i]   = __half2(h0, h1);
    ((__half2*)hi)[2*i+1] = __half2(h2, h3);
    ((__half2*)lo)[2*i]   = __half2(l0, l1);
    ((__half2*)lo)[2*i+1] = __half2(l2, l3);
}

// ---------------------------------------------------------------------------
// RoPE table
// ---------------------------------------------------------------------------
__global__ void __launch_bounds__(256) rope_table_kernel()
{
    int i = blockIdx.x * 256 + threadIdx.x;    // 0..131071
    int t = i >> 6, p = i & 63;
    float inv = exp2f((float)p * RF);
    float s, c;
    sincosf((float)t * inv, &s, &c);
    g_rope[i] = make_float2(c, s);
}

// ---------------------------------------------------------------------------
// Merged weight transpose (fp16): one launch for all 5 weights.
// ---------------------------------------------------------------------------
struct TDesc { const float* W; __half* hi; int K, N, start; };
struct TDescs { TDesc d[5]; };

__global__ void __launch_bounds__(256) transpose_multi(TDescs ds)
{
    __shared__ float s[32][33];
    int t = blockIdx.x;
    int i = 0;
    #pragma unroll
    for (int j = 1; j < 5; j++) if (t >= ds.d[j].start) i = j;
    const float* W = ds.d[i].W;
    __half* Th = ds.d[i].hi;
    const int K = ds.d[i].K, N = ds.d[i].N;
    int lt = t - ds.d[i].start;
    int ncols = N >> 5;
    int k0 = (lt / ncols) * 32;
    int n0 = (lt % ncols) * 32;

    const int tx = threadIdx.x & 31;
    const int ty = threadIdx.x >> 5;
    #pragma unroll
    for (int q = 0; q < 4; q++)
        s[ty + 8*q][tx] = W[(size_t)(k0 + ty + 8*q) * N + n0 + tx];
    __syncthreads();
    #pragma unroll
    for (int q = 0; q < 4; q++) {
        float v = s[tx][ty + 8*q];
        Th[(size_t)(n0 + ty + 8*q) * K + k0 + tx] = __float2half(v);
    }
}

// ---------------------------------------------------------------------------
// GEMM mainloop: 128x128 tile, 8 warps (64x32), K-chunk 64, 2-stage pipeline.
// TWOT: A hi/lo 2-term; else A hi only.
// ---------------------------------------------------------------------------
struct GemmOps {
    const __half *Ah, *Al, *Bh;
    int K, row0, bcol0;
};

template<bool TWOT>
__device__ __forceinline__ void gemm_mainloop(const GemmOps& op, uint32_t sbase,
                                              float acc[4][4][4])
{
    constexpr uint32_t GST_B   = TWOT ? 32768u : 16384u;
    constexpr uint32_t G_STAGE = TWOT ? 49152u : 32768u;

    const int tid  = threadIdx.x;
    const int wid  = tid >> 5;
    const int lane = tid & 31;
    const int wm   = (wid & 1) * 64;
    const int wn   = (wid >> 1) * 32;
    const int K    = op.K;
    const int nchunks = K >> 6;

    auto load_chunk = [&](uint32_t sb, int k0) {
        #pragma unroll
        for (int t = 0; t < 4; t++) {
            int idx = tid + t * 256;
            int r   = idx >> 3;
            int c   = idx & 7;
            uint32_t soff = SW128R(r, c);
            size_t aoff = (size_t)(op.row0 + r) * K + k0 + c * 8;
            size_t boff = (size_t)(op.bcol0 + r) * K + k0 + c * 8;
            ldgsts16(sb + soff, op.Ah + aoff);
            if (TWOT) ldgsts16(sb + GST_ALO + soff, op.Al + aoff);
            ldgsts16(sb + GST_B + soff, op.Bh + boff);
        }
        cp_commit();
    };

    load_chunk(sbase, 0);
    if (nchunks > 1) load_chunk(sbase + G_STAGE, 64);

    for (int cch = 0; cch < nchunks; cch++) {
        const uint32_t sb = sbase + (uint32_t)(cch & 1) * G_STAGE;
        if (cch + 1 < nchunks) {
            cp_wait<1>();
        } else {
            cp_wait<0>();
        }
        __syncthreads();

        #pragma unroll
        for (int ks = 0; ks < 4; ks++) {
            uint32_t ahi[4][4], alo[4][4];
            #pragma unroll
            for (int mi = 0; mi < 4; mi++) {
                int r = wm + mi * 16 + (lane & 15);
                int c = ks * 2 + (lane >> 4);
                uint32_t ad = sb + SW128R(r, c);
                ldsm4(ahi[mi], ad);
                if (TWOT) ldsm4(alo[mi], ad + GST_ALO);
            }
            uint32_t bhi[4][2];
            #pragma unroll
            for (int j = 0; j < 2; j++) {
                int m4 = lane >> 3;
                int n  = wn + j * 16 + ((m4 >> 1) << 3) + (lane & 7);
                int c  = ks * 2 + (m4 & 1);
                uint32_t rh[4];
                ldsm4(rh, sb + GST_B + SW128R(n, c));
                bhi[2*j][0] = rh[0]; bhi[2*j][1] = rh[1];
                bhi[2*j+1][0] = rh[2]; bhi[2*j+1][1] = rh[3];
            }
            #pragma unroll
            for (int mi = 0; mi < 4; mi++)
                #pragma unroll
                for (int ni = 0; ni < 4; ni++) {
                    mma_fp16(acc[mi][ni], ahi[mi], bhi[ni]);
                    if (TWOT) mma_fp16(acc[mi][ni], alo[mi], bhi[ni]);
                }
        }
        __syncthreads();
        if (cch + 2 < nchunks) load_chunk(sb, (cch + 2) * 64);
    }
}

// ---------------------------------------------------------------------------
// QG GEMM (2-term): grid (24, 32). cb<8: Q | else G (16 blocks)
// ---------------------------------------------------------------------------
__global__ void __launch_bounds__(256, 2) qg_gemm()
{
    extern __shared__ char smem[];
    const uint32_t sbase = smem_u32(smem);
    const int tid  = threadIdx.x;
    const int wid  = tid >> 5;
    const int lane = tid & 31;
    const int row0 = blockIdx.y * 128;
    const int cb   = blockIdx.x;
    const int wm   = (wid & 1) * 64;
    const int wn   = (wid >> 1) * 32;

    const bool isQ = (cb < 8);
    const int lcol0 = isQ ? cb * 128 : (cb - 8) * 128;
    const __half* Bh = isQ ? g_WqT : g_WgT;

    float acc[4][4][4];
    #pragma unroll
    for (int mi = 0; mi < 4; mi++)
        #pragma unroll
        for (int ni = 0; ni < 4; ni++)
            #pragma unroll
            for (int e = 0; e < 4; e++) acc[mi][ni][e] = 0.0f;

    GemmOps op{ g_hs_hi, g_hs_lo, Bh, HQ, row0, lcol0 };
    gemm_mainloop<true>(op, sbase, acc);

    #pragma unroll
    for (int mi = 0; mi < 4; mi++) {
        const int row = row0 + wm + mi * 16 + (lane >> 2);
        #pragma unroll
        for (int ni = 0; ni < 4; ni++) {
            const int col = lcol0 + wn + ni * 8 + 2 * (lane & 3);
            float v0 = acc[mi][ni][0], v1 = acc[mi][ni][1];
            float v2 = acc[mi][ni][2], v3 = acc[mi][ni][3];
            if (isQ) {   // scale + RoPE + hi/lo split
                v0 *= QSCALE; v1 *= QSCALE; v2 *= QSCALE; v3 *= QSCALE;
                const int p = (col & 127) >> 1;
                float2 cs0 = g_rope[(row & (LQ - 1)) * 64 + p];
                float2 cs1 = g_rope[((row + 8) & (LQ - 1)) * 64 + p];
                float x0 = v0, x1 = v1;
                v0 = x0 * cs0.x - x1 * cs0.y;
                v1 = x1 * cs0.x + x0 * cs0.y;
                x0 = v2; x1 = v3;
                v2 = x0 * cs1.x - x1 * cs1.y;
                v3 = x1 * cs1.x + x0 * cs1.y;
                __half h0 = __float2half(v0), h1 = __float2half(v1);
                __half h2 = __float2half(v2), h3 = __float2half(v3);
                __half l0 = __float2half(v0 - __half2float(h0));
                __half l1 = __float2half(v1 - __half2float(h1));
                __half l2 = __float2half(v2 - __half2float(h2));
                __half l3 = __float2half(v3 - __half2float(h3));
                *(__half2*)(g_Qhi + (size_t)row * HQ + col)       = __half2(h0, h1);
                *(__half2*)(g_Qhi + (size_t)(row + 8) * HQ + col) = __half2(h2, h3);
                *(__half2*)(g_Qlo + (size_t)row * HQ + col)       = __half2(l0, l1);
                *(__half2*)(g_Qlo + (size_t)(row + 8) * HQ + col) = __half2(l2, l3);
            } else {     // G: fp32
                *(float2*)(g_G + (size_t)row * VDIMQ + col)       = make_float2(v0, v1);
                *(float2*)(g_G + (size_t)(row + 8) * VDIMQ + col) = make_float2(v2, v3);
            }
        }
    }
}

// ---------------------------------------------------------------------------
// KV GEMM (1-term): grid (24, 32). cb<8: K (+Kdec, 8 blocks) | else V (16 blocks)
// ---------------------------------------------------------------------------
__global__ void __launch_bounds__(256, 2) kv_gemm()
{
    extern __shared__ char smem[];
    const uint32_t sbase = smem_u32(smem);
    const int tid  = threadIdx.x;
    const int wid  = tid >> 5;
    const int lane = tid & 31;
    const int row0 = blockIdx.y * 128;
    const int cb   = blockIdx.x;
    const int wm   = (wid & 1) * 64;
    const int wn   = (wid >> 1) * 32;

    const bool isK = (cb < 8);
    const int lcol0 = isK ? cb * 128 : (cb - 8) * 128;
    const __half* Bh = isK ? g_WkT : g_WvT;

    float acc[4][4][4];
    #pragma unroll
    for (int mi = 0; mi < 4; mi++)
        #pragma unroll
        for (int ni = 0; ni < 4; ni++)
            #pragma unroll
            for (int e = 0; e < 4; e++) acc[mi][ni][e] = 0.0f;

    GemmOps op{ g_hs_hi, nullptr, Bh, HQ, row0, lcol0 };
    gemm_mainloop<false>(op, sbase, acc);

    float sdecK = 0.0f;
    if (isK) sdecK = log2f(1.0f - exp2f(-5.0f - (float)cb));

    #pragma unroll
    for (int mi = 0; mi < 4; mi++) {
        const int row = row0 + wm + mi * 16 + (lane >> 2);
        #pragma unroll
        for (int ni = 0; ni < 4; ni++) {
            const int col = lcol0 + wn + ni * 8 + 2 * (lane & 3);
            float v0 = acc[mi][ni][0], v1 = acc[mi][ni][1];
            float v2 = acc[mi][ni][2], v3 = acc[mi][ni][3];
            if (isK) {   // RoPE + hi + decayed copy
                const int p = (col & 127) >> 1;
                float2 cs0 = g_rope[(row & (LQ - 1)) * 64 + p];
                float2 cs1 = g_rope[((row + 8) & (LQ - 1)) * 64 + p];
                float x0 = v0, x1 = v1;
                v0 = x0 * cs0.x - x1 * cs0.y;
                v1 = x1 * cs0.x + x0 * cs0.y;
                x0 = v2; x1 = v3;
                v2 = x0 * cs1.x - x1 * cs1.y;
                v3 = x1 * cs1.x + x0 * cs1.y;
                *(__half2*)(g_Khi + (size_t)row * HQ + col)       = __floats2half2_rn(v0, v1);
                *(__half2*)(g_Khi + (size_t)(row + 8) * HQ + col) = __floats2half2_rn(v2, v3);
                float p0 = exp2f(sdecK * (float)(CHK - (row & (CHK - 1))));
                float p1 = exp2f(sdecK * (float)(CHK - ((row + 8) & (CHK - 1))));
                *(__half2*)(g_Kdec + (size_t)row * HQ + col)       = __floats2half2_rn(v0 * p0, v1 * p0);
                *(__half2*)(g_Kdec + (size_t)(row + 8) * HQ + col) = __floats2half2_rn(v2 * p1, v3 * p1);
            } else {     // V: fp16
                *(__half2*)(g_Vhi + (size_t)row * VDIMQ + col)       = __floats2half2_rn(v0, v1);
                *(__half2*)(g_Vhi + (size_t)(row + 8) * VDIMQ + col) = __floats2half2_rn(v2, v3);
            }
        }
    }
}

// ---------------------------------------------------------------------------
// Wo GEMM (2-term): fp32 out. K=2048, N=1024.
// ---------------------------------------------------------------------------
__global__ void __launch_bounds__(256, 2) wo_gemm(float* __restrict__ C)
{
    extern __shared__ char smem[];
    const uint32_t sbase = smem_u32(smem);
    const int tid  = threadIdx.x;
    const int wid  = tid >> 5;
    const int lane = tid & 31;
    const int row0 = blockIdx.y * 128;
    const int col0 = blockIdx.x * 128;
    const int wm   = (wid & 1) * 64;
    const int wn   = (wid >> 1) * 32;

    float acc[4][4][4];
    #pragma unroll
    for (int mi = 0; mi < 4; mi++)
        #pragma unroll
        for (int ni = 0; ni < 4; ni++)
            #pragma unroll
            for (int e = 0; e < 4; e++) acc[mi][ni][e] = 0.0f;

    GemmOps op{ g_O_hi, g_O_lo, g_WoT, VDIMQ, row0, col0 };
    gemm_mainloop<true>(op, sbase, acc);

    #pragma unroll
    for (int mi = 0; mi < 4; mi++) {
        const int row = row0 + wm + mi * 16 + (lane >> 2);
        #pragma unroll
        for (int ni = 0; ni < 4; ni++) {
            const int col = col0 + wn + ni * 8 + 2 * (lane & 3);
            *(float2*)(C + (size_t)row * HQ + col) =
                make_float2(acc[mi][ni][0], acc[mi][ni][1]);
            *(float2*)(C + (size_t)(row + 8) * HQ + col) =
                make_float2(acc[mi][ni][2], acc[mi][ni][3]);
        }
    }
}

// ---------------------------------------------------------------------------
// Attention Kernel A: per-chunk outer product  A_c = Kdec_c^T V_c
// ---------------------------------------------------------------------------
#define ATTA_SMEM 98304

__global__ void __launch_bounds__(512) chunk_state_kernel()
{
    extern __shared__ char smem[];
    const uint32_t SB   = smem_u32(smem);
    const uint32_t kbuf = SB;            // [128 r][128 d1] fp16 SW256
    const uint32_t vbuf = SB + 32768;    // [128 r][256 d2] fp16 SW512

    const int ch = blockIdx.x, bh = blockIdx.y;
    const int b = bh >> 3, h = bh & 7;
    const int tid = threadIdx.x, wid = tid >> 5, lane = tid & 31;
    const int trow = ch * CHK;

    const __half* Kd_g = g_Kdec + (size_t)(b * LQ + trow) * HQ + h * DQKQ;
    const __half* Vh_g = g_Vhi + (size_t)(b * LQ + trow) * VDIMQ + h * DVQ;

    #pragma unroll
    for (int t = 0; t < 4; t++) {
        int idx = tid + t * 512;
        int r = idx >> 4, cc = idx & 15;
        ldgsts16(kbuf + SW256(r, cc), Kd_g + (size_t)r * HQ + cc * 8);
    }
    #pragma unroll
    for (int t = 0; t < 8; t++) {
        int idx = tid + t * 512;
        int r = idx >> 5, cc = idx & 31;
        ldgsts16(vbuf + SW512(r, cc), Vh_g + (size_t)r * VDIMQ + cc * 8);
    }
    cp_commit();
    cp_wait<0>();
    __syncthreads();

    const int wm = (wid & 3) * 32;
    const int wn = (wid >> 2) * 64;

    float acc[2][8][4];
    #pragma unroll
    for (int mi = 0; mi < 2; mi++)
        #pragma unroll
        for (int nt = 0; nt < 8; nt++)
            #pragma unroll
            for (int e = 0; e < 4; e++) acc[mi][nt][e] = 0.0f;

    #pragma unroll
    for (int ks = 0; ks < 8; ks++) {
        uint32_t af[2][4];
        #pragma unroll
        for (int mi = 0; mi < 2; mi++) {
            int m0 = wm + mi * 16;
            int r_src = ks * 16 + ((lane >> 4) << 3) + (lane & 7);
            int d_off = (m0 >> 3) + ((lane >> 3) & 1);
            ldsm4t(af[mi], kbuf + SW256(r_src, d_off));
        }
        uint32_t bf[8][2];
        #pragma unroll
        for (int np = 0; np < 4; np++) {
            int row = ks * 16 + ((lane >> 3) & 1) * 8 + (lane & 7);
            int cn  = (wn + np * 16 + (lane >> 4) * 8) >> 3;
            uint32_t rh[4];
            ldsm4t(rh, vbuf + SW512(row, cn));
            bf[2*np][0] = rh[0]; bf[2*np][1] = rh[1];
            bf[2*np+1][0] = rh[2]; bf[2*np+1][1] = rh[3];
        }
        #pragma unroll
        for (int mi = 0; mi < 2; mi++)
            #pragma unroll
            for (int nt = 0; nt < 8; nt++)
                mma_fp16(acc[mi][nt], af[mi], bf[nt]);
    }

    float* Ag = g_A + ((size_t)(bh * NCH + ch) << 15);
    #pragma unroll
    for (int mi = 0; mi < 2; mi++) {
        int d1 = wm + mi * 16 + (lane >> 2);
        #pragma unroll
        for (int nt = 0; nt < 8; nt++) {
            int d2 = wn + nt * 8 + 2 * (lane & 3);
            *(float2*)(Ag + (size_t)d1 * DVQ + d2) =
                make_float2(acc[mi][nt][0], acc[mi][nt][1]);
            *(float2*)(Ag + (size_t)(d1 + 8) * DVQ + d2) =
                make_float2(acc[mi][nt][2], acc[mi][nt][3]);
        }
    }
}

// ---------------------------------------------------------------------------
// Attention Kernel B: per-element decay scan over chunks -> states S_c (hi/lo)
// ---------------------------------------------------------------------------
__global__ void __launch_bounds__(512) scan_kernel()
{
    const int e  = blockIdx.x * 512 + threadIdx.x;
    const int bh = blockIdx.y;
    const int h  = bh & 7;
    const float sdec = log2f(1.0f - exp2f(-5.0f - (float)h));
    const float lamC = exp2f(sdec * (float)CHK);

    const size_t base = (size_t)bh * NCH << 15;
    float S = 0.0f;
    #pragma unroll
    for (int c = 0; c < NCH; c++) {
        size_t off = base + ((size_t)c << 15) + e;
        __half hi = __float2half(S);
        g_Shi[off] = hi;
        g_Slo[off] = __float2half(S - __half2float(hi));
        S = S * lamC + g_A[off];
    }
}

// ---------------------------------------------------------------------------
// Attention Kernel C: per (chunk, bh, dv-half) output.
// ---------------------------------------------------------------------------
#define ATTC_SMEM 229376

__global__ void __launch_bounds__(512) attn_chunk_kernel()
{
    extern __shared__ char smem[];
    const uint32_t SB  = smem_u32(smem);
    const uint32_t sQh = SB;
    const uint32_t sQl = SB + 32768;
    const uint32_t sK  = SB + 65536;
    const uint32_t sSh = SB + 98304;
    const uint32_t sSl = SB + 131072;
    const uint32_t sV  = SB + 163840;
    const uint32_t sPl = SB + 196608;
    const uint32_t sPh = sK;            // aliased after K consumed

    const int vh = blockIdx.x;
    const int ch = blockIdx.y;
    const int bh = blockIdx.z;
    const int b = bh >> 3, h = bh & 7;
    const int tid = threadIdx.x, wid = tid >> 5, lane = tid & 31;
    const int trow = ch * CHK;
    const float sdec = log2f(1.0f - exp2f(-5.0f - (float)h));

    const __half* Qh_g = g_Qhi + (size_t)(b * LQ + trow) * HQ + h * DQKQ;
    const __half* Ql_g = g_Qlo + (size_t)(b * LQ + trow) * HQ + h * DQKQ;
    const __half* Kh_g = g_Khi + (size_t)(b * LQ + trow) * HQ + h * DQKQ;
    const __half* Vh_g = g_Vhi + (size_t)(b * LQ + trow) * VDIMQ + h * DVQ + vh * 128;
    const __half* Sh_g = g_Shi + ((size_t)(bh * NCH + ch) << 15) + vh * 128;
    const __half* Sl_g = g_Slo + ((size_t)(bh * NCH + ch) << 15) + vh * 128;

    #pragma unroll
    for (int t = 0; t < 4; t++) {
        int idx = tid + t * 512;
        int r = idx >> 4, cc = idx & 15;
        ldgsts16(sQh + SW256(r, cc), Qh_g + (size_t)r * HQ + cc * 8);
        ldgsts16(sQl + SW256(r, cc), Ql_g + (size_t)r * HQ + cc * 8);
        ldgsts16(sK  + SW256(r, cc), Kh_g + (size_t)r * HQ + cc * 8);
    }
    cp_commit();
    #pragma unroll
    for (int t = 0; t < 4; t++) {
        int idx = tid + t * 512;
        int r = idx >> 4, cc = idx & 15;
        ldgsts16(sSh + SW256(r, cc), Sh_g + (size_t)r * DVQ + cc * 8);
        ldgsts16(sSl + SW256(r, cc), Sl_g + (size_t)r * DVQ + cc * 8);
        ldgsts16(sV  + SW256(r, cc), Vh_g + (size_t)r * VDIMQ + cc * 8);
    }
    cp_commit();

    const int wm = (wid & 3) * 32;
    const int wn = (wid >> 2) * 32;

    cp_wait<1>();
    __syncthreads();

    // ---- P = Q K^T (128x128), 2 terms ----
    float sacc[2][4][4];
    #pragma unroll
    for (int mi = 0; mi < 2; mi++)
        #pragma unroll
        for (int ni = 0; ni < 4; ni++)
            #pragma unroll
            for (int e = 0; e < 4; e++) sacc[mi][ni][e] = 0.0f;

    #pragma unroll
    for (int ks = 0; ks < 8; ks++) {
        uint32_t qh[2][4], ql[2][4];
        #pragma unroll
        for (int mi = 0; mi < 2; mi++) {
            int r = wm + mi * 16 + (lane & 15);
            int cc = ks * 2 + (lane >> 4);
            uint32_t ad = sQh + SW256(r, cc);
            ldsm4(qh[mi], ad);
            ldsm4(ql[mi], ad + 32768);
        }
        uint32_t kb[4][2];
        #pragma unroll
        for (int j = 0; j < 2; j++) {
            int m4 = lane >> 3;
            int n  = wn + j * 16 + ((m4 >> 1) << 3) + (lane & 7);
            int cc = ks * 2 + (m4 & 1);
            uint32_t rh[4];
            ldsm4(rh, sK + SW256(n, cc));
            kb[2*j][0] = rh[0]; kb[2*j][1] = rh[1];
            kb[2*j+1][0] = rh[2]; kb[2*j+1][1] = rh[3];
        }
        #pragma unroll
        for (int mi = 0; mi < 2; mi++)
            #pragma unroll
            for (int ni = 0; ni < 4; ni++) {
                mma_fp16(sacc[mi][ni], qh[mi], kb[ni]);
                mma_fp16(sacc[mi][ni], ql[mi], kb[ni]);
            }
    }
    __syncthreads();

    // ---- decay + causal + split -> store P hi/lo ----
    #pragma unroll
    for (int mi = 0; mi < 2; mi++) {
        int r0 = wm + mi * 16 + (lane >> 2);
        #pragma unroll
        for (int ni = 0; ni < 4; ni++) {
            int j0 = wn + ni * 8 + 2 * (lane & 3);
            float d00 = (r0 >= j0)         ? exp2f(sdec * (float)(r0 - j0))     : 0.0f;
            float d01 = (r0 >= j0 + 1)     ? exp2f(sdec * (float)(r0 - j0 - 1)) : 0.0f;
            float d10 = (r0 + 8 >= j0)     ? exp2f(sdec * (float)(r0 + 8 - j0))     : 0.0f;
            float d11 = (r0 + 8 >= j0 + 1) ? exp2f(sdec * (float)(r0 + 8 - j0 - 1)) : 0.0f;
            float v0 = sacc[mi][ni][0] * d00, v1 = sacc[mi][ni][1] * d01;
            float v2 = sacc[mi][ni][2] * d10, v3 = sacc[mi][ni][3] * d11;
            float h0 = __half2float(__float2half(v0));
            float h1 = __half2float(__float2half(v1));
            float h2 = __half2float(__float2half(v2));
            float h3 = __half2float(__float2half(v3));
            int cc = j0 >> 3;
            int off = (j0 & 7) * 2;
            sts32(sPh + SW256(r0, cc) + off,     pack_h2(v0, v1));
            sts32(sPl + SW256(r0, cc) + off,     pack_h2(v0 - h0, v1 - h1));
            sts32(sPh + SW256(r0 + 8, cc) + off, pack_h2(v2, v3));
            sts32(sPl + SW256(r0 + 8, cc) + off, pack_h2(v2 - h2, v3 - h3));
        }
    }
    cp_wait<0>();
    __syncthreads();

    // ---- X = Q @ S (128x128), 3 terms ----
    float xacc[2][4][4];
    #pragma unroll
    for (int mi = 0; mi < 2; mi++)
        #pragma unroll
        for (int ni = 0; ni < 4; ni++)
            #pragma unroll
            for (int e = 0; e < 4; e++) xacc[mi][ni][e] = 0.0f;

    #pragma unroll
    for (int ks = 0; ks < 8; ks++) {
        uint32_t qh[2][4], ql[2][4];
        #pragma unroll
        for (int mi = 0; mi < 2; mi++) {
            int r = wm + mi * 16 + (lane & 15);
            int cc = ks * 2 + (lane >> 4);
            uint32_t ad = sQh + SW256(r, cc);
            ldsm4(qh[mi], ad);
            ldsm4(ql[mi], ad + 32768);
        }
        uint32_t sbh[4][2], sbl[4][2];
        #pragma unroll
        for (int np = 0; np < 2; np++) {
            int row = ks * 16 + ((lane >> 3) & 1) * 8 + (lane & 7);
            int cn  = (wn + np * 16 + (lane >> 4) * 8) >> 3;
            uint32_t rh[4], rl[4];
            ldsm4t(rh, sSh + SW256(row, cn));
            ldsm4t(rl, sSl + SW256(row, cn));
            sbh[2*np][0] = rh[0]; sbh[2*np][1] = rh[1];
            sbh[2*np+1][0] = rh[2]; sbh[2*np+1][1] = rh[3];
            sbl[2*np][0] = rl[0]; sbl[2*np][1] = rl[1];
            sbl[2*np+1][0] = rl[2]; sbl[2*np+1][1] = rl[3];
        }
        #pragma unroll
        for (int mi = 0; mi < 2; mi++)
            #pragma unroll
            for (int ni = 0; ni < 4; ni++) {
                mma_fp16(xacc[mi][ni], qh[mi], sbh[ni]);
                mma_fp16(xacc[mi][ni], ql[mi], sbh[ni]);
                mma_fp16(xacc[mi][ni], qh[mi], sbl[ni]);
            }
    }

    // ---- O_intra = P @ V (128x128), 2 terms ----
    float oacc[2][4][4];
    #pragma unroll
    for (int mi = 0; mi < 2; mi++)
        #pragma unroll
        for (int ni = 0; ni < 4; ni++)
            #pragma unroll
            for (int e = 0; e < 4; e++) oacc[mi][ni][e] = 0.0f;

    #pragma unroll
    for (int ks = 0; ks < 8; ks++) {
        uint32_t ph[2][4], pl[2][4];
        #pragma unroll
        for (int mi = 0; mi < 2; mi++) {
            int r = wm + mi * 16 + (lane & 15);
            int cc = ks * 2 + (lane >> 4);
            ldsm4(ph[mi], sPh + SW256(r, cc));
            ldsm4(pl[mi], sPl + SW256(r, cc));
        }
        uint32_t vb[4][2];
        #pragma unroll
        for (int np = 0; np < 2; np++) {
            int row = ks * 16 + ((lane >> 3) & 1) * 8 + (lane & 7);
            int cn  = (wn + np * 16 + (lane >> 4) * 8) >> 3;
            uint32_t rh[4];
            ldsm4t(rh, sV + SW256(row, cn));
            vb[2*np][0] = rh[0]; vb[2*np][1] = rh[1];
            vb[2*np+1][0] = rh[2]; vb[2*np+1][1] = rh[3];
        }
        #pragma unroll
        for (int mi = 0; mi < 2; mi++)
            #pragma unroll
            for (int ni = 0; ni < 4; ni++) {
                mma_fp16(oacc[mi][ni], ph[mi], vb[ni]);
                mma_fp16(oacc[mi][ni], pl[mi], vb[ni]);
            }
    }

    // ---- combine + write O ----
    float* Og = g_O + (size_t)(b * LQ + trow) * VDIMQ + h * DVQ + vh * 128;
    #pragma unroll
    for (int mi = 0; mi < 2; mi++) {
        int r0 = wm + mi * 16 + (lane >> 2);
        float lam0 = exp2f(sdec * (float)r0);
        float lam1 = exp2f(sdec * (float)(r0 + 8));
        #pragma unroll
        for (int ni = 0; ni < 4; ni++) {
            int col = wn + ni * 8 + 2 * (lane & 3);
            *(float2*)(Og + (size_t)r0 * VDIMQ + col) =
                make_float2(oacc[mi][ni][0] + lam0 * xacc[mi][ni][0],
                            oacc[mi][ni][1] + lam0 * xacc[mi][ni][1]);
            *(float2*)(Og + (size_t)(r0 + 8) * VDIMQ + col) =
                make_float2(oacc[mi][ni][2] + lam1 * xacc[mi][ni][2],
                            oacc[mi][ni][3] + lam1 * xacc[mi][ni][3]);
        }
    }
}

// ---------------------------------------------------------------------------
// Fused RMSNorm + swish gate + split -> fp16 hi/lo
// ---------------------------------------------------------------------------
__global__ void __launch_bounds__(256) normgate_split_kernel(const float* __restrict__ gw)
{
    const int warp = (blockIdx.x << 3) + (threadIdx.x >> 5);
    const int lane = threadIdx.x & 31;
    const size_t base = (size_t)(warp >> 3) * VDIMQ + (size_t)(warp & 7) * DVQ;
    const float* Op = g_O + base;
    const float* Gp = g_G + base;
    __half* Oh = g_O_hi + base;
    __half* Ol = g_O_lo + base;

    const int d0 = lane * 4;
    const int d1 = 128 + lane * 4;
    float4 o0 = *(const float4*)(Op + d0);
    float4 o1 = *(const float4*)(Op + d1);

    float ss = o0.x*o0.x + o0.y*o0.y + o0.z*o0.z + o0.w*o0.w
             + o1.x*o1.x + o1.y*o1.y + o1.z*o1.z + o1.w*o1.w;
    #pragma unroll
    for (int off = 16; off > 0; off >>= 1)
        ss += __shfl_xor_sync(0xFFFFFFFFu, ss, off);

    const float r = rsqrtf(ss * (1.0f / 256.0f) + 1e-5f);

    float4 g0 = *(const float4*)(Gp + d0);
    float4 g1 = *(const float4*)(Gp + d1);
    float4 w0 = *(const float4*)(gw + d0);
    float4 w1 = *(const float4*)(gw + d1);

    float v[8];
    v[0] = o0.x * r * w0.x * (g0.x / (1.0f + expf(-g0.x)));
    v[1] = o0.y * r * w0.y * (g0.y / (1.0f + expf(-g0.y)));
    v[2] = o0.z * r * w0.z * (g0.z / (1.0f + expf(-g0.z)));
    v[3] = o0.w * r * w0.w * (g0.w / (1.0f + expf(-g0.w)));
    v[4] = o1.x * r * w1.x * (g1.x / (1.0f + expf(-g1.x)));
    v[5] = o1.y * r * w1.y * (g1.y / (1.0f + expf(-g1.y)));
    v[6] = o1.z * r * w1.z * (g1.z / (1.0f + expf(-g1.z)));
    v[7] = o1.w * r * w1.w * (g1.w / (1.0f + expf(-g1.w)));

    __half h[8], l[8];
    #pragma unroll
    for (int i = 0; i < 8; i++) {
        h[i] = __float2half(v[i]);
        l[i] = __float2half(v[i] - __half2float(h[i]));
    }
    *(__half2*)(Oh + d0)     = __half2(h[0], h[1]);
    *(__half2*)(Oh + d0 + 2) = __half2(h[2], h[3]);
    *(__half2*)(Oh + d1)     = __half2(h[4], h[5]);
    *(__half2*)(Oh + d1 + 2) = __half2(h[6], h[7]);
    *(__half2*)(Ol + d0)     = __half2(l[0], l[1]);
    *(__half2*)(Ol + d0 + 2) = __half2(l[2], l[3]);
    *(__half2*)(Ol + d1)     = __half2(l[4], l[5]);
    *(__half2*)(Ol + d1 + 2) = __half2(l[6], l[7]);
}

// ---------------------------------------------------------------------------
// kernel_launch
// ---------------------------------------------------------------------------
extern "C" void kernel_launch(void* const* d_in, const int* in_sizes, int n_in,
                              void* d_out, int out_size)
{
    const float* hs = (const float*)d_in[0];
    const float* Wq = (const float*)d_in[1];
    const float* Wk = (const float*)d_in[2];
    const float* Wv = (const float*)d_in[3];
    const float* Wg = (const float*)d_in[4];
    const float* Wo = (const float*)d_in[5];
    const float* gw = (const float*)d_in[6];
    float* out = (float*)d_out;

    __half *hsh, *hsl;
    __half *qw, *kw, *vw, *gwt, *ow;
    cudaGetSymbolAddress((void**)&hsh, g_hs_hi);
    cudaGetSymbolAddress((void**)&hsl, g_hs_lo);
    cudaGetSymbolAddress((void**)&qw, g_WqT);
    cudaGetSymbolAddress((void**)&kw, g_WkT);
    cudaGetSymbolAddress((void**)&vw, g_WvT);
    cudaGetSymbolAddress((void**)&gwt, g_WgT);
    cudaGetSymbolAddress((void**)&ow, g_WoT);

    cudaFuncSetAttribute(qg_gemm, cudaFuncAttributeMaxDynamicSharedMemorySize, TCG_SMEM_2T);
    cudaFuncSetAttribute(kv_gemm, cudaFuncAttributeMaxDynamicSharedMemorySize, TCG_SMEM_1T);
    cudaFuncSetAttribute(wo_gemm, cudaFuncAttributeMaxDynamicSharedMemorySize, TCG_SMEM_2T);
    cudaFuncSetAttribute(chunk_state_kernel, cudaFuncAttributeMaxDynamicSharedMemorySize, ATTA_SMEM);
    cudaFuncSetAttribute(attn_chunk_kernel,  cudaFuncAttributeMaxDynamicSharedMemorySize, ATTC_SMEM);

    dim3 blk(256);

    // 1) prep: hs split + RoPE table + weight transposes
    split_kernel<<<(MROWS*HQ/4 + 255)/256, blk>>>(hs, hsh, hsl, MROWS*HQ/4);
    rope_table_kernel<<<LQ*64/256, blk>>>();
    TDescs ds;
    ds.d[0] = { Wq, qw,  HQ,    HQ,    0    };
    ds.d[1] = { Wk, kw,  HQ,    HQ,    1024 };
    ds.d[2] = { Wv, vw,  HQ,    VDIMQ, 2048 };
    ds.d[3] = { Wg, gwt, HQ,    VDIMQ, 4096 };
    ds.d[4] = { Wo, ow,  VDIMQ, HQ,    6144 };
    transpose_multi<<<8192, blk>>>(ds);

    // 2) projections: KV first (1-term, 24 blocks: 8 K + 16 V), then QG (2-term)
    kv_gemm<<<dim3(24, MROWS/128), blk, TCG_SMEM_1T>>>();
    qg_gemm<<<dim3(24, MROWS/128), blk, TCG_SMEM_2T>>>();

    // 3) chunked-recurrent retention: states -> scan -> outputs
    chunk_state_kernel<<<dim3(NCH, 16), 512, ATTA_SMEM>>>();
    scan_kernel<<<dim3(64, 16), 512>>>();
    attn_chunk_kernel<<<dim3(2, NCH, 16), 512, ATTC_SMEM>>>();

    // 4) fused RMSNorm + swish gate + split
    normgate_split_kernel<<<4096, blk>>>(gw);

    // 5) output projection
    wo_gemm<<<dim3(HQ/128, MROWS/128), blk, TCG_SMEM_2T>>>(out);
}

// round 15
// speedup vs baseline: 1.4545x; 1.1068x over previous
#include <cuda_runtime.h>
#include <cuda_fp16.h>
#include <math.h>
#include <stdint.h>

// Problem constants
#define BQ 2
#define LQ 2048
#define HQ 1024
#define NHQ 8
#define DQKQ 128
#define DVQ 256
#define VDIMQ 2048
#define MROWS (BQ*LQ)   // 4096
#define CHK 128         // retention chunk size
#define NCH (LQ/CHK)    // 16 chunks per sequence

#define QSCALE 0.08838834764831843f          // 128^-0.5
#define RF (-0.20762050593045852f)           // -2*log2(10000)/128

// ---------------------------------------------------------------------------
// Scratch (device globals)
// ---------------------------------------------------------------------------
__device__ float g_G[MROWS*VDIMQ];
__device__ float g_O[MROWS*VDIMQ];
__device__ float g_A[16*NCH*DQKQ*DVQ];            // per-chunk KV outer products
__device__ float2 g_rope[LQ*64];                  // (cos, sin) per (t, pair)

__device__ __half g_hs_hi[MROWS*HQ],  g_hs_lo[MROWS*HQ];
__device__ __half g_O_hi[MROWS*VDIMQ];
__device__ __half g_Qhi[MROWS*HQ],    g_Qlo[MROWS*HQ];
__device__ __half g_Khi[MROWS*HQ];
__device__ __half g_Kdec[MROWS*HQ];               // K * lam^(CHK - r%CHK)
__device__ __half g_Vhi[MROWS*VDIMQ];
__device__ __half g_Shi[16*NCH*DQKQ*DVQ];         // chunk-entry states hi
__device__ __half g_Slo[16*NCH*DQKQ*DVQ];         // chunk-entry states lo
__device__ __half g_WqT[HQ*HQ];
__device__ __half g_WkT[HQ*HQ];
__device__ __half g_WvT[VDIMQ*HQ];
__device__ __half g_WgT[VDIMQ*HQ];
__device__ __half g_WoT[HQ*VDIMQ];

// ---------------------------------------------------------------------------
// PTX helpers
// ---------------------------------------------------------------------------
__device__ __forceinline__ uint32_t smem_u32(const void* p) {
    uint32_t a;
    asm("{ .reg .u64 t; cvta.to.shared.u64 t, %1; cvt.u32.u64 %0, t; }"
        : "=r"(a) : "l"(p));
    return a;
}
__device__ __forceinline__ void ldgsts16(uint32_t dst, const void* src) {
    asm volatile("cp.async.cg.shared.global [%0], [%1], 16;" :: "r"(dst), "l"(src));
}
__device__ __forceinline__ void cp_commit() {
    asm volatile("cp.async.commit_group;" ::: "memory");
}
template<int N_>
__device__ __forceinline__ void cp_wait() {
    asm volatile("cp.async.wait_group %0;" :: "n"(N_) : "memory");
}
__device__ __forceinline__ void ldsm4(uint32_t* r, uint32_t addr) {
    asm volatile("ldmatrix.sync.aligned.m8n8.x4.shared.b16 {%0,%1,%2,%3}, [%4];"
        : "=r"(r[0]), "=r"(r[1]), "=r"(r[2]), "=r"(r[3]) : "r"(addr));
}
__device__ __forceinline__ void ldsm4t(uint32_t* r, uint32_t addr) {
    asm volatile("ldmatrix.sync.aligned.m8n8.x4.trans.shared.b16 {%0,%1,%2,%3}, [%4];"
        : "=r"(r[0]), "=r"(r[1]), "=r"(r[2]), "=r"(r[3]) : "r"(addr));
}
__device__ __forceinline__ void sts32(uint32_t addr, uint32_t v) {
    asm volatile("st.shared.b32 [%0], %1;" :: "r"(addr), "r"(v) : "memory");
}
__device__ __forceinline__ void mma_fp16(float* c, const uint32_t* a, const uint32_t* b) {
    asm volatile("mma.sync.aligned.m16n8k16.row.col.f32.f16.f16.f32 "
        "{%0,%1,%2,%3}, {%4,%5,%6,%7}, {%8,%9}, {%0,%1,%2,%3};"
        : "+f"(c[0]), "+f"(c[1]), "+f"(c[2]), "+f"(c[3])
        : "r"(a[0]), "r"(a[1]), "r"(a[2]), "r"(a[3]), "r"(b[0]), "r"(b[1]));
}
__device__ __forceinline__ uint32_t pack_h2(float a, float b) {
    __half2 t = __floats2half2_rn(a, b);
    return *(uint32_t*)&t;
}

// Swizzles: row stride in bytes; 16B chunk xor'd by (r&7)
#define SW128R(r, c) ((uint32_t)((r) * 128u + ((uint32_t)((c) ^ ((r) & 7)) << 4)))
#define SW256(r, c)  ((uint32_t)((r) * 256u + ((uint32_t)((c) ^ ((r) & 7)) << 4)))
#define SW512(r, c)  ((uint32_t)((r) * 512u + ((uint32_t)((c) ^ ((r) & 7)) << 4)))

// GEMM tiles per operand: 128x64 fp16 = 16KB. 2-stage pipelines.
// 2-term stage: Ahi|Alo|Bhi = 48KB; 1-term stage: Ahi|Bhi = 32KB.
#define GST_ALO 16384
#define TCG_SMEM_2T (2 * 49152)
#define TCG_SMEM_1T (2 * 32768)

// ---------------------------------------------------------------------------
// hs split -> fp16 hi/lo
// ---------------------------------------------------------------------------
__global__ void __launch_bounds__(256) split_kernel(const float* __restrict__ x,
                                                    __half* __restrict__ hi,
                                                    __half* __restrict__ lo,
                                                    int n4)
{
    int i = blockIdx.x * 256 + threadIdx.x;
    if (i >= n4) return;
    float4 v = ((const float4*)x)[i];
    __half h0 = __float2half(v.x), h1 = __float2half(v.y);
    __half h2 = __float2half(v.z), h3 = __float2half(v.w);
    __half l0 = __float2half(v.x - __half2float(h0));
    __half l1 = __float2half(v.y - __half2float(h1));
    __half l2 = __float2half(v.z - __half2float(h2));
    __half l3 = __float2half(v.w - __half2float(h3));
    ((__half2*)hi)[2*i]   = __half2(h0, h1);
    ((__half2*)hi)[2*i+1] = __half2(h2, h3);
    ((__half2*)lo)[2*i]   = __half2(l0, l1);
    ((__half2*)lo)[2*i+1] = __half2(l2, l3);
}

// ---------------------------------------------------------------------------
// RoPE table
// ---------------------------------------------------------------------------
__global__ void __launch_bounds__(256) rope_table_kernel()
{
    int i = blockIdx.x * 256 + threadIdx.x;    // 0..131071
    int t = i >> 6, p = i & 63;
    float inv = exp2f((float)p * RF);
    float s, c;
    sincosf((float)t * inv, &s, &c);
    g_rope[i] = make_float2(c, s);
}

// ---------------------------------------------------------------------------
// Merged weight transpose (fp16): one launch for all 5 weights.
// ---------------------------------------------------------------------------
struct TDesc { const float* W; __half* hi; int K, N, start; };
struct TDescs { TDesc d[5]; };

__global__ void __launch_bounds__(256) transpose_multi(TDescs ds)
{
    __shared__ float s[32][33];
    int t = blockIdx.x;
    int i = 0;
    #pragma unroll
    for (int j = 1; j < 5; j++) if (t >= ds.d[j].start) i = j;
    const float* W = ds.d[i].W;
    __half* Th = ds.d[i].hi;
    const int K = ds.d[i].K, N = ds.d[i].N;
    int lt = t - ds.d[i].start;
    int ncols = N >> 5;
    int k0 = (lt / ncols) * 32;
    int n0 = (lt % ncols) * 32;

    const int tx = threadIdx.x & 31;
    const int ty = threadIdx.x >> 5;
    #pragma unroll
    for (int q = 0; q < 4; q++)
        s[ty + 8*q][tx] = W[(size_t)(k0 + ty + 8*q) * N + n0 + tx];
    __syncthreads();
    #pragma unroll
    for (int q = 0; q < 4; q++) {
        float v = s[tx][ty + 8*q];
        Th[(size_t)(n0 + ty + 8*q) * K + k0 + tx] = __float2half(v);
    }
}

// ---------------------------------------------------------------------------
// GEMM mainloop: 128x128 tile, 8 warps (64x32), K-chunk 64, 2-stage pipeline.
// TWOT: A hi/lo 2-term; else A hi only.
// ---------------------------------------------------------------------------
struct GemmOps {
    const __half *Ah, *Al, *Bh;
    int K, row0, bcol0;
};

template<bool TWOT>
__device__ __forceinline__ void gemm_mainloop(const GemmOps& op, uint32_t sbase,
                                              float acc[4][4][4])
{
    constexpr uint32_t GST_B   = TWOT ? 32768u : 16384u;
    constexpr uint32_t G_STAGE = TWOT ? 49152u : 32768u;

    const int tid  = threadIdx.x;
    const int wid  = tid >> 5;
    const int lane = tid & 31;
    const int wm   = (wid & 1) * 64;
    const int wn   = (wid >> 1) * 32;
    const int K    = op.K;
    const int nchunks = K >> 6;

    auto load_chunk = [&](uint32_t sb, int k0) {
        #pragma unroll
        for (int t = 0; t < 4; t++) {
            int idx = tid + t * 256;
            int r   = idx >> 3;
            int c   = idx & 7;
            uint32_t soff = SW128R(r, c);
            size_t aoff = (size_t)(op.row0 + r) * K + k0 + c * 8;
            size_t boff = (size_t)(op.bcol0 + r) * K + k0 + c * 8;
            ldgsts16(sb + soff, op.Ah + aoff);
            if (TWOT) ldgsts16(sb + GST_ALO + soff, op.Al + aoff);
            ldgsts16(sb + GST_B + soff, op.Bh + boff);
        }
        cp_commit();
    };

    load_chunk(sbase, 0);
    if (nchunks > 1) load_chunk(sbase + G_STAGE, 64);

    for (int cch = 0; cch < nchunks; cch++) {
        const uint32_t sb = sbase + (uint32_t)(cch & 1) * G_STAGE;
        if (cch + 1 < nchunks) {
            cp_wait<1>();
        } else {
            cp_wait<0>();
        }
        __syncthreads();

        #pragma unroll
        for (int ks = 0; ks < 4; ks++) {
            uint32_t ahi[4][4], alo[4][4];
            #pragma unroll
            for (int mi = 0; mi < 4; mi++) {
                int r = wm + mi * 16 + (lane & 15);
                int c = ks * 2 + (lane >> 4);
                uint32_t ad = sb + SW128R(r, c);
                ldsm4(ahi[mi], ad);
                if (TWOT) ldsm4(alo[mi], ad + GST_ALO);
            }
            uint32_t bhi[4][2];
            #pragma unroll
            for (int j = 0; j < 2; j++) {
                int m4 = lane >> 3;
                int n  = wn + j * 16 + ((m4 >> 1) << 3) + (lane & 7);
                int c  = ks * 2 + (m4 & 1);
                uint32_t rh[4];
                ldsm4(rh, sb + GST_B + SW128R(n, c));
                bhi[2*j][0] = rh[0]; bhi[2*j][1] = rh[1];
                bhi[2*j+1][0] = rh[2]; bhi[2*j+1][1] = rh[3];
            }
            #pragma unroll
            for (int mi = 0; mi < 4; mi++)
                #pragma unroll
                for (int ni = 0; ni < 4; ni++) {
                    mma_fp16(acc[mi][ni], ahi[mi], bhi[ni]);
                    if (TWOT) mma_fp16(acc[mi][ni], alo[mi], bhi[ni]);
                }
        }
        __syncthreads();
        if (cch + 2 < nchunks) load_chunk(sb, (cch + 2) * 64);
    }
}

// ---------------------------------------------------------------------------
// QG GEMM (2-term): grid (24, 32). cb<8: Q | else G (16 blocks)
// ---------------------------------------------------------------------------
__global__ void __launch_bounds__(256, 2) qg_gemm()
{
    extern __shared__ char smem[];
    const uint32_t sbase = smem_u32(smem);
    const int tid  = threadIdx.x;
    const int wid  = tid >> 5;
    const int lane = tid & 31;
    const int row0 = blockIdx.y * 128;
    const int cb   = blockIdx.x;
    const int wm   = (wid & 1) * 64;
    const int wn   = (wid >> 1) * 32;

    const bool isQ = (cb < 8);
    const int lcol0 = isQ ? cb * 128 : (cb - 8) * 128;
    const __half* Bh = isQ ? g_WqT : g_WgT;

    float acc[4][4][4];
    #pragma unroll
    for (int mi = 0; mi < 4; mi++)
        #pragma unroll
        for (int ni = 0; ni < 4; ni++)
            #pragma unroll
            for (int e = 0; e < 4; e++) acc[mi][ni][e] = 0.0f;

    GemmOps op{ g_hs_hi, g_hs_lo, Bh, HQ, row0, lcol0 };
    gemm_mainloop<true>(op, sbase, acc);

    #pragma unroll
    for (int mi = 0; mi < 4; mi++) {
        const int row = row0 + wm + mi * 16 + (lane >> 2);
        #pragma unroll
        for (int ni = 0; ni < 4; ni++) {
            const int col = lcol0 + wn + ni * 8 + 2 * (lane & 3);
            float v0 = acc[mi][ni][0], v1 = acc[mi][ni][1];
            float v2 = acc[mi][ni][2], v3 = acc[mi][ni][3];
            if (isQ) {   // scale + RoPE + hi/lo split
                v0 *= QSCALE; v1 *= QSCALE; v2 *= QSCALE; v3 *= QSCALE;
                const int p = (col & 127) >> 1;
                float2 cs0 = g_rope[(row & (LQ - 1)) * 64 + p];
                float2 cs1 = g_rope[((row + 8) & (LQ - 1)) * 64 + p];
                float x0 = v0, x1 = v1;
                v0 = x0 * cs0.x - x1 * cs0.y;
                v1 = x1 * cs0.x + x0 * cs0.y;
                x0 = v2; x1 = v3;
                v2 = x0 * cs1.x - x1 * cs1.y;
                v3 = x1 * cs1.x + x0 * cs1.y;
                __half h0 = __float2half(v0), h1 = __float2half(v1);
                __half h2 = __float2half(v2), h3 = __float2half(v3);
                __half l0 = __float2half(v0 - __half2float(h0));
                __half l1 = __float2half(v1 - __half2float(h1));
                __half l2 = __float2half(v2 - __half2float(h2));
                __half l3 = __float2half(v3 - __half2float(h3));
                *(__half2*)(g_Qhi + (size_t)row * HQ + col)       = __half2(h0, h1);
                *(__half2*)(g_Qhi + (size_t)(row + 8) * HQ + col) = __half2(h2, h3);
                *(__half2*)(g_Qlo + (size_t)row * HQ + col)       = __half2(l0, l1);
                *(__half2*)(g_Qlo + (size_t)(row + 8) * HQ + col) = __half2(l2, l3);
            } else {     // G: fp32
                *(float2*)(g_G + (size_t)row * VDIMQ + col)       = make_float2(v0, v1);
                *(float2*)(g_G + (size_t)(row + 8) * VDIMQ + col) = make_float2(v2, v3);
            }
        }
    }
}

// ---------------------------------------------------------------------------
// KV GEMM (1-term): grid (24, 32). cb<8: K (+Kdec, 8 blocks) | else V (16 blocks)
// ---------------------------------------------------------------------------
__global__ void __launch_bounds__(256, 2) kv_gemm()
{
    extern __shared__ char smem[];
    const uint32_t sbase = smem_u32(smem);
    const int tid  = threadIdx.x;
    const int wid  = tid >> 5;
    const int lane = tid & 31;
    const int row0 = blockIdx.y * 128;
    const int cb   = blockIdx.x;
    const int wm   = (wid & 1) * 64;
    const int wn   = (wid >> 1) * 32;

    const bool isK = (cb < 8);
    const int lcol0 = isK ? cb * 128 : (cb - 8) * 128;
    const __half* Bh = isK ? g_WkT : g_WvT;

    float acc[4][4][4];
    #pragma unroll
    for (int mi = 0; mi < 4; mi++)
        #pragma unroll
        for (int ni = 0; ni < 4; ni++)
            #pragma unroll
            for (int e = 0; e < 4; e++) acc[mi][ni][e] = 0.0f;

    GemmOps op{ g_hs_hi, nullptr, Bh, HQ, row0, lcol0 };
    gemm_mainloop<false>(op, sbase, acc);

    float sdecK = 0.0f;
    if (isK) sdecK = log2f(1.0f - exp2f(-5.0f - (float)cb));

    #pragma unroll
    for (int mi = 0; mi < 4; mi++) {
        const int row = row0 + wm + mi * 16 + (lane >> 2);
        #pragma unroll
        for (int ni = 0; ni < 4; ni++) {
            const int col = lcol0 + wn + ni * 8 + 2 * (lane & 3);
            float v0 = acc[mi][ni][0], v1 = acc[mi][ni][1];
            float v2 = acc[mi][ni][2], v3 = acc[mi][ni][3];
            if (isK) {   // RoPE + hi + decayed copy
                const int p = (col & 127) >> 1;
                float2 cs0 = g_rope[(row & (LQ - 1)) * 64 + p];
                float2 cs1 = g_rope[((row + 8) & (LQ - 1)) * 64 + p];
                float x0 = v0, x1 = v1;
                v0 = x0 * cs0.x - x1 * cs0.y;
                v1 = x1 * cs0.x + x0 * cs0.y;
                x0 = v2; x1 = v3;
                v2 = x0 * cs1.x - x1 * cs1.y;
                v3 = x1 * cs1.x + x0 * cs1.y;
                *(__half2*)(g_Khi + (size_t)row * HQ + col)       = __floats2half2_rn(v0, v1);
                *(__half2*)(g_Khi + (size_t)(row + 8) * HQ + col) = __floats2half2_rn(v2, v3);
                float p0 = exp2f(sdecK * (float)(CHK - (row & (CHK - 1))));
                float p1 = exp2f(sdecK * (float)(CHK - ((row + 8) & (CHK - 1))));
                *(__half2*)(g_Kdec + (size_t)row * HQ + col)       = __floats2half2_rn(v0 * p0, v1 * p0);
                *(__half2*)(g_Kdec + (size_t)(row + 8) * HQ + col) = __floats2half2_rn(v2 * p1, v3 * p1);
            } else {     // V: fp16
                *(__half2*)(g_Vhi + (size_t)row * VDIMQ + col)       = __floats2half2_rn(v0, v1);
                *(__half2*)(g_Vhi + (size_t)(row + 8) * VDIMQ + col) = __floats2half2_rn(v2, v3);
            }
        }
    }
}

// ---------------------------------------------------------------------------
// Wo GEMM (1-term: O fp16 hi only): fp32 out. K=2048, N=1024.
// ---------------------------------------------------------------------------
__global__ void __launch_bounds__(256, 2) wo_gemm(float* __restrict__ C)
{
    extern __shared__ char smem[];
    const uint32_t sbase = smem_u32(smem);
    const int tid  = threadIdx.x;
    const int wid  = tid >> 5;
    const int lane = tid & 31;
    const int row0 = blockIdx.y * 128;
    const int col0 = blockIdx.x * 128;
    const int wm   = (wid & 1) * 64;
    const int wn   = (wid >> 1) * 32;

    float acc[4][4][4];
    #pragma unroll
    for (int mi = 0; mi < 4; mi++)
        #pragma unroll
        for (int ni = 0; ni < 4; ni++)
            #pragma unroll
            for (int e = 0; e < 4; e++) acc[mi][ni][e] = 0.0f;

    GemmOps op{ g_O_hi, nullptr, g_WoT, VDIMQ, row0, col0 };
    gemm_mainloop<false>(op, sbase, acc);

    #pragma unroll
    for (int mi = 0; mi < 4; mi++) {
        const int row = row0 + wm + mi * 16 + (lane >> 2);
        #pragma unroll
        for (int ni = 0; ni < 4; ni++) {
            const int col = col0 + wn + ni * 8 + 2 * (lane & 3);
            *(float2*)(C + (size_t)row * HQ + col) =
                make_float2(acc[mi][ni][0], acc[mi][ni][1]);
            *(float2*)(C + (size_t)(row + 8) * HQ + col) =
                make_float2(acc[mi][ni][2], acc[mi][ni][3]);
        }
    }
}

// ---------------------------------------------------------------------------
// Attention Kernel A: per-chunk outer product  A_c = Kdec_c^T V_c
// ---------------------------------------------------------------------------
#define ATTA_SMEM 98304

__global__ void __launch_bounds__(512) chunk_state_kernel()
{
    extern __shared__ char smem[];
    const uint32_t SB   = smem_u32(smem);
    const uint32_t kbuf = SB;            // [128 r][128 d1] fp16 SW256
    const uint32_t vbuf = SB + 32768;    // [128 r][256 d2] fp16 SW512

    const int ch = blockIdx.x, bh = blockIdx.y;
    const int b = bh >> 3, h = bh & 7;
    const int tid = threadIdx.x, wid = tid >> 5, lane = tid & 31;
    const int trow = ch * CHK;

    const __half* Kd_g = g_Kdec + (size_t)(b * LQ + trow) * HQ + h * DQKQ;
    const __half* Vh_g = g_Vhi + (size_t)(b * LQ + trow) * VDIMQ + h * DVQ;

    #pragma unroll
    for (int t = 0; t < 4; t++) {
        int idx = tid + t * 512;
        int r = idx >> 4, cc = idx & 15;
        ldgsts16(kbuf + SW256(r, cc), Kd_g + (size_t)r * HQ + cc * 8);
    }
    #pragma unroll
    for (int t = 0; t < 8; t++) {
        int idx = tid + t * 512;
        int r = idx >> 5, cc = idx & 31;
        ldgsts16(vbuf + SW512(r, cc), Vh_g + (size_t)r * VDIMQ + cc * 8);
    }
    cp_commit();
    cp_wait<0>();
    __syncthreads();

    const int wm = (wid & 3) * 32;
    const int wn = (wid >> 2) * 64;

    float acc[2][8][4];
    #pragma unroll
    for (int mi = 0; mi < 2; mi++)
        #pragma unroll
        for (int nt = 0; nt < 8; nt++)
            #pragma unroll
            for (int e = 0; e < 4; e++) acc[mi][nt][e] = 0.0f;

    #pragma unroll
    for (int ks = 0; ks < 8; ks++) {
        uint32_t af[2][4];
        #pragma unroll
        for (int mi = 0; mi < 2; mi++) {
            int m0 = wm + mi * 16;
            int r_src = ks * 16 + ((lane >> 4) << 3) + (lane & 7);
            int d_off = (m0 >> 3) + ((lane >> 3) & 1);
            ldsm4t(af[mi], kbuf + SW256(r_src, d_off));
        }
        uint32_t bf[8][2];
        #pragma unroll
        for (int np = 0; np < 4; np++) {
            int row = ks * 16 + ((lane >> 3) & 1) * 8 + (lane & 7);
            int cn  = (wn + np * 16 + (lane >> 4) * 8) >> 3;
            uint32_t rh[4];
            ldsm4t(rh, vbuf + SW512(row, cn));
            bf[2*np][0] = rh[0]; bf[2*np][1] = rh[1];
            bf[2*np+1][0] = rh[2]; bf[2*np+1][1] = rh[3];
        }
        #pragma unroll
        for (int mi = 0; mi < 2; mi++)
            #pragma unroll
            for (int nt = 0; nt < 8; nt++)
                mma_fp16(acc[mi][nt], af[mi], bf[nt]);
    }

    float* Ag = g_A + ((size_t)(bh * NCH + ch) << 15);
    #pragma unroll
    for (int mi = 0; mi < 2; mi++) {
        int d1 = wm + mi * 16 + (lane >> 2);
        #pragma unroll
        for (int nt = 0; nt < 8; nt++) {
            int d2 = wn + nt * 8 + 2 * (lane & 3);
            *(float2*)(Ag + (size_t)d1 * DVQ + d2) =
                make_float2(acc[mi][nt][0], acc[mi][nt][1]);
            *(float2*)(Ag + (size_t)(d1 + 8) * DVQ + d2) =
                make_float2(acc[mi][nt][2], acc[mi][nt][3]);
        }
    }
}

// ---------------------------------------------------------------------------
// Attention Kernel B: per-element decay scan over chunks -> states S_c (hi/lo)
// ---------------------------------------------------------------------------
__global__ void __launch_bounds__(512) scan_kernel()
{
    const int e  = blockIdx.x * 512 + threadIdx.x;
    const int bh = blockIdx.y;
    const int h  = bh & 7;
    const float sdec = log2f(1.0f - exp2f(-5.0f - (float)h));
    const float lamC = exp2f(sdec * (float)CHK);

    const size_t base = (size_t)bh * NCH << 15;
    float S = 0.0f;
    #pragma unroll
    for (int c = 0; c < NCH; c++) {
        size_t off = base + ((size_t)c << 15) + e;
        __half hi = __float2half(S);
        g_Shi[off] = hi;
        g_Slo[off] = __float2half(S - __half2float(hi));
        S = S * lamC + g_A[off];
    }
}

// ---------------------------------------------------------------------------
// Attention Kernel C: per (chunk, bh, dv-half) output.
// ---------------------------------------------------------------------------
#define ATTC_SMEM 229376

__global__ void __launch_bounds__(512) attn_chunk_kernel()
{
    extern __shared__ char smem[];
    const uint32_t SB  = smem_u32(smem);
    const uint32_t sQh = SB;
    const uint32_t sQl = SB + 32768;
    const uint32_t sK  = SB + 65536;
    const uint32_t sSh = SB + 98304;
    const uint32_t sSl = SB + 131072;
    const uint32_t sV  = SB + 163840;
    const uint32_t sPl = SB + 196608;
    const uint32_t sPh = sK;            // aliased after K consumed

    const int vh = blockIdx.x;
    const int ch = blockIdx.y;
    const int bh = blockIdx.z;
    const int b = bh >> 3, h = bh & 7;
    const int tid = threadIdx.x, wid = tid >> 5, lane = tid & 31;
    const int trow = ch * CHK;
    const float sdec = log2f(1.0f - exp2f(-5.0f - (float)h));

    const __half* Qh_g = g_Qhi + (size_t)(b * LQ + trow) * HQ + h * DQKQ;
    const __half* Ql_g = g_Qlo + (size_t)(b * LQ + trow) * HQ + h * DQKQ;
    const __half* Kh_g = g_Khi + (size_t)(b * LQ + trow) * HQ + h * DQKQ;
    const __half* Vh_g = g_Vhi + (size_t)(b * LQ + trow) * VDIMQ + h * DVQ + vh * 128;
    const __half* Sh_g = g_Shi + ((size_t)(bh * NCH + ch) << 15) + vh * 128;
    const __half* Sl_g = g_Slo + ((size_t)(bh * NCH + ch) << 15) + vh * 128;

    #pragma unroll
    for (int t = 0; t < 4; t++) {
        int idx = tid + t * 512;
        int r = idx >> 4, cc = idx & 15;
        ldgsts16(sQh + SW256(r, cc), Qh_g + (size_t)r * HQ + cc * 8);
        ldgsts16(sQl + SW256(r, cc), Ql_g + (size_t)r * HQ + cc * 8);
        ldgsts16(sK  + SW256(r, cc), Kh_g + (size_t)r * HQ + cc * 8);
    }
    cp_commit();
    #pragma unroll
    for (int t = 0; t < 4; t++) {
        int idx = tid + t * 512;
        int r = idx >> 4, cc = idx & 15;
        ldgsts16(sSh + SW256(r, cc), Sh_g + (size_t)r * DVQ + cc * 8);
        ldgsts16(sSl + SW256(r, cc), Sl_g + (size_t)r * DVQ + cc * 8);
        ldgsts16(sV  + SW256(r, cc), Vh_g + (size_t)r * VDIMQ + cc * 8);
    }
    cp_commit();

    const int wm = (wid & 3) * 32;
    const int wn = (wid >> 2) * 32;

    cp_wait<1>();
    __syncthreads();

    // ---- P = Q K^T (128x128), 2 terms ----
    float sacc[2][4][4];
    #pragma unroll
    for (int mi = 0; mi < 2; mi++)
        #pragma unroll
        for (int ni = 0; ni < 4; ni++)
            #pragma unroll
            for (int e = 0; e < 4; e++) sacc[mi][ni][e] = 0.0f;

    #pragma unroll
    for (int ks = 0; ks < 8; ks++) {
        uint32_t qh[2][4], ql[2][4];
        #pragma unroll
        for (int mi = 0; mi < 2; mi++) {
            int r = wm + mi * 16 + (lane & 15);
            int cc = ks * 2 + (lane >> 4);
            uint32_t ad = sQh + SW256(r, cc);
            ldsm4(qh[mi], ad);
            ldsm4(ql[mi], ad + 32768);
        }
        uint32_t kb[4][2];
        #pragma unroll
        for (int j = 0; j < 2; j++) {
            int m4 = lane >> 3;
            int n  = wn + j * 16 + ((m4 >> 1) << 3) + (lane & 7);
            int cc = ks * 2 + (m4 & 1);
            uint32_t rh[4];
            ldsm4(rh, sK + SW256(n, cc));
            kb[2*j][0] = rh[0]; kb[2*j][1] = rh[1];
            kb[2*j+1][0] = rh[2]; kb[2*j+1][1] = rh[3];
        }
        #pragma unroll
        for (int mi = 0; mi < 2; mi++)
            #pragma unroll
            for (int ni = 0; ni < 4; ni++) {
                mma_fp16(sacc[mi][ni], qh[mi], kb[ni]);
                mma_fp16(sacc[mi][ni], ql[mi], kb[ni]);
            }
    }
    __syncthreads();

    // ---- decay + causal + split -> store P hi/lo ----
    #pragma unroll
    for (int mi = 0; mi < 2; mi++) {
        int r0 = wm + mi * 16 + (lane >> 2);
        #pragma unroll
        for (int ni = 0; ni < 4; ni++) {
            int j0 = wn + ni * 8 + 2 * (lane & 3);
            float d00 = (r0 >= j0)         ? exp2f(sdec * (float)(r0 - j0))     : 0.0f;
            float d01 = (r0 >= j0 + 1)     ? exp2f(sdec * (float)(r0 - j0 - 1)) : 0.0f;
            float d10 = (r0 + 8 >= j0)     ? exp2f(sdec * (float)(r0 + 8 - j0))     : 0.0f;
            float d11 = (r0 + 8 >= j0 + 1) ? exp2f(sdec * (float)(r0 + 8 - j0 - 1)) : 0.0f;
            float v0 = sacc[mi][ni][0] * d00, v1 = sacc[mi][ni][1] * d01;
            float v2 = sacc[mi][ni][2] * d10, v3 = sacc[mi][ni][3] * d11;
            float h0 = __half2float(__float2half(v0));
            float h1 = __half2float(__float2half(v1));
            float h2 = __half2float(__float2half(v2));
            float h3 = __half2float(__float2half(v3));
            int cc = j0 >> 3;
            int off = (j0 & 7) * 2;
            sts32(sPh + SW256(r0, cc) + off,     pack_h2(v0, v1));
            sts32(sPl + SW256(r0, cc) + off,     pack_h2(v0 - h0, v1 - h1));
            sts32(sPh + SW256(r0 + 8, cc) + off, pack_h2(v2, v3));
            sts32(sPl + SW256(r0 + 8, cc) + off, pack_h2(v2 - h2, v3 - h3));
        }
    }
    cp_wait<0>();
    __syncthreads();

    // ---- X = Q @ S (128x128), 3 terms ----
    float xacc[2][4][4];
    #pragma unroll
    for (int mi = 0; mi < 2; mi++)
        #pragma unroll
        for (int ni = 0; ni < 4; ni++)
            #pragma unroll
            for (int e = 0; e < 4; e++) xacc[mi][ni][e] = 0.0f;

    #pragma unroll
    for (int ks = 0; ks < 8; ks++) {
        uint32_t qh[2][4], ql[2][4];
        #pragma unroll
        for (int mi = 0; mi < 2; mi++) {
            int r = wm + mi * 16 + (lane & 15);
            int cc = ks * 2 + (lane >> 4);
            uint32_t ad = sQh + SW256(r, cc);
            ldsm4(qh[mi], ad);
            ldsm4(ql[mi], ad + 32768);
        }
        uint32_t sbh[4][2], sbl[4][2];
        #pragma unroll
        for (int np = 0; np < 2; np++) {
            int row = ks * 16 + ((lane >> 3) & 1) * 8 + (lane & 7);
            int cn  = (wn + np * 16 + (lane >> 4) * 8) >> 3;
            uint32_t rh[4], rl[4];
            ldsm4t(rh, sSh + SW256(row, cn));
            ldsm4t(rl, sSl + SW256(row, cn));
            sbh[2*np][0] = rh[0]; sbh[2*np][1] = rh[1];
            sbh[2*np+1][0] = rh[2]; sbh[2*np+1][1] = rh[3];
            sbl[2*np][0] = rl[0]; sbl[2*np][1] = rl[1];
            sbl[2*np+1][0] = rl[2]; sbl[2*np+1][1] = rl[3];
        }
        #pragma unroll
        for (int mi = 0; mi < 2; mi++)
            #pragma unroll
            for (int ni = 0; ni < 4; ni++) {
                mma_fp16(xacc[mi][ni], qh[mi], sbh[ni]);
                mma_fp16(xacc[mi][ni], ql[mi], sbh[ni]);
                mma_fp16(xacc[mi][ni], qh[mi], sbl[ni]);
            }
    }

    // ---- O_intra = P @ V (128x128), 2 terms ----
    float oacc[2][4][4];
    #pragma unroll
    for (int mi = 0; mi < 2; mi++)
        #pragma unroll
        for (int ni = 0; ni < 4; ni++)
            #pragma unroll
            for (int e = 0; e < 4; e++) oacc[mi][ni][e] = 0.0f;

    #pragma unroll
    for (int ks = 0; ks < 8; ks++) {
        uint32_t ph[2][4], pl[2][4];
        #pragma unroll
        for (int mi = 0; mi < 2; mi++) {
            int r = wm + mi * 16 + (lane & 15);
            int cc = ks * 2 + (lane >> 4);
            ldsm4(ph[mi], sPh + SW256(r, cc));
            ldsm4(pl[mi], sPl + SW256(r, cc));
        }
        uint32_t vb[4][2];
        #pragma unroll
        for (int np = 0; np < 2; np++) {
            int row = ks * 16 + ((lane >> 3) & 1) * 8 + (lane & 7);
            int cn  = (wn + np * 16 + (lane >> 4) * 8) >> 3;
            uint32_t rh[4];
            ldsm4t(rh, sV + SW256(row, cn));
            vb[2*np][0] = rh[0]; vb[2*np][1] = rh[1];
            vb[2*np+1][0] = rh[2]; vb[2*np+1][1] = rh[3];
        }
        #pragma unroll
        for (int mi = 0; mi < 2; mi++)
            #pragma unroll
            for (int ni = 0; ni < 4; ni++) {
                mma_fp16(oacc[mi][ni], ph[mi], vb[ni]);
                mma_fp16(oacc[mi][ni], pl[mi], vb[ni]);
            }
    }

    // ---- combine + write O ----
    float* Og = g_O + (size_t)(b * LQ + trow) * VDIMQ + h * DVQ + vh * 128;
    #pragma unroll
    for (int mi = 0; mi < 2; mi++) {
        int r0 = wm + mi * 16 + (lane >> 2);
        float lam0 = exp2f(sdec * (float)r0);
        float lam1 = exp2f(sdec * (float)(r0 + 8));
        #pragma unroll
        for (int ni = 0; ni < 4; ni++) {
            int col = wn + ni * 8 + 2 * (lane & 3);
            *(float2*)(Og + (size_t)r0 * VDIMQ + col) =
                make_float2(oacc[mi][ni][0] + lam0 * xacc[mi][ni][0],
                            oacc[mi][ni][1] + lam0 * xacc[mi][ni][1]);
            *(float2*)(Og + (size_t)(r0 + 8) * VDIMQ + col) =
                make_float2(oacc[mi][ni][2] + lam1 * xacc[mi][ni][2],
                            oacc[mi][ni][3] + lam1 * xacc[mi][ni][3]);
        }
    }
}

// ---------------------------------------------------------------------------
// Fused RMSNorm + swish gate -> fp16 (hi only)
// ---------------------------------------------------------------------------
__global__ void __launch_bounds__(256) normgate_split_kernel(const float* __restrict__ gw)
{
    const int warp = (blockIdx.x << 3) + (threadIdx.x >> 5);
    const int lane = threadIdx.x & 31;
    const size_t base = (size_t)(warp >> 3) * VDIMQ + (size_t)(warp & 7) * DVQ;
    const float* Op = g_O + base;
    const float* Gp = g_G + base;
    __half* Oh = g_O_hi + base;

    const int d0 = lane * 4;
    const int d1 = 128 + lane * 4;
    float4 o0 = *(const float4*)(Op + d0);
    float4 o1 = *(const float4*)(Op + d1);

    float ss = o0.x*o0.x + o0.y*o0.y + o0.z*o0.z + o0.w*o0.w
             + o1.x*o1.x + o1.y*o1.y + o1.z*o1.z + o1.w*o1.w;
    #pragma unroll
    for (int off = 16; off > 0; off >>= 1)
        ss += __shfl_xor_sync(0xFFFFFFFFu, ss, off);

    const float r = rsqrtf(ss * (1.0f / 256.0f) + 1e-5f);

    float4 g0 = *(const float4*)(Gp + d0);
    float4 g1 = *(const float4*)(Gp + d1);
    float4 w0 = *(const float4*)(gw + d0);
    float4 w1 = *(const float4*)(gw + d1);

    float v[8];
    v[0] = o0.x * r * w0.x * (g0.x / (1.0f + expf(-g0.x)));
    v[1] = o0.y * r * w0.y * (g0.y / (1.0f + expf(-g0.y)));
    v[2] = o0.z * r * w0.z * (g0.z / (1.0f + expf(-g0.z)));
    v[3] = o0.w * r * w0.w * (g0.w / (1.0f + expf(-g0.w)));
    v[4] = o1.x * r * w1.x * (g1.x / (1.0f + expf(-g1.x)));
    v[5] = o1.y * r * w1.y * (g1.y / (1.0f + expf(-g1.y)));
    v[6] = o1.z * r * w1.z * (g1.z / (1.0f + expf(-g1.z)));
    v[7] = o1.w * r * w1.w * (g1.w / (1.0f + expf(-g1.w)));

    *(__half2*)(Oh + d0)     = __floats2half2_rn(v[0], v[1]);
    *(__half2*)(Oh + d0 + 2) = __floats2half2_rn(v[2], v[3]);
    *(__half2*)(Oh + d1)     = __floats2half2_rn(v[4], v[5]);
    *(__half2*)(Oh + d1 + 2) = __floats2half2_rn(v[6], v[7]);
}

// ---------------------------------------------------------------------------
// kernel_launch
// ---------------------------------------------------------------------------
extern "C" void kernel_launch(void* const* d_in, const int* in_sizes, int n_in,
                              void* d_out, int out_size)
{
    const float* hs = (const float*)d_in[0];
    const float* Wq = (const float*)d_in[1];
    const float* Wk = (const float*)d_in[2];
    const float* Wv = (const float*)d_in[3];
    const float* Wg = (const float*)d_in[4];
    const float* Wo = (const float*)d_in[5];
    const float* gw = (const float*)d_in[6];
    float* out = (float*)d_out;

    __half *hsh, *hsl;
    __half *qw, *kw, *vw, *gwt, *ow;
    cudaGetSymbolAddress((void**)&hsh, g_hs_hi);
    cudaGetSymbolAddress((void**)&hsl, g_hs_lo);
    cudaGetSymbolAddress((void**)&qw, g_WqT);
    cudaGetSymbolAddress((void**)&kw, g_WkT);
    cudaGetSymbolAddress((void**)&vw, g_WvT);
    cudaGetSymbolAddress((void**)&gwt, g_WgT);
    cudaGetSymbolAddress((void**)&ow, g_WoT);

    cudaFuncSetAttribute(qg_gemm, cudaFuncAttributeMaxDynamicSharedMemorySize, TCG_SMEM_2T);
    cudaFuncSetAttribute(kv_gemm, cudaFuncAttributeMaxDynamicSharedMemorySize, TCG_SMEM_1T);
    cudaFuncSetAttribute(wo_gemm, cudaFuncAttributeMaxDynamicSharedMemorySize, TCG_SMEM_1T);
    cudaFuncSetAttribute(chunk_state_kernel, cudaFuncAttributeMaxDynamicSharedMemorySize, ATTA_SMEM);
    cudaFuncSetAttribute(attn_chunk_kernel,  cudaFuncAttributeMaxDynamicSharedMemorySize, ATTC_SMEM);

    dim3 blk(256);

    // 1) prep: hs split + RoPE table + weight transposes
    split_kernel<<<(MROWS*HQ/4 + 255)/256, blk>>>(hs, hsh, hsl, MROWS*HQ/4);
    rope_table_kernel<<<LQ*64/256, blk>>>();
    TDescs ds;
    ds.d[0] = { Wq, qw,  HQ,    HQ,    0    };
    ds.d[1] = { Wk, kw,  HQ,    HQ,    1024 };
    ds.d[2] = { Wv, vw,  HQ,    VDIMQ, 2048 };
    ds.d[3] = { Wg, gwt, HQ,    VDIMQ, 4096 };
    ds.d[4] = { Wo, ow,  VDIMQ, HQ,    6144 };
    transpose_multi<<<8192, blk>>>(ds);

    // 2) projections: KV first (1-term, 24 blocks: 8 K + 16 V), then QG (2-term)
    kv_gemm<<<dim3(24, MROWS/128), blk, TCG_SMEM_1T>>>();
    qg_gemm<<<dim3(24, MROWS/128), blk, TCG_SMEM_2T>>>();

    // 3) chunked-recurrent retention: states -> scan -> outputs
    chunk_state_kernel<<<dim3(NCH, 16), 512, ATTA_SMEM>>>();
    scan_kernel<<<dim3(64, 16), 512>>>();
    attn_chunk_kernel<<<dim3(2, NCH, 16), 512, ATTC_SMEM>>>();

    // 4) fused RMSNorm + swish gate (fp16 hi only)
    normgate_split_kernel<<<4096, blk>>>(gw);

    // 5) output projection (1-term)
    wo_gemm<<<dim3(HQ/128, MROWS/128), blk, TCG_SMEM_1T>>>(out);
}

// round 16
// speedup vs baseline: 1.6904x; 1.1622x over previous
#include <cuda_runtime.h>
#include <cuda_fp16.h>
#include <math.h>
#include <stdint.h>

// Problem constants
#define BQ 2
#define LQ 2048
#define HQ 1024
#define NHQ 8
#define DQKQ 128
#define DVQ 256
#define VDIMQ 2048
#define MROWS (BQ*LQ)   // 4096
#define CHK 128         // retention chunk size
#define NCH (LQ/CHK)    // 16 chunks per sequence

#define QSCALE 0.08838834764831843f          // 128^-0.5
#define RF (-0.20762050593045852f)           // -2*log2(10000)/128

// ---------------------------------------------------------------------------
// Scratch (device globals)
// ---------------------------------------------------------------------------
__device__ float g_G[MROWS*VDIMQ];
__device__ float g_O[MROWS*VDIMQ];
__device__ float g_A[16*NCH*DQKQ*DVQ];            // per-chunk KV outer products
__device__ float2 g_rope[LQ*64];                  // (cos, sin) per (t, pair)

__device__ __half g_hs_hi[MROWS*HQ],  g_hs_lo[MROWS*HQ];
__device__ __half g_O_hi[MROWS*VDIMQ];
__device__ __half g_Qhi[MROWS*HQ],    g_Qlo[MROWS*HQ];
__device__ __half g_Khi[MROWS*HQ];
__device__ __half g_Kdec[MROWS*HQ];               // K * lam^(CHK - r%CHK)
__device__ __half g_Vhi[MROWS*VDIMQ];
__device__ __half g_Shi[16*NCH*DQKQ*DVQ];         // chunk-entry states hi
__device__ __half g_Slo[16*NCH*DQKQ*DVQ];         // chunk-entry states lo
__device__ __half g_WqT[HQ*HQ];
__device__ __half g_WkT[HQ*HQ];
__device__ __half g_WvT[VDIMQ*HQ];
__device__ __half g_WgT[VDIMQ*HQ];
__device__ __half g_WoT[HQ*VDIMQ];

// ---------------------------------------------------------------------------
// PTX helpers
// ---------------------------------------------------------------------------
__device__ __forceinline__ uint32_t smem_u32(const void* p) {
    uint32_t a;
    asm("{ .reg .u64 t; cvta.to.shared.u64 t, %1; cvt.u32.u64 %0, t; }"
        : "=r"(a) : "l"(p));
    return a;
}
__device__ __forceinline__ void ldgsts16(uint32_t dst, const void* src) {
    asm volatile("cp.async.cg.shared.global [%0], [%1], 16;" :: "r"(dst), "l"(src));
}
__device__ __forceinline__ void cp_commit() {
    asm volatile("cp.async.commit_group;" ::: "memory");
}
template<int N_>
__device__ __forceinline__ void cp_wait() {
    asm volatile("cp.async.wait_group %0;" :: "n"(N_) : "memory");
}
__device__ __forceinline__ void ldsm4(uint32_t* r, uint32_t addr) {
    asm volatile("ldmatrix.sync.aligned.m8n8.x4.shared.b16 {%0,%1,%2,%3}, [%4];"
        : "=r"(r[0]), "=r"(r[1]), "=r"(r[2]), "=r"(r[3]) : "r"(addr));
}
__device__ __forceinline__ void ldsm4t(uint32_t* r, uint32_t addr) {
    asm volatile("ldmatrix.sync.aligned.m8n8.x4.trans.shared.b16 {%0,%1,%2,%3}, [%4];"
        : "=r"(r[0]), "=r"(r[1]), "=r"(r[2]), "=r"(r[3]) : "r"(addr));
}
__device__ __forceinline__ void sts32(uint32_t addr, uint32_t v) {
    asm volatile("st.shared.b32 [%0], %1;" :: "r"(addr), "r"(v) : "memory");
}
__device__ __forceinline__ void mma_fp16(float* c, const uint32_t* a, const uint32_t* b) {
    asm volatile("mma.sync.aligned.m16n8k16.row.col.f32.f16.f16.f32 "
        "{%0,%1,%2,%3}, {%4,%5,%6,%7}, {%8,%9}, {%0,%1,%2,%3};"
        : "+f"(c[0]), "+f"(c[1]), "+f"(c[2]), "+f"(c[3])
        : "r"(a[0]), "r"(a[1]), "r"(a[2]), "r"(a[3]), "r"(b[0]), "r"(b[1]));
}
__device__ __forceinline__ uint32_t pack_h2(float a, float b) {
    __half2 t = __floats2half2_rn(a, b);
    return *(uint32_t*)&t;
}

// Swizzles: row stride in bytes; 16B chunk xor'd by (r&7)
#define SW128R(r, c) ((uint32_t)((r) * 128u + ((uint32_t)((c) ^ ((r) & 7)) << 4)))
#define SW256(r, c)  ((uint32_t)((r) * 256u + ((uint32_t)((c) ^ ((r) & 7)) << 4)))
#define SW512(r, c)  ((uint32_t)((r) * 512u + ((uint32_t)((c) ^ ((r) & 7)) << 4)))

// GEMM tiles per operand: 128x64 fp16 = 16KB. 2-stage pipelines.
// 2-term stage: Ahi|Alo|Bhi = 48KB; 1-term stage: Ahi|Bhi = 32KB.
#define GST_ALO 16384
#define TCG_SMEM_2T (2 * 49152)
#define TCG_SMEM_1T (2 * 32768)

// ---------------------------------------------------------------------------
// hs split -> fp16 hi/lo
// ---------------------------------------------------------------------------
__global__ void __launch_bounds__(256) split_kernel(const float* __restrict__ x,
                                                    __half* __restrict__ hi,
                                                    __half* __restrict__ lo,
                                                    int n4)
{
    int i = blockIdx.x * 256 + threadIdx.x;
    if (i >= n4) return;
    float4 v = ((const float4*)x)[i];
    __half h0 = __float2half(v.x), h1 = __float2half(v.y);
    __half h2 = __float2half(v.z), h3 = __float2half(v.w);
    __half l0 = __float2half(v.x - __half2float(h0));
    __half l1 = __float2half(v.y - __half2float(h1));
    __half l2 = __float2half(v.z - __half2float(h2));
    __half l3 = __float2half(v.w - __half2float(h3));
    ((__half2*)hi)[2*i]   = __half2(h0, h1);
    ((__half2*)hi)[2*i+1] = __half2(h2, h3);
    ((__half2*)lo)[2*i]   = __half2(l0, l1);
    ((__half2*)lo)[2*i+1] = __half2(l2, l3);
}

// ---------------------------------------------------------------------------
// RoPE table
// ---------------------------------------------------------------------------
__global__ void __launch_bounds__(256) rope_table_kernel()
{
    int i = blockIdx.x * 256 + threadIdx.x;    // 0..131071
    int t = i >> 6, p = i & 63;
    float inv = exp2f((float)p * RF);
    float s, c;
    sincosf((float)t * inv, &s, &c);
    g_rope[i] = make_float2(c, s);
}

// ---------------------------------------------------------------------------
// Merged weight transpose (fp16): one launch for all 5 weights.
// ---------------------------------------------------------------------------
struct TDesc { const float* W; __half* hi; int K, N, start; };
struct TDescs { TDesc d[5]; };

__global__ void __launch_bounds__(256) transpose_multi(TDescs ds)
{
    __shared__ float s[32][33];
    int t = blockIdx.x;
    int i = 0;
    #pragma unroll
    for (int j = 1; j < 5; j++) if (t >= ds.d[j].start) i = j;
    const float* W = ds.d[i].W;
    __half* Th = ds.d[i].hi;
    const int K = ds.d[i].K, N = ds.d[i].N;
    int lt = t - ds.d[i].start;
    int ncols = N >> 5;
    int k0 = (lt / ncols) * 32;
    int n0 = (lt % ncols) * 32;

    const int tx = threadIdx.x & 31;
    const int ty = threadIdx.x >> 5;
    #pragma unroll
    for (int q = 0; q < 4; q++)
        s[ty + 8*q][tx] = W[(size_t)(k0 + ty + 8*q) * N + n0 + tx];
    __syncthreads();
    #pragma unroll
    for (int q = 0; q < 4; q++) {
        float v = s[tx][ty + 8*q];
        Th[(size_t)(n0 + ty + 8*q) * K + k0 + tx] = __float2half(v);
    }
}

// ---------------------------------------------------------------------------
// GEMM mainloop: 128x128 tile, 8 warps (64x32), K-chunk 64, 2-stage pipeline.
// TWOT: A hi/lo 2-term; else A hi only.
// ---------------------------------------------------------------------------
struct GemmOps {
    const __half *Ah, *Al, *Bh;
    int K, row0, bcol0;
};

template<bool TWOT>
__device__ __forceinline__ void gemm_mainloop(const GemmOps& op, uint32_t sbase,
                                              float acc[4][4][4])
{
    constexpr uint32_t GST_B   = TWOT ? 32768u : 16384u;
    constexpr uint32_t G_STAGE = TWOT ? 49152u : 32768u;

    const int tid  = threadIdx.x;
    const int wid  = tid >> 5;
    const int lane = tid & 31;
    const int wm   = (wid & 1) * 64;
    const int wn   = (wid >> 1) * 32;
    const int K    = op.K;
    const int nchunks = K >> 6;

    auto load_chunk = [&](uint32_t sb, int k0) {
        #pragma unroll
        for (int t = 0; t < 4; t++) {
            int idx = tid + t * 256;
            int r   = idx >> 3;
            int c   = idx & 7;
            uint32_t soff = SW128R(r, c);
            size_t aoff = (size_t)(op.row0 + r) * K + k0 + c * 8;
            size_t boff = (size_t)(op.bcol0 + r) * K + k0 + c * 8;
            ldgsts16(sb + soff, op.Ah + aoff);
            if (TWOT) ldgsts16(sb + GST_ALO + soff, op.Al + aoff);
            ldgsts16(sb + GST_B + soff, op.Bh + boff);
        }
        cp_commit();
    };

    load_chunk(sbase, 0);
    if (nchunks > 1) load_chunk(sbase + G_STAGE, 64);

    for (int cch = 0; cch < nchunks; cch++) {
        const uint32_t sb = sbase + (uint32_t)(cch & 1) * G_STAGE;
        if (cch + 1 < nchunks) {
            cp_wait<1>();
        } else {
            cp_wait<0>();
        }
        __syncthreads();

        #pragma unroll
        for (int ks = 0; ks < 4; ks++) {
            uint32_t ahi[4][4], alo[4][4];
            #pragma unroll
            for (int mi = 0; mi < 4; mi++) {
                int r = wm + mi * 16 + (lane & 15);
                int c = ks * 2 + (lane >> 4);
                uint32_t ad = sb + SW128R(r, c);
                ldsm4(ahi[mi], ad);
                if (TWOT) ldsm4(alo[mi], ad + GST_ALO);
            }
            uint32_t bhi[4][2];
            #pragma unroll
            for (int j = 0; j < 2; j++) {
                int m4 = lane >> 3;
                int n  = wn + j * 16 + ((m4 >> 1) << 3) + (lane & 7);
                int c  = ks * 2 + (m4 & 1);
                uint32_t rh[4];
                ldsm4(rh, sb + GST_B + SW128R(n, c));
                bhi[2*j][0] = rh[0]; bhi[2*j][1] = rh[1];
                bhi[2*j+1][0] = rh[2]; bhi[2*j+1][1] = rh[3];
            }
            #pragma unroll
            for (int mi = 0; mi < 4; mi++)
                #pragma unroll
                for (int ni = 0; ni < 4; ni++) {
                    mma_fp16(acc[mi][ni], ahi[mi], bhi[ni]);
                    if (TWOT) mma_fp16(acc[mi][ni], alo[mi], bhi[ni]);
                }
        }
        __syncthreads();
        if (cch + 2 < nchunks) load_chunk(sb, (cch + 2) * 64);
    }
}

// ---------------------------------------------------------------------------
// Q GEMM (2-term): grid (8, 32). Q: scale + RoPE + hi/lo split.
// ---------------------------------------------------------------------------
__global__ void __launch_bounds__(256, 2) q_gemm()
{
    extern __shared__ char smem[];
    const uint32_t sbase = smem_u32(smem);
    const int tid  = threadIdx.x;
    const int wid  = tid >> 5;
    const int lane = tid & 31;
    const int row0 = blockIdx.y * 128;
    const int lcol0 = blockIdx.x * 128;
    const int wm   = (wid & 1) * 64;
    const int wn   = (wid >> 1) * 32;

    float acc[4][4][4];
    #pragma unroll
    for (int mi = 0; mi < 4; mi++)
        #pragma unroll
        for (int ni = 0; ni < 4; ni++)
            #pragma unroll
            for (int e = 0; e < 4; e++) acc[mi][ni][e] = 0.0f;

    GemmOps op{ g_hs_hi, g_hs_lo, g_WqT, HQ, row0, lcol0 };
    gemm_mainloop<true>(op, sbase, acc);

    #pragma unroll
    for (int mi = 0; mi < 4; mi++) {
        const int row = row0 + wm + mi * 16 + (lane >> 2);
        #pragma unroll
        for (int ni = 0; ni < 4; ni++) {
            const int col = lcol0 + wn + ni * 8 + 2 * (lane & 3);
            float v0 = acc[mi][ni][0] * QSCALE, v1 = acc[mi][ni][1] * QSCALE;
            float v2 = acc[mi][ni][2] * QSCALE, v3 = acc[mi][ni][3] * QSCALE;
            const int p = (col & 127) >> 1;
            float2 cs0 = g_rope[(row & (LQ - 1)) * 64 + p];
            float2 cs1 = g_rope[((row + 8) & (LQ - 1)) * 64 + p];
            float x0 = v0, x1 = v1;
            v0 = x0 * cs0.x - x1 * cs0.y;
            v1 = x1 * cs0.x + x0 * cs0.y;
            x0 = v2; x1 = v3;
            v2 = x0 * cs1.x - x1 * cs1.y;
            v3 = x1 * cs1.x + x0 * cs1.y;
            __half h0 = __float2half(v0), h1 = __float2half(v1);
            __half h2 = __float2half(v2), h3 = __float2half(v3);
            __half l0 = __float2half(v0 - __half2float(h0));
            __half l1 = __float2half(v1 - __half2float(h1));
            __half l2 = __float2half(v2 - __half2float(h2));
            __half l3 = __float2half(v3 - __half2float(h3));
            *(__half2*)(g_Qhi + (size_t)row * HQ + col)       = __half2(h0, h1);
            *(__half2*)(g_Qhi + (size_t)(row + 8) * HQ + col) = __half2(h2, h3);
            *(__half2*)(g_Qlo + (size_t)row * HQ + col)       = __half2(l0, l1);
            *(__half2*)(g_Qlo + (size_t)(row + 8) * HQ + col) = __half2(l2, l3);
        }
    }
}

// ---------------------------------------------------------------------------
// KVG GEMM (1-term): grid (40, 32).
// cb<8: K (+Kdec) | cb<24: V (fp16) | else: G (fp32)
// ---------------------------------------------------------------------------
__global__ void __launch_bounds__(256, 2) kvg_gemm()
{
    extern __shared__ char smem[];
    const uint32_t sbase = smem_u32(smem);
    const int tid  = threadIdx.x;
    const int wid  = tid >> 5;
    const int lane = tid & 31;
    const int row0 = blockIdx.y * 128;
    const int cb   = blockIdx.x;
    const int wm   = (wid & 1) * 64;
    const int wn   = (wid >> 1) * 32;

    int mode, lcol0;
    const __half* Bh;
    if (cb < 8)       { mode = 0; lcol0 = cb * 128;        Bh = g_WkT; }
    else if (cb < 24) { mode = 1; lcol0 = (cb - 8) * 128;  Bh = g_WvT; }
    else              { mode = 2; lcol0 = (cb - 24) * 128; Bh = g_WgT; }

    float acc[4][4][4];
    #pragma unroll
    for (int mi = 0; mi < 4; mi++)
        #pragma unroll
        for (int ni = 0; ni < 4; ni++)
            #pragma unroll
            for (int e = 0; e < 4; e++) acc[mi][ni][e] = 0.0f;

    GemmOps op{ g_hs_hi, nullptr, Bh, HQ, row0, lcol0 };
    gemm_mainloop<false>(op, sbase, acc);

    float sdecK = 0.0f;
    if (mode == 0) sdecK = log2f(1.0f - exp2f(-5.0f - (float)cb));

    #pragma unroll
    for (int mi = 0; mi < 4; mi++) {
        const int row = row0 + wm + mi * 16 + (lane >> 2);
        #pragma unroll
        for (int ni = 0; ni < 4; ni++) {
            const int col = lcol0 + wn + ni * 8 + 2 * (lane & 3);
            float v0 = acc[mi][ni][0], v1 = acc[mi][ni][1];
            float v2 = acc[mi][ni][2], v3 = acc[mi][ni][3];
            if (mode == 0) {   // K: RoPE + hi + decayed copy
                const int p = (col & 127) >> 1;
                float2 cs0 = g_rope[(row & (LQ - 1)) * 64 + p];
                float2 cs1 = g_rope[((row + 8) & (LQ - 1)) * 64 + p];
                float x0 = v0, x1 = v1;
                v0 = x0 * cs0.x - x1 * cs0.y;
                v1 = x1 * cs0.x + x0 * cs0.y;
                x0 = v2; x1 = v3;
                v2 = x0 * cs1.x - x1 * cs1.y;
                v3 = x1 * cs1.x + x0 * cs1.y;
                *(__half2*)(g_Khi + (size_t)row * HQ + col)       = __floats2half2_rn(v0, v1);
                *(__half2*)(g_Khi + (size_t)(row + 8) * HQ + col) = __floats2half2_rn(v2, v3);
                float p0 = exp2f(sdecK * (float)(CHK - (row & (CHK - 1))));
                float p1 = exp2f(sdecK * (float)(CHK - ((row + 8) & (CHK - 1))));
                *(__half2*)(g_Kdec + (size_t)row * HQ + col)       = __floats2half2_rn(v0 * p0, v1 * p0);
                *(__half2*)(g_Kdec + (size_t)(row + 8) * HQ + col) = __floats2half2_rn(v2 * p1, v3 * p1);
            } else if (mode == 1) {   // V: fp16
                *(__half2*)(g_Vhi + (size_t)row * VDIMQ + col)       = __floats2half2_rn(v0, v1);
                *(__half2*)(g_Vhi + (size_t)(row + 8) * VDIMQ + col) = __floats2half2_rn(v2, v3);
            } else {                  // G: fp32
                *(float2*)(g_G + (size_t)row * VDIMQ + col)       = make_float2(v0, v1);
                *(float2*)(g_G + (size_t)(row + 8) * VDIMQ + col) = make_float2(v2, v3);
            }
        }
    }
}

// ---------------------------------------------------------------------------
// Wo GEMM (1-term: O fp16 hi only): fp32 out. K=2048, N=1024.
// ---------------------------------------------------------------------------
__global__ void __launch_bounds__(256, 2) wo_gemm(float* __restrict__ C)
{
    extern __shared__ char smem[];
    const uint32_t sbase = smem_u32(smem);
    const int tid  = threadIdx.x;
    const int wid  = tid >> 5;
    const int lane = tid & 31;
    const int row0 = blockIdx.y * 128;
    const int col0 = blockIdx.x * 128;
    const int wm   = (wid & 1) * 64;
    const int wn   = (wid >> 1) * 32;

    float acc[4][4][4];
    #pragma unroll
    for (int mi = 0; mi < 4; mi++)
        #pragma unroll
        for (int ni = 0; ni < 4; ni++)
            #pragma unroll
            for (int e = 0; e < 4; e++) acc[mi][ni][e] = 0.0f;

    GemmOps op{ g_O_hi, nullptr, g_WoT, VDIMQ, row0, col0 };
    gemm_mainloop<false>(op, sbase, acc);

    #pragma unroll
    for (int mi = 0; mi < 4; mi++) {
        const int row = row0 + wm + mi * 16 + (lane >> 2);
        #pragma unroll
        for (int ni = 0; ni < 4; ni++) {
            const int col = col0 + wn + ni * 8 + 2 * (lane & 3);
            *(float2*)(C + (size_t)row * HQ + col) =
                make_float2(acc[mi][ni][0], acc[mi][ni][1]);
            *(float2*)(C + (size_t)(row + 8) * HQ + col) =
                make_float2(acc[mi][ni][2], acc[mi][ni][3]);
        }
    }
}

// ---------------------------------------------------------------------------
// Attention Kernel A: per-chunk outer product  A_c = Kdec_c^T V_c
// ---------------------------------------------------------------------------
#define ATTA_SMEM 98304

__global__ void __launch_bounds__(512) chunk_state_kernel()
{
    extern __shared__ char smem[];
    const uint32_t SB   = smem_u32(smem);
    const uint32_t kbuf = SB;            // [128 r][128 d1] fp16 SW256
    const uint32_t vbuf = SB + 32768;    // [128 r][256 d2] fp16 SW512

    const int ch = blockIdx.x, bh = blockIdx.y;
    const int b = bh >> 3, h = bh & 7;
    const int tid = threadIdx.x, wid = tid >> 5, lane = tid & 31;
    const int trow = ch * CHK;

    const __half* Kd_g = g_Kdec + (size_t)(b * LQ + trow) * HQ + h * DQKQ;
    const __half* Vh_g = g_Vhi + (size_t)(b * LQ + trow) * VDIMQ + h * DVQ;

    #pragma unroll
    for (int t = 0; t < 4; t++) {
        int idx = tid + t * 512;
        int r = idx >> 4, cc = idx & 15;
        ldgsts16(kbuf + SW256(r, cc), Kd_g + (size_t)r * HQ + cc * 8);
    }
    #pragma unroll
    for (int t = 0; t < 8; t++) {
        int idx = tid + t * 512;
        int r = idx >> 5, cc = idx & 31;
        ldgsts16(vbuf + SW512(r, cc), Vh_g + (size_t)r * VDIMQ + cc * 8);
    }
    cp_commit();
    cp_wait<0>();
    __syncthreads();

    const int wm = (wid & 3) * 32;
    const int wn = (wid >> 2) * 64;

    float acc[2][8][4];
    #pragma unroll
    for (int mi = 0; mi < 2; mi++)
        #pragma unroll
        for (int nt = 0; nt < 8; nt++)
            #pragma unroll
            for (int e = 0; e < 4; e++) acc[mi][nt][e] = 0.0f;

    #pragma unroll
    for (int ks = 0; ks < 8; ks++) {
        uint32_t af[2][4];
        #pragma unroll
        for (int mi = 0; mi < 2; mi++) {
            int m0 = wm + mi * 16;
            int r_src = ks * 16 + ((lane >> 4) << 3) + (lane & 7);
            int d_off = (m0 >> 3) + ((lane >> 3) & 1);
            ldsm4t(af[mi], kbuf + SW256(r_src, d_off));
        }
        uint32_t bf[8][2];
        #pragma unroll
        for (int np = 0; np < 4; np++) {
            int row = ks * 16 + ((lane >> 3) & 1) * 8 + (lane & 7);
            int cn  = (wn + np * 16 + (lane >> 4) * 8) >> 3;
            uint32_t rh[4];
            ldsm4t(rh, vbuf + SW512(row, cn));
            bf[2*np][0] = rh[0]; bf[2*np][1] = rh[1];
            bf[2*np+1][0] = rh[2]; bf[2*np+1][1] = rh[3];
        }
        #pragma unroll
        for (int mi = 0; mi < 2; mi++)
            #pragma unroll
            for (int nt = 0; nt < 8; nt++)
                mma_fp16(acc[mi][nt], af[mi], bf[nt]);
    }

    float* Ag = g_A + ((size_t)(bh * NCH + ch) << 15);
    #pragma unroll
    for (int mi = 0; mi < 2; mi++) {
        int d1 = wm + mi * 16 + (lane >> 2);
        #pragma unroll
        for (int nt = 0; nt < 8; nt++) {
            int d2 = wn + nt * 8 + 2 * (lane & 3);
            *(float2*)(Ag + (size_t)d1 * DVQ + d2) =
                make_float2(acc[mi][nt][0], acc[mi][nt][1]);
            *(float2*)(Ag + (size_t)(d1 + 8) * DVQ + d2) =
                make_float2(acc[mi][nt][2], acc[mi][nt][3]);
        }
    }
}

// ---------------------------------------------------------------------------
// Attention Kernel B: per-element decay scan over chunks -> states S_c (hi/lo)
// ---------------------------------------------------------------------------
__global__ void __launch_bounds__(512) scan_kernel()
{
    const int e  = blockIdx.x * 512 + threadIdx.x;
    const int bh = blockIdx.y;
    const int h  = bh & 7;
    const float sdec = log2f(1.0f - exp2f(-5.0f - (float)h));
    const float lamC = exp2f(sdec * (float)CHK);

    const size_t base = (size_t)bh * NCH << 15;
    float S = 0.0f;
    #pragma unroll
    for (int c = 0; c < NCH; c++) {
        size_t off = base + ((size_t)c << 15) + e;
        __half hi = __float2half(S);
        g_Shi[off] = hi;
        g_Slo[off] = __float2half(S - __half2float(hi));
        S = S * lamC + g_A[off];
    }
}

// ---------------------------------------------------------------------------
// Attention Kernel C: per (chunk, bh, dv-half) output.
// ---------------------------------------------------------------------------
#define ATTC_SMEM 229376

__global__ void __launch_bounds__(512) attn_chunk_kernel()
{
    extern __shared__ char smem[];
    const uint32_t SB  = smem_u32(smem);
    const uint32_t sQh = SB;
    const uint32_t sQl = SB + 32768;
    const uint32_t sK  = SB + 65536;
    const uint32_t sSh = SB + 98304;
    const uint32_t sSl = SB + 131072;
    const uint32_t sV  = SB + 163840;
    const uint32_t sPl = SB + 196608;
    const uint32_t sPh = sK;            // aliased after K consumed

    const int vh = blockIdx.x;
    const int ch = blockIdx.y;
    const int bh = blockIdx.z;
    const int b = bh >> 3, h = bh & 7;
    const int tid = threadIdx.x, wid = tid >> 5, lane = tid & 31;
    const int trow = ch * CHK;
    const float sdec = log2f(1.0f - exp2f(-5.0f - (float)h));

    const __half* Qh_g = g_Qhi + (size_t)(b * LQ + trow) * HQ + h * DQKQ;
    const __half* Ql_g = g_Qlo + (size_t)(b * LQ + trow) * HQ + h * DQKQ;
    const __half* Kh_g = g_Khi + (size_t)(b * LQ + trow) * HQ + h * DQKQ;
    const __half* Vh_g = g_Vhi + (size_t)(b * LQ + trow) * VDIMQ + h * DVQ + vh * 128;
    const __half* Sh_g = g_Shi + ((size_t)(bh * NCH + ch) << 15) + vh * 128;
    const __half* Sl_g = g_Slo + ((size_t)(bh * NCH + ch) << 15) + vh * 128;

    #pragma unroll
    for (int t = 0; t < 4; t++) {
        int idx = tid + t * 512;
        int r = idx >> 4, cc = idx & 15;
        ldgsts16(sQh + SW256(r, cc), Qh_g + (size_t)r * HQ + cc * 8);
        ldgsts16(sQl + SW256(r, cc), Ql_g + (size_t)r * HQ + cc * 8);
        ldgsts16(sK  + SW256(r, cc), Kh_g + (size_t)r * HQ + cc * 8);
    }
    cp_commit();
    #pragma unroll
    for (int t = 0; t < 4; t++) {
        int idx = tid + t * 512;
        int r = idx >> 4, cc = idx & 15;
        ldgsts16(sSh + SW256(r, cc), Sh_g + (size_t)r * DVQ + cc * 8);
        ldgsts16(sSl + SW256(r, cc), Sl_g + (size_t)r * DVQ + cc * 8);
        ldgsts16(sV  + SW256(r, cc), Vh_g + (size_t)r * VDIMQ + cc * 8);
    }
    cp_commit();

    const int wm = (wid & 3) * 32;
    const int wn = (wid >> 2) * 32;

    cp_wait<1>();
    __syncthreads();

    // ---- P = Q K^T (128x128), 2 terms ----
    float sacc[2][4][4];
    #pragma unroll
    for (int mi = 0; mi < 2; mi++)
        #pragma unroll
        for (int ni = 0; ni < 4; ni++)
            #pragma unroll
            for (int e = 0; e < 4; e++) sacc[mi][ni][e] = 0.0f;

    #pragma unroll
    for (int ks = 0; ks < 8; ks++) {
        uint32_t qh[2][4], ql[2][4];
        #pragma unroll
        for (int mi = 0; mi < 2; mi++) {
            int r = wm + mi * 16 + (lane & 15);
            int cc = ks * 2 + (lane >> 4);
            uint32_t ad = sQh + SW256(r, cc);
            ldsm4(qh[mi], ad);
            ldsm4(ql[mi], ad + 32768);
        }
        uint32_t kb[4][2];
        #pragma unroll
        for (int j = 0; j < 2; j++) {
            int m4 = lane >> 3;
            int n  = wn + j * 16 + ((m4 >> 1) << 3) + (lane & 7);
            int cc = ks * 2 + (m4 & 1);
            uint32_t rh[4];
            ldsm4(rh, sK + SW256(n, cc));
            kb[2*j][0] = rh[0]; kb[2*j][1] = rh[1];
            kb[2*j+1][0] = rh[2]; kb[2*j+1][1] = rh[3];
        }
        #pragma unroll
        for (int mi = 0; mi < 2; mi++)
            #pragma unroll
            for (int ni = 0; ni < 4; ni++) {
                mma_fp16(sacc[mi][ni], qh[mi], kb[ni]);
                mma_fp16(sacc[mi][ni], ql[mi], kb[ni]);
            }
    }
    __syncthreads();

    // ---- decay + causal + split -> store P hi/lo ----
    #pragma unroll
    for (int mi = 0; mi < 2; mi++) {
        int r0 = wm + mi * 16 + (lane >> 2);
        #pragma unroll
        for (int ni = 0; ni < 4; ni++) {
            int j0 = wn + ni * 8 + 2 * (lane & 3);
            float d00 = (r0 >= j0)         ? exp2f(sdec * (float)(r0 - j0))     : 0.0f;
            float d01 = (r0 >= j0 + 1)     ? exp2f(sdec * (float)(r0 - j0 - 1)) : 0.0f;
            float d10 = (r0 + 8 >= j0)     ? exp2f(sdec * (float)(r0 + 8 - j0))     : 0.0f;
            float d11 = (r0 + 8 >= j0 + 1) ? exp2f(sdec * (float)(r0 + 8 - j0 - 1)) : 0.0f;
            float v0 = sacc[mi][ni][0] * d00, v1 = sacc[mi][ni][1] * d01;
            float v2 = sacc[mi][ni][2] * d10, v3 = sacc[mi][ni][3] * d11;
            float h0 = __half2float(__float2half(v0));
            float h1 = __half2float(__float2half(v1));
            float h2 = __half2float(__float2half(v2));
            float h3 = __half2float(__float2half(v3));
            int cc = j0 >> 3;
            int off = (j0 & 7) * 2;
            sts32(sPh + SW256(r0, cc) + off,     pack_h2(v0, v1));
            sts32(sPl + SW256(r0, cc) + off,     pack_h2(v0 - h0, v1 - h1));
            sts32(sPh + SW256(r0 + 8, cc) + off, pack_h2(v2, v3));
            sts32(sPl + SW256(r0 + 8, cc) + off, pack_h2(v2 - h2, v3 - h3));
        }
    }
    cp_wait<0>();
    __syncthreads();

    // ---- X = Q @ S (128x128), 3 terms ----
    float xacc[2][4][4];
    #pragma unroll
    for (int mi = 0; mi < 2; mi++)
        #pragma unroll
        for (int ni = 0; ni < 4; ni++)
            #pragma unroll
            for (int e = 0; e < 4; e++) xacc[mi][ni][e] = 0.0f;

    #pragma unroll
    for (int ks = 0; ks < 8; ks++) {
        uint32_t qh[2][4], ql[2][4];
        #pragma unroll
        for (int mi = 0; mi < 2; mi++) {
            int r = wm + mi * 16 + (lane & 15);
            int cc = ks * 2 + (lane >> 4);
            uint32_t ad = sQh + SW256(r, cc);
            ldsm4(qh[mi], ad);
            ldsm4(ql[mi], ad + 32768);
        }
        uint32_t sbh[4][2], sbl[4][2];
        #pragma unroll
        for (int np = 0; np < 2; np++) {
            int row = ks * 16 + ((lane >> 3) & 1) * 8 + (lane & 7);
            int cn  = (wn + np * 16 + (lane >> 4) * 8) >> 3;
            uint32_t rh[4], rl[4];
            ldsm4t(rh, sSh + SW256(row, cn));
            ldsm4t(rl, sSl + SW256(row, cn));
            sbh[2*np][0] = rh[0]; sbh[2*np][1] = rh[1];
            sbh[2*np+1][0] = rh[2]; sbh[2*np+1][1] = rh[3];
            sbl[2*np][0] = rl[0]; sbl[2*np][1] = rl[1];
            sbl[2*np+1][0] = rl[2]; sbl[2*np+1][1] = rl[3];
        }
        #pragma unroll
        for (int mi = 0; mi < 2; mi++)
            #pragma unroll
            for (int ni = 0; ni < 4; ni++) {
                mma_fp16(xacc[mi][ni], qh[mi], sbh[ni]);
                mma_fp16(xacc[mi][ni], ql[mi], sbh[ni]);
                mma_fp16(xacc[mi][ni], qh[mi], sbl[ni]);
            }
    }

    // ---- O_intra = P @ V (128x128), 2 terms ----
    float oacc[2][4][4];
    #pragma unroll
    for (int mi = 0; mi < 2; mi++)
        #pragma unroll
        for (int ni = 0; ni < 4; ni++)
            #pragma unroll
            for (int e = 0; e < 4; e++) oacc[mi][ni][e] = 0.0f;

    #pragma unroll
    for (int ks = 0; ks < 8; ks++) {
        uint32_t ph[2][4], pl[2][4];
        #pragma unroll
        for (int mi = 0; mi < 2; mi++) {
            int r = wm + mi * 16 + (lane & 15);
            int cc = ks * 2 + (lane >> 4);
            ldsm4(ph[mi], sPh + SW256(r, cc));
            ldsm4(pl[mi], sPl + SW256(r, cc));
        }
        uint32_t vb[4][2];
        #pragma unroll
        for (int np = 0; np < 2; np++) {
            int row = ks * 16 + ((lane >> 3) & 1) * 8 + (lane & 7);
            int cn  = (wn + np * 16 + (lane >> 4) * 8) >> 3;
            uint32_t rh[4];
            ldsm4t(rh, sV + SW256(row, cn));
            vb[2*np][0] = rh[0]; vb[2*np][1] = rh[1];
            vb[2*np+1][0] = rh[2]; vb[2*np+1][1] = rh[3];
        }
        #pragma unroll
        for (int mi = 0; mi < 2; mi++)
            #pragma unroll
            for (int ni = 0; ni < 4; ni++) {
                mma_fp16(oacc[mi][ni], ph[mi], vb[ni]);
                mma_fp16(oacc[mi][ni], pl[mi], vb[ni]);
            }
    }

    // ---- combine + write O ----
    float* Og = g_O + (size_t)(b * LQ + trow) * VDIMQ + h * DVQ + vh * 128;
    #pragma unroll
    for (int mi = 0; mi < 2; mi++) {
        int r0 = wm + mi * 16 + (lane >> 2);
        float lam0 = exp2f(sdec * (float)r0);
        float lam1 = exp2f(sdec * (float)(r0 + 8));
        #pragma unroll
        for (int ni = 0; ni < 4; ni++) {
            int col = wn + ni * 8 + 2 * (lane & 3);
            *(float2*)(Og + (size_t)r0 * VDIMQ + col) =
                make_float2(oacc[mi][ni][0] + lam0 * xacc[mi][ni][0],
                            oacc[mi][ni][1] + lam0 * xacc[mi][ni][1]);
            *(float2*)(Og + (size_t)(r0 + 8) * VDIMQ + col) =
                make_float2(oacc[mi][ni][2] + lam1 * xacc[mi][ni][2],
                            oacc[mi][ni][3] + lam1 * xacc[mi][ni][3]);
        }
    }
}

// ---------------------------------------------------------------------------
// Fused RMSNorm + swish gate -> fp16 (hi only)
// ---------------------------------------------------------------------------
__global__ void __launch_bounds__(256) normgate_split_kernel(const float* __restrict__ gw)
{
    const int warp = (blockIdx.x << 3) + (threadIdx.x >> 5);
    const int lane = threadIdx.x & 31;
    const size_t base = (size_t)(warp >> 3) * VDIMQ + (size_t)(warp & 7) * DVQ;
    const float* Op = g_O + base;
    const float* Gp = g_G + base;
    __half* Oh = g_O_hi + base;

    const int d0 = lane * 4;
    const int d1 = 128 + lane * 4;
    float4 o0 = *(const float4*)(Op + d0);
    float4 o1 = *(const float4*)(Op + d1);

    float ss = o0.x*o0.x + o0.y*o0.y + o0.z*o0.z + o0.w*o0.w
             + o1.x*o1.x + o1.y*o1.y + o1.z*o1.z + o1.w*o1.w;
    #pragma unroll
    for (int off = 16; off > 0; off >>= 1)
        ss += __shfl_xor_sync(0xFFFFFFFFu, ss, off);

    const float r = rsqrtf(ss * (1.0f / 256.0f) + 1e-5f);

    float4 g0 = *(const float4*)(Gp + d0);
    float4 g1 = *(const float4*)(Gp + d1);
    float4 w0 = *(const float4*)(gw + d0);
    float4 w1 = *(const float4*)(gw + d1);

    float v[8];
    v[0] = o0.x * r * w0.x * (g0.x / (1.0f + expf(-g0.x)));
    v[1] = o0.y * r * w0.y * (g0.y / (1.0f + expf(-g0.y)));
    v[2] = o0.z * r * w0.z * (g0.z / (1.0f + expf(-g0.z)));
    v[3] = o0.w * r * w0.w * (g0.w / (1.0f + expf(-g0.w)));
    v[4] = o1.x * r * w1.x * (g1.x / (1.0f + expf(-g1.x)));
    v[5] = o1.y * r * w1.y * (g1.y / (1.0f + expf(-g1.y)));
    v[6] = o1.z * r * w1.z * (g1.z / (1.0f + expf(-g1.z)));
    v[7] = o1.w * r * w1.w * (g1.w / (1.0f + expf(-g1.w)));

    *(__half2*)(Oh + d0)     = __floats2half2_rn(v[0], v[1]);
    *(__half2*)(Oh + d0 + 2) = __floats2half2_rn(v[2], v[3]);
    *(__half2*)(Oh + d1)     = __floats2half2_rn(v[4], v[5]);
    *(__half2*)(Oh + d1 + 2) = __floats2half2_rn(v[6], v[7]);
}

// ---------------------------------------------------------------------------
// kernel_launch
// ---------------------------------------------------------------------------
extern "C" void kernel_launch(void* const* d_in, const int* in_sizes, int n_in,
                              void* d_out, int out_size)
{
    const float* hs = (const float*)d_in[0];
    const float* Wq = (const float*)d_in[1];
    const float* Wk = (const float*)d_in[2];
    const float* Wv = (const float*)d_in[3];
    const float* Wg = (const float*)d_in[4];
    const float* Wo = (const float*)d_in[5];
    const float* gw = (const float*)d_in[6];
    float* out = (float*)d_out;

    __half *hsh, *hsl;
    __half *qw, *kw, *vw, *gwt, *ow;
    cudaGetSymbolAddress((void**)&hsh, g_hs_hi);
    cudaGetSymbolAddress((void**)&hsl, g_hs_lo);
    cudaGetSymbolAddress((void**)&qw, g_WqT);
    cudaGetSymbolAddress((void**)&kw, g_WkT);
    cudaGetSymbolAddress((void**)&vw, g_WvT);
    cudaGetSymbolAddress((void**)&gwt, g_WgT);
    cudaGetSymbolAddress((void**)&ow, g_WoT);

    cudaFuncSetAttribute(q_gemm,   cudaFuncAttributeMaxDynamicSharedMemorySize, TCG_SMEM_2T);
    cudaFuncSetAttribute(kvg_gemm, cudaFuncAttributeMaxDynamicSharedMemorySize, TCG_SMEM_1T);
    cudaFuncSetAttribute(wo_gemm,  cudaFuncAttributeMaxDynamicSharedMemorySize, TCG_SMEM_1T);
    cudaFuncSetAttribute(chunk_state_kernel, cudaFuncAttributeMaxDynamicSharedMemorySize, ATTA_SMEM);
    cudaFuncSetAttribute(attn_chunk_kernel,  cudaFuncAttributeMaxDynamicSharedMemorySize, ATTC_SMEM);

    dim3 blk(256);

    // 1) prep: hs split + RoPE table + weight transposes
    split_kernel<<<(MROWS*HQ/4 + 255)/256, blk>>>(hs, hsh, hsl, MROWS*HQ/4);
    rope_table_kernel<<<LQ*64/256, blk>>>();
    TDescs ds;
    ds.d[0] = { Wq, qw,  HQ,    HQ,    0    };
    ds.d[1] = { Wk, kw,  HQ,    HQ,    1024 };
    ds.d[2] = { Wv, vw,  HQ,    VDIMQ, 2048 };
    ds.d[3] = { Wg, gwt, HQ,    VDIMQ, 4096 };
    ds.d[4] = { Wo, ow,  VDIMQ, HQ,    6144 };
    transpose_multi<<<8192, blk>>>(ds);

    // 2) projections: KVG first (1-term: 8 K + 16 V + 16 G), then Q (2-term)
    kvg_gemm<<<dim3(40, MROWS/128), blk, TCG_SMEM_1T>>>();
    q_gemm<<<dim3(8, MROWS/128), blk, TCG_SMEM_2T>>>();

    // 3) chunked-recurrent retention: states -> scan -> outputs
    chunk_state_kernel<<<dim3(NCH, 16), 512, ATTA_SMEM>>>();
    scan_kernel<<<dim3(64, 16), 512>>>();
    attn_chunk_kernel<<<dim3(2, NCH, 16), 512, ATTC_SMEM>>>();

    // 4) fused RMSNorm + swish gate (fp16 hi only)
    normgate_split_kernel<<<4096, blk>>>(gw);

    // 5) output projection (1-term)
    wo_gemm<<<dim3(HQ/128, MROWS/128), blk, TCG_SMEM_1T>>>(out);
}

// round 17
// speedup vs baseline: 1.9037x; 1.1262x over previous
#include <cuda_runtime.h>
#include <cuda_fp16.h>
#include <math.h>
#include <stdint.h>

// Problem constants
#define BQ 2
#define LQ 2048
#define HQ 1024
#define NHQ 8
#define DQKQ 128
#define DVQ 256
#define VDIMQ 2048
#define MROWS (BQ*LQ)   // 4096
#define CHK 128         // retention chunk size
#define NCH (LQ/CHK)    // 16 chunks per sequence

#define QSCALE 0.08838834764831843f          // 128^-0.5
#define RF (-0.20762050593045852f)           // -2*log2(10000)/128

// ---------------------------------------------------------------------------
// Scratch (device globals)
// ---------------------------------------------------------------------------
__device__ float g_G[MROWS*VDIMQ];
__device__ float g_O[MROWS*VDIMQ];
__device__ float g_A[16*NCH*DQKQ*DVQ];            // per-chunk KV outer products
__device__ float2 g_rope[LQ*64];                  // (cos, sin) per (t, pair)

__device__ __half g_hs16[MROWS*HQ];
__device__ __half g_O_hi[MROWS*VDIMQ];
__device__ __half g_Qhi[MROWS*HQ];
__device__ __half g_Khi[MROWS*HQ];
__device__ __half g_Kdec[MROWS*HQ];               // K * lam^(CHK - r%CHK)
__device__ __half g_Vhi[MROWS*VDIMQ];
__device__ __half g_Shi[16*NCH*DQKQ*DVQ];         // chunk-entry states hi
__device__ __half g_Slo[16*NCH*DQKQ*DVQ];         // chunk-entry states lo
__device__ __half g_WqT[HQ*HQ];
__device__ __half g_WkT[HQ*HQ];
__device__ __half g_WvT[VDIMQ*HQ];
__device__ __half g_WgT[VDIMQ*HQ];
__device__ __half g_WoT[HQ*VDIMQ];

// ---------------------------------------------------------------------------
// PTX helpers
// ---------------------------------------------------------------------------
__device__ __forceinline__ uint32_t smem_u32(const void* p) {
    uint32_t a;
    asm("{ .reg .u64 t; cvta.to.shared.u64 t, %1; cvt.u32.u64 %0, t; }"
        : "=r"(a) : "l"(p));
    return a;
}
__device__ __forceinline__ void ldgsts16(uint32_t dst, const void* src) {
    asm volatile("cp.async.cg.shared.global [%0], [%1], 16;" :: "r"(dst), "l"(src));
}
__device__ __forceinline__ void cp_commit() {
    asm volatile("cp.async.commit_group;" ::: "memory");
}
template<int N_>
__device__ __forceinline__ void cp_wait() {
    asm volatile("cp.async.wait_group %0;" :: "n"(N_) : "memory");
}
__device__ __forceinline__ void ldsm4(uint32_t* r, uint32_t addr) {
    asm volatile("ldmatrix.sync.aligned.m8n8.x4.shared.b16 {%0,%1,%2,%3}, [%4];"
        : "=r"(r[0]), "=r"(r[1]), "=r"(r[2]), "=r"(r[3]) : "r"(addr));
}
__device__ __forceinline__ void ldsm4t(uint32_t* r, uint32_t addr) {
    asm volatile("ldmatrix.sync.aligned.m8n8.x4.trans.shared.b16 {%0,%1,%2,%3}, [%4];"
        : "=r"(r[0]), "=r"(r[1]), "=r"(r[2]), "=r"(r[3]) : "r"(addr));
}
__device__ __forceinline__ void sts32(uint32_t addr, uint32_t v) {
    asm volatile("st.shared.b32 [%0], %1;" :: "r"(addr), "r"(v) : "memory");
}
__device__ __forceinline__ void mma_fp16(float* c, const uint32_t* a, const uint32_t* b) {
    asm volatile("mma.sync.aligned.m16n8k16.row.col.f32.f16.f16.f32 "
        "{%0,%1,%2,%3}, {%4,%5,%6,%7}, {%8,%9}, {%0,%1,%2,%3};"
        : "+f"(c[0]), "+f"(c[1]), "+f"(c[2]), "+f"(c[3])
        : "r"(a[0]), "r"(a[1]), "r"(a[2]), "r"(a[3]), "r"(b[0]), "r"(b[1]));
}
__device__ __forceinline__ uint32_t pack_h2(float a, float b) {
    __half2 t = __floats2half2_rn(a, b);
    return *(uint32_t*)&t;
}

// Swizzles: row stride in bytes; 16B chunk xor'd by (r&7)
#define SW128R(r, c) ((uint32_t)((r) * 128u + ((uint32_t)((c) ^ ((r) & 7)) << 4)))
#define SW256(r, c)  ((uint32_t)((r) * 256u + ((uint32_t)((c) ^ ((r) & 7)) << 4)))
#define SW512(r, c)  ((uint32_t)((r) * 512u + ((uint32_t)((c) ^ ((r) & 7)) << 4)))

// GEMM (all 1-term): A 16KB | B 16KB per stage; 2 stages = 64KB; 2 CTAs/SM.
#define GST_B   16384u
#define G_STAGE 32768u
#define TCG_SMEM (2 * 32768)

// ---------------------------------------------------------------------------
// hs convert -> fp16
// ---------------------------------------------------------------------------
__global__ void __launch_bounds__(256) hs_convert_kernel(const float* __restrict__ x,
                                                         __half* __restrict__ hi,
                                                         int n4)
{
    int i = blockIdx.x * 256 + threadIdx.x;
    if (i >= n4) return;
    float4 v = ((const float4*)x)[i];
    ((__half2*)hi)[2*i]   = __floats2half2_rn(v.x, v.y);
    ((__half2*)hi)[2*i+1] = __floats2half2_rn(v.z, v.w);
}

// ---------------------------------------------------------------------------
// RoPE table
// ---------------------------------------------------------------------------
__global__ void __launch_bounds__(256) rope_table_kernel()
{
    int i = blockIdx.x * 256 + threadIdx.x;    // 0..131071
    int t = i >> 6, p = i & 63;
    float inv = exp2f((float)p * RF);
    float s, c;
    sincosf((float)t * inv, &s, &c);
    g_rope[i] = make_float2(c, s);
}

// ---------------------------------------------------------------------------
// Merged weight transpose (fp16): one launch for all 5 weights.
// ---------------------------------------------------------------------------
struct TDesc { const float* W; __half* hi; int K, N, start; };
struct TDescs { TDesc d[5]; };

__global__ void __launch_bounds__(256) transpose_multi(TDescs ds)
{
    __shared__ float s[32][33];
    int t = blockIdx.x;
    int i = 0;
    #pragma unroll
    for (int j = 1; j < 5; j++) if (t >= ds.d[j].start) i = j;
    const float* W = ds.d[i].W;
    __half* Th = ds.d[i].hi;
    const int K = ds.d[i].K, N = ds.d[i].N;
    int lt = t - ds.d[i].start;
    int ncols = N >> 5;
    int k0 = (lt / ncols) * 32;
    int n0 = (lt % ncols) * 32;

    const int tx = threadIdx.x & 31;
    const int ty = threadIdx.x >> 5;
    #pragma unroll
    for (int q = 0; q < 4; q++)
        s[ty + 8*q][tx] = W[(size_t)(k0 + ty + 8*q) * N + n0 + tx];
    __syncthreads();
    #pragma unroll
    for (int q = 0; q < 4; q++) {
        float v = s[tx][ty + 8*q];
        Th[(size_t)(n0 + ty + 8*q) * K + k0 + tx] = __float2half(v);
    }
}

// ---------------------------------------------------------------------------
// GEMM mainloop (1-term fp16): 128x128 tile, 8 warps (64x32), K-chunk 64,
// 2-stage pipeline.
// ---------------------------------------------------------------------------
struct GemmOps {
    const __half *Ah, *Bh;
    int K, row0, bcol0;
};

__device__ __forceinline__ void gemm_mainloop(const GemmOps& op, uint32_t sbase,
                                              float acc[4][4][4])
{
    const int tid  = threadIdx.x;
    const int wid  = tid >> 5;
    const int lane = tid & 31;
    const int wm   = (wid & 1) * 64;
    const int wn   = (wid >> 1) * 32;
    const int K    = op.K;
    const int nchunks = K >> 6;

    auto load_chunk = [&](uint32_t sb, int k0) {
        #pragma unroll
        for (int t = 0; t < 4; t++) {
            int idx = tid + t * 256;
            int r   = idx >> 3;
            int c   = idx & 7;
            uint32_t soff = SW128R(r, c);
            ldgsts16(sb + soff,         op.Ah + (size_t)(op.row0 + r) * K + k0 + c * 8);
            ldgsts16(sb + GST_B + soff, op.Bh + (size_t)(op.bcol0 + r) * K + k0 + c * 8);
        }
        cp_commit();
    };

    load_chunk(sbase, 0);
    if (nchunks > 1) load_chunk(sbase + G_STAGE, 64);

    for (int cch = 0; cch < nchunks; cch++) {
        const uint32_t sb = sbase + (uint32_t)(cch & 1) * G_STAGE;
        if (cch + 1 < nchunks) {
            cp_wait<1>();
        } else {
            cp_wait<0>();
        }
        __syncthreads();

        #pragma unroll
        for (int ks = 0; ks < 4; ks++) {
            uint32_t ahi[4][4];
            #pragma unroll
            for (int mi = 0; mi < 4; mi++) {
                int r = wm + mi * 16 + (lane & 15);
                int c = ks * 2 + (lane >> 4);
                ldsm4(ahi[mi], sb + SW128R(r, c));
            }
            uint32_t bhi[4][2];
            #pragma unroll
            for (int j = 0; j < 2; j++) {
                int m4 = lane >> 3;
                int n  = wn + j * 16 + ((m4 >> 1) << 3) + (lane & 7);
                int c  = ks * 2 + (m4 & 1);
                uint32_t rh[4];
                ldsm4(rh, sb + GST_B + SW128R(n, c));
                bhi[2*j][0] = rh[0]; bhi[2*j][1] = rh[1];
                bhi[2*j+1][0] = rh[2]; bhi[2*j+1][1] = rh[3];
            }
            #pragma unroll
            for (int mi = 0; mi < 4; mi++)
                #pragma unroll
                for (int ni = 0; ni < 4; ni++)
                    mma_fp16(acc[mi][ni], ahi[mi], bhi[ni]);
        }
        __syncthreads();
        if (cch + 2 < nchunks) load_chunk(sb, (cch + 2) * 64);
    }
}

// ---------------------------------------------------------------------------
// QKVG GEMM (all 1-term): grid (48, 32).
// cb<8: Q (scale+RoPE) | cb<16: K (+Kdec) | cb<32: V | else: G (fp32)
// ---------------------------------------------------------------------------
__global__ void __launch_bounds__(256, 2) qkvg_gemm()
{
    extern __shared__ char smem[];
    const uint32_t sbase = smem_u32(smem);
    const int tid  = threadIdx.x;
    const int wid  = tid >> 5;
    const int lane = tid & 31;
    const int row0 = blockIdx.y * 128;
    const int cb   = blockIdx.x;
    const int wm   = (wid & 1) * 64;
    const int wn   = (wid >> 1) * 32;

    int mode, lcol0;
    const __half* Bh;
    if (cb < 8)       { mode = 0; lcol0 = cb * 128;        Bh = g_WqT; }
    else if (cb < 16) { mode = 1; lcol0 = (cb - 8) * 128;  Bh = g_WkT; }
    else if (cb < 32) { mode = 2; lcol0 = (cb - 16) * 128; Bh = g_WvT; }
    else              { mode = 3; lcol0 = (cb - 32) * 128; Bh = g_WgT; }

    float acc[4][4][4];
    #pragma unroll
    for (int mi = 0; mi < 4; mi++)
        #pragma unroll
        for (int ni = 0; ni < 4; ni++)
            #pragma unroll
            for (int e = 0; e < 4; e++) acc[mi][ni][e] = 0.0f;

    GemmOps op{ g_hs16, Bh, HQ, row0, lcol0 };
    gemm_mainloop(op, sbase, acc);

    float sdecK = 0.0f;
    if (mode == 1) sdecK = log2f(1.0f - exp2f(-5.0f - (float)(cb - 8)));

    #pragma unroll
    for (int mi = 0; mi < 4; mi++) {
        const int row = row0 + wm + mi * 16 + (lane >> 2);
        #pragma unroll
        for (int ni = 0; ni < 4; ni++) {
            const int col = lcol0 + wn + ni * 8 + 2 * (lane & 3);
            float v0 = acc[mi][ni][0], v1 = acc[mi][ni][1];
            float v2 = acc[mi][ni][2], v3 = acc[mi][ni][3];
            if (mode <= 1) {   // Q or K: (scale+) RoPE
                if (mode == 0) { v0 *= QSCALE; v1 *= QSCALE; v2 *= QSCALE; v3 *= QSCALE; }
                const int p = (col & 127) >> 1;
                float2 cs0 = g_rope[(row & (LQ - 1)) * 64 + p];
                float2 cs1 = g_rope[((row + 8) & (LQ - 1)) * 64 + p];
                float x0 = v0, x1 = v1;
                v0 = x0 * cs0.x - x1 * cs0.y;
                v1 = x1 * cs0.x + x0 * cs0.y;
                x0 = v2; x1 = v3;
                v2 = x0 * cs1.x - x1 * cs1.y;
                v3 = x1 * cs1.x + x0 * cs1.y;
                if (mode == 0) {
                    *(__half2*)(g_Qhi + (size_t)row * HQ + col)       = __floats2half2_rn(v0, v1);
                    *(__half2*)(g_Qhi + (size_t)(row + 8) * HQ + col) = __floats2half2_rn(v2, v3);
                } else {
                    *(__half2*)(g_Khi + (size_t)row * HQ + col)       = __floats2half2_rn(v0, v1);
                    *(__half2*)(g_Khi + (size_t)(row + 8) * HQ + col) = __floats2half2_rn(v2, v3);
                    float p0 = exp2f(sdecK * (float)(CHK - (row & (CHK - 1))));
                    float p1 = exp2f(sdecK * (float)(CHK - ((row + 8) & (CHK - 1))));
                    *(__half2*)(g_Kdec + (size_t)row * HQ + col)       = __floats2half2_rn(v0 * p0, v1 * p0);
                    *(__half2*)(g_Kdec + (size_t)(row + 8) * HQ + col) = __floats2half2_rn(v2 * p1, v3 * p1);
                }
            } else if (mode == 2) {   // V: fp16
                *(__half2*)(g_Vhi + (size_t)row * VDIMQ + col)       = __floats2half2_rn(v0, v1);
                *(__half2*)(g_Vhi + (size_t)(row + 8) * VDIMQ + col) = __floats2half2_rn(v2, v3);
            } else {                  // G: fp32
                *(float2*)(g_G + (size_t)row * VDIMQ + col)       = make_float2(v0, v1);
                *(float2*)(g_G + (size_t)(row + 8) * VDIMQ + col) = make_float2(v2, v3);
            }
        }
    }
}

// ---------------------------------------------------------------------------
// Wo GEMM (1-term): fp32 out. K=2048, N=1024.
// ---------------------------------------------------------------------------
__global__ void __launch_bounds__(256, 2) wo_gemm(float* __restrict__ C)
{
    extern __shared__ char smem[];
    const uint32_t sbase = smem_u32(smem);
    const int tid  = threadIdx.x;
    const int wid  = tid >> 5;
    const int lane = tid & 31;
    const int row0 = blockIdx.y * 128;
    const int col0 = blockIdx.x * 128;
    const int wm   = (wid & 1) * 64;
    const int wn   = (wid >> 1) * 32;

    float acc[4][4][4];
    #pragma unroll
    for (int mi = 0; mi < 4; mi++)
        #pragma unroll
        for (int ni = 0; ni < 4; ni++)
            #pragma unroll
            for (int e = 0; e < 4; e++) acc[mi][ni][e] = 0.0f;

    GemmOps op{ g_O_hi, g_WoT, VDIMQ, row0, col0 };
    gemm_mainloop(op, sbase, acc);

    #pragma unroll
    for (int mi = 0; mi < 4; mi++) {
        const int row = row0 + wm + mi * 16 + (lane >> 2);
        #pragma unroll
        for (int ni = 0; ni < 4; ni++) {
            const int col = col0 + wn + ni * 8 + 2 * (lane & 3);
            *(float2*)(C + (size_t)row * HQ + col) =
                make_float2(acc[mi][ni][0], acc[mi][ni][1]);
            *(float2*)(C + (size_t)(row + 8) * HQ + col) =
                make_float2(acc[mi][ni][2], acc[mi][ni][3]);
        }
    }
}

// ---------------------------------------------------------------------------
// Attention Kernel A: per-chunk outer product  A_c = Kdec_c^T V_c
// ---------------------------------------------------------------------------
#define ATTA_SMEM 98304

__global__ void __launch_bounds__(512) chunk_state_kernel()
{
    extern __shared__ char smem[];
    const uint32_t SB   = smem_u32(smem);
    const uint32_t kbuf = SB;            // [128 r][128 d1] fp16 SW256
    const uint32_t vbuf = SB + 32768;    // [128 r][256 d2] fp16 SW512

    const int ch = blockIdx.x, bh = blockIdx.y;
    const int b = bh >> 3, h = bh & 7;
    const int tid = threadIdx.x, wid = tid >> 5, lane = tid & 31;
    const int trow = ch * CHK;

    const __half* Kd_g = g_Kdec + (size_t)(b * LQ + trow) * HQ + h * DQKQ;
    const __half* Vh_g = g_Vhi + (size_t)(b * LQ + trow) * VDIMQ + h * DVQ;

    #pragma unroll
    for (int t = 0; t < 4; t++) {
        int idx = tid + t * 512;
        int r = idx >> 4, cc = idx & 15;
        ldgsts16(kbuf + SW256(r, cc), Kd_g + (size_t)r * HQ + cc * 8);
    }
    #pragma unroll
    for (int t = 0; t < 8; t++) {
        int idx = tid + t * 512;
        int r = idx >> 5, cc = idx & 31;
        ldgsts16(vbuf + SW512(r, cc), Vh_g + (size_t)r * VDIMQ + cc * 8);
    }
    cp_commit();
    cp_wait<0>();
    __syncthreads();

    const int wm = (wid & 3) * 32;
    const int wn = (wid >> 2) * 64;

    float acc[2][8][4];
    #pragma unroll
    for (int mi = 0; mi < 2; mi++)
        #pragma unroll
        for (int nt = 0; nt < 8; nt++)
            #pragma unroll
            for (int e = 0; e < 4; e++) acc[mi][nt][e] = 0.0f;

    #pragma unroll
    for (int ks = 0; ks < 8; ks++) {
        uint32_t af[2][4];
        #pragma unroll
        for (int mi = 0; mi < 2; mi++) {
            int m0 = wm + mi * 16;
            int r_src = ks * 16 + ((lane >> 4) << 3) + (lane & 7);
            int d_off = (m0 >> 3) + ((lane >> 3) & 1);
            ldsm4t(af[mi], kbuf + SW256(r_src, d_off));
        }
        uint32_t bf[8][2];
        #pragma unroll
        for (int np = 0; np < 4; np++) {
            int row = ks * 16 + ((lane >> 3) & 1) * 8 + (lane & 7);
            int cn  = (wn + np * 16 + (lane >> 4) * 8) >> 3;
            uint32_t rh[4];
            ldsm4t(rh, vbuf + SW512(row, cn));
            bf[2*np][0] = rh[0]; bf[2*np][1] = rh[1];
            bf[2*np+1][0] = rh[2]; bf[2*np+1][1] = rh[3];
        }
        #pragma unroll
        for (int mi = 0; mi < 2; mi++)
            #pragma unroll
            for (int nt = 0; nt < 8; nt++)
                mma_fp16(acc[mi][nt], af[mi], bf[nt]);
    }

    float* Ag = g_A + ((size_t)(bh * NCH + ch) << 15);
    #pragma unroll
    for (int mi = 0; mi < 2; mi++) {
        int d1 = wm + mi * 16 + (lane >> 2);
        #pragma unroll
        for (int nt = 0; nt < 8; nt++) {
            int d2 = wn + nt * 8 + 2 * (lane & 3);
            *(float2*)(Ag + (size_t)d1 * DVQ + d2) =
                make_float2(acc[mi][nt][0], acc[mi][nt][1]);
            *(float2*)(Ag + (size_t)(d1 + 8) * DVQ + d2) =
                make_float2(acc[mi][nt][2], acc[mi][nt][3]);
        }
    }
}

// ---------------------------------------------------------------------------
// Attention Kernel B: per-element decay scan over chunks -> states S_c (hi/lo)
// ---------------------------------------------------------------------------
__global__ void __launch_bounds__(512) scan_kernel()
{
    const int e  = blockIdx.x * 512 + threadIdx.x;
    const int bh = blockIdx.y;
    const int h  = bh & 7;
    const float sdec = log2f(1.0f - exp2f(-5.0f - (float)h));
    const float lamC = exp2f(sdec * (float)CHK);

    const size_t base = (size_t)bh * NCH << 15;
    float S = 0.0f;
    #pragma unroll
    for (int c = 0; c < NCH; c++) {
        size_t off = base + ((size_t)c << 15) + e;
        __half hi = __float2half(S);
        g_Shi[off] = hi;
        g_Slo[off] = __float2half(S - __half2float(hi));
        S = S * lamC + g_A[off];
    }
}

// ---------------------------------------------------------------------------
// Attention Kernel C: per (chunk, bh, dv-half) output.
// O = (QK^T ∘ decay) V + lam^r (Q S_c).  Q 1-term; S hi/lo; P hi/lo.
// SMEM: Q 32K | K 32K (→aliased Ph) | Sh 32K | Sl 32K | V 32K | Pl 32K = 192K
// ---------------------------------------------------------------------------
#define ATTC_SMEM 196608

__global__ void __launch_bounds__(512) attn_chunk_kernel()
{
    extern __shared__ char smem[];
    const uint32_t SB  = smem_u32(smem);
    const uint32_t sQh = SB;
    const uint32_t sK  = SB + 32768;
    const uint32_t sSh = SB + 65536;
    const uint32_t sSl = SB + 98304;
    const uint32_t sV  = SB + 131072;
    const uint32_t sPl = SB + 163840;
    const uint32_t sPh = sK;            // aliased after K consumed

    const int vh = blockIdx.x;
    const int ch = blockIdx.y;
    const int bh = blockIdx.z;
    const int b = bh >> 3, h = bh & 7;
    const int tid = threadIdx.x, wid = tid >> 5, lane = tid & 31;
    const int trow = ch * CHK;
    const float sdec = log2f(1.0f - exp2f(-5.0f - (float)h));

    const __half* Qh_g = g_Qhi + (size_t)(b * LQ + trow) * HQ + h * DQKQ;
    const __half* Kh_g = g_Khi + (size_t)(b * LQ + trow) * HQ + h * DQKQ;
    const __half* Vh_g = g_Vhi + (size_t)(b * LQ + trow) * VDIMQ + h * DVQ + vh * 128;
    const __half* Sh_g = g_Shi + ((size_t)(bh * NCH + ch) << 15) + vh * 128;
    const __half* Sl_g = g_Slo + ((size_t)(bh * NCH + ch) << 15) + vh * 128;

    #pragma unroll
    for (int t = 0; t < 4; t++) {
        int idx = tid + t * 512;
        int r = idx >> 4, cc = idx & 15;
        ldgsts16(sQh + SW256(r, cc), Qh_g + (size_t)r * HQ + cc * 8);
        ldgsts16(sK  + SW256(r, cc), Kh_g + (size_t)r * HQ + cc * 8);
    }
    cp_commit();
    #pragma unroll
    for (int t = 0; t < 4; t++) {
        int idx = tid + t * 512;
        int r = idx >> 4, cc = idx & 15;
        ldgsts16(sSh + SW256(r, cc), Sh_g + (size_t)r * DVQ + cc * 8);
        ldgsts16(sSl + SW256(r, cc), Sl_g + (size_t)r * DVQ + cc * 8);
        ldgsts16(sV  + SW256(r, cc), Vh_g + (size_t)r * VDIMQ + cc * 8);
    }
    cp_commit();

    const int wm = (wid & 3) * 32;
    const int wn = (wid >> 2) * 32;

    cp_wait<1>();
    __syncthreads();

    // ---- P = Q K^T (128x128), 1 term ----
    float sacc[2][4][4];
    #pragma unroll
    for (int mi = 0; mi < 2; mi++)
        #pragma unroll
        for (int ni = 0; ni < 4; ni++)
            #pragma unroll
            for (int e = 0; e < 4; e++) sacc[mi][ni][e] = 0.0f;

    #pragma unroll
    for (int ks = 0; ks < 8; ks++) {
        uint32_t qh[2][4];
        #pragma unroll
        for (int mi = 0; mi < 2; mi++) {
            int r = wm + mi * 16 + (lane & 15);
            int cc = ks * 2 + (lane >> 4);
            ldsm4(qh[mi], sQh + SW256(r, cc));
        }
        uint32_t kb[4][2];
        #pragma unroll
        for (int j = 0; j < 2; j++) {
            int m4 = lane >> 3;
            int n  = wn + j * 16 + ((m4 >> 1) << 3) + (lane & 7);
            int cc = ks * 2 + (m4 & 1);
            uint32_t rh[4];
            ldsm4(rh, sK + SW256(n, cc));
            kb[2*j][0] = rh[0]; kb[2*j][1] = rh[1];
            kb[2*j+1][0] = rh[2]; kb[2*j+1][1] = rh[3];
        }
        #pragma unroll
        for (int mi = 0; mi < 2; mi++)
            #pragma unroll
            for (int ni = 0; ni < 4; ni++)
                mma_fp16(sacc[mi][ni], qh[mi], kb[ni]);
    }
    __syncthreads();

    // ---- decay + causal + split -> store P hi/lo ----
    #pragma unroll
    for (int mi = 0; mi < 2; mi++) {
        int r0 = wm + mi * 16 + (lane >> 2);
        #pragma unroll
        for (int ni = 0; ni < 4; ni++) {
            int j0 = wn + ni * 8 + 2 * (lane & 3);
            float d00 = (r0 >= j0)         ? exp2f(sdec * (float)(r0 - j0))     : 0.0f;
            float d01 = (r0 >= j0 + 1)     ? exp2f(sdec * (float)(r0 - j0 - 1)) : 0.0f;
            float d10 = (r0 + 8 >= j0)     ? exp2f(sdec * (float)(r0 + 8 - j0))     : 0.0f;
            float d11 = (r0 + 8 >= j0 + 1) ? exp2f(sdec * (float)(r0 + 8 - j0 - 1)) : 0.0f;
            float v0 = sacc[mi][ni][0] * d00, v1 = sacc[mi][ni][1] * d01;
            float v2 = sacc[mi][ni][2] * d10, v3 = sacc[mi][ni][3] * d11;
            float h0 = __half2float(__float2half(v0));
            float h1 = __half2float(__float2half(v1));
            float h2 = __half2float(__float2half(v2));
            float h3 = __half2float(__float2half(v3));
            int cc = j0 >> 3;
            int off = (j0 & 7) * 2;
            sts32(sPh + SW256(r0, cc) + off,     pack_h2(v0, v1));
            sts32(sPl + SW256(r0, cc) + off,     pack_h2(v0 - h0, v1 - h1));
            sts32(sPh + SW256(r0 + 8, cc) + off, pack_h2(v2, v3));
            sts32(sPl + SW256(r0 + 8, cc) + off, pack_h2(v2 - h2, v3 - h3));
        }
    }
    cp_wait<0>();
    __syncthreads();

    // ---- X = Q @ S (128x128), 2 terms (S hi/lo) ----
    float xacc[2][4][4];
    #pragma unroll
    for (int mi = 0; mi < 2; mi++)
        #pragma unroll
        for (int ni = 0; ni < 4; ni++)
            #pragma unroll
            for (int e = 0; e < 4; e++) xacc[mi][ni][e] = 0.0f;

    #pragma unroll
    for (int ks = 0; ks < 8; ks++) {
        uint32_t qh[2][4];
        #pragma unroll
        for (int mi = 0; mi < 2; mi++) {
            int r = wm + mi * 16 + (lane & 15);
            int cc = ks * 2 + (lane >> 4);
            ldsm4(qh[mi], sQh + SW256(r, cc));
        }
        uint32_t sbh[4][2], sbl[4][2];
        #pragma unroll
        for (int np = 0; np < 2; np++) {
            int row = ks * 16 + ((lane >> 3) & 1) * 8 + (lane & 7);
            int cn  = (wn + np * 16 + (lane >> 4) * 8) >> 3;
            uint32_t rh[4], rl[4];
            ldsm4t(rh, sSh + SW256(row, cn));
            ldsm4t(rl, sSl + SW256(row, cn));
            sbh[2*np][0] = rh[0]; sbh[2*np][1] = rh[1];
            sbh[2*np+1][0] = rh[2]; sbh[2*np+1][1] = rh[3];
            sbl[2*np][0] = rl[0]; sbl[2*np][1] = rl[1];
            sbl[2*np+1][0] = rl[2]; sbl[2*np+1][1] = rl[3];
        }
        #pragma unroll
        for (int mi = 0; mi < 2; mi++)
            #pragma unroll
            for (int ni = 0; ni < 4; ni++) {
                mma_fp16(xacc[mi][ni], qh[mi], sbh[ni]);
                mma_fp16(xacc[mi][ni], qh[mi], sbl[ni]);
            }
    }

    // ---- O_intra = P @ V (128x128), 2 terms (P hi/lo) ----
    float oacc[2][4][4];
    #pragma unroll
    for (int mi = 0; mi < 2; mi++)
        #pragma unroll
        for (int ni = 0; ni < 4; ni++)
            #pragma unroll
            for (int e = 0; e < 4; e++) oacc[mi][ni][e] = 0.0f;

    #pragma unroll
    for (int ks = 0; ks < 8; ks++) {
        uint32_t ph[2][4], pl[2][4];
        #pragma unroll
        for (int mi = 0; mi < 2; mi++) {
            int r = wm + mi * 16 + (lane & 15);
            int cc = ks * 2 + (lane >> 4);
            ldsm4(ph[mi], sPh + SW256(r, cc));
            ldsm4(pl[mi], sPl + SW256(r, cc));
        }
        uint32_t vb[4][2];
        #pragma unroll
        for (int np = 0; np < 2; np++) {
            int row = ks * 16 + ((lane >> 3) & 1) * 8 + (lane & 7);
            int cn  = (wn + np * 16 + (lane >> 4) * 8) >> 3;
            uint32_t rh[4];
            ldsm4t(rh, sV + SW256(row, cn));
            vb[2*np][0] = rh[0]; vb[2*np][1] = rh[1];
            vb[2*np+1][0] = rh[2]; vb[2*np+1][1] = rh[3];
        }
        #pragma unroll
        for (int mi = 0; mi < 2; mi++)
            #pragma unroll
            for (int ni = 0; ni < 4; ni++) {
                mma_fp16(oacc[mi][ni], ph[mi], vb[ni]);
                mma_fp16(oacc[mi][ni], pl[mi], vb[ni]);
            }
    }

    // ---- combine + write O ----
    float* Og = g_O + (size_t)(b * LQ + trow) * VDIMQ + h * DVQ + vh * 128;
    #pragma unroll
    for (int mi = 0; mi < 2; mi++) {
        int r0 = wm + mi * 16 + (lane >> 2);
        float lam0 = exp2f(sdec * (float)r0);
        float lam1 = exp2f(sdec * (float)(r0 + 8));
        #pragma unroll
        for (int ni = 0; ni < 4; ni++) {
            int col = wn + ni * 8 + 2 * (lane & 3);
            *(float2*)(Og + (size_t)r0 * VDIMQ + col) =
                make_float2(oacc[mi][ni][0] + lam0 * xacc[mi][ni][0],
                            oacc[mi][ni][1] + lam0 * xacc[mi][ni][1]);
            *(float2*)(Og + (size_t)(r0 + 8) * VDIMQ + col) =
                make_float2(oacc[mi][ni][2] + lam1 * xacc[mi][ni][2],
                            oacc[mi][ni][3] + lam1 * xacc[mi][ni][3]);
        }
    }
}

// ---------------------------------------------------------------------------
// Fused RMSNorm + swish gate -> fp16 (hi only)
// ---------------------------------------------------------------------------
__global__ void __launch_bounds__(256) normgate_split_kernel(const float* __restrict__ gw)
{
    const int warp = (blockIdx.x << 3) + (threadIdx.x >> 5);
    const int lane = threadIdx.x & 31;
    const size_t base = (size_t)(warp >> 3) * VDIMQ + (size_t)(warp & 7) * DVQ;
    const float* Op = g_O + base;
    const float* Gp = g_G + base;
    __half* Oh = g_O_hi + base;

    const int d0 = lane * 4;
    const int d1 = 128 + lane * 4;
    float4 o0 = *(const float4*)(Op + d0);
    float4 o1 = *(const float4*)(Op + d1);

    float ss = o0.x*o0.x + o0.y*o0.y + o0.z*o0.z + o0.w*o0.w
             + o1.x*o1.x + o1.y*o1.y + o1.z*o1.z + o1.w*o1.w;
    #pragma unroll
    for (int off = 16; off > 0; off >>= 1)
        ss += __shfl_xor_sync(0xFFFFFFFFu, ss, off);

    const float r = rsqrtf(ss * (1.0f / 256.0f) + 1e-5f);

    float4 g0 = *(const float4*)(Gp + d0);
    float4 g1 = *(const float4*)(Gp + d1);
    float4 w0 = *(const float4*)(gw + d0);
    float4 w1 = *(const float4*)(gw + d1);

    float v[8];
    v[0] = o0.x * r * w0.x * (g0.x / (1.0f + expf(-g0.x)));
    v[1] = o0.y * r * w0.y * (g0.y / (1.0f + expf(-g0.y)));
    v[2] = o0.z * r * w0.z * (g0.z / (1.0f + expf(-g0.z)));
    v[3] = o0.w * r * w0.w * (g0.w / (1.0f + expf(-g0.w)));
    v[4] = o1.x * r * w1.x * (g1.x / (1.0f + expf(-g1.x)));
    v[5] = o1.y * r * w1.y * (g1.y / (1.0f + expf(-g1.y)));
    v[6] = o1.z * r * w1.z * (g1.z / (1.0f + expf(-g1.z)));
    v[7] = o1.w * r * w1.w * (g1.w / (1.0f + expf(-g1.w)));

    *(__half2*)(Oh + d0)     = __floats2half2_rn(v[0], v[1]);
    *(__half2*)(Oh + d0 + 2) = __floats2half2_rn(v[2], v[3]);
    *(__half2*)(Oh + d1)     = __floats2half2_rn(v[4], v[5]);
    *(__half2*)(Oh + d1 + 2) = __floats2half2_rn(v[6], v[7]);
}

// ---------------------------------------------------------------------------
// kernel_launch
// ---------------------------------------------------------------------------
extern "C" void kernel_launch(void* const* d_in, const int* in_sizes, int n_in,
                              void* d_out, int out_size)
{
    const float* hs = (const float*)d_in[0];
    const float* Wq = (const float*)d_in[1];
    const float* Wk = (const float*)d_in[2];
    const float* Wv = (const float*)d_in[3];
    const float* Wg = (const float*)d_in[4];
    const float* Wo = (const float*)d_in[5];
    const float* gw = (const float*)d_in[6];
    float* out = (float*)d_out;

    __half *hsh;
    __half *qw, *kw, *vw, *gwt, *ow;
    cudaGetSymbolAddress((void**)&hsh, g_hs16);
    cudaGetSymbolAddress((void**)&qw, g_WqT);
    cudaGetSymbolAddress((void**)&kw, g_WkT);
    cudaGetSymbolAddress((void**)&vw, g_WvT);
    cudaGetSymbolAddress((void**)&gwt, g_WgT);
    cudaGetSymbolAddress((void**)&ow, g_WoT);

    cudaFuncSetAttribute(qkvg_gemm, cudaFuncAttributeMaxDynamicSharedMemorySize, TCG_SMEM);
    cudaFuncSetAttribute(wo_gemm,   cudaFuncAttributeMaxDynamicSharedMemorySize, TCG_SMEM);
    cudaFuncSetAttribute(chunk_state_kernel, cudaFuncAttributeMaxDynamicSharedMemorySize, ATTA_SMEM);
    cudaFuncSetAttribute(attn_chunk_kernel,  cudaFuncAttributeMaxDynamicSharedMemorySize, ATTC_SMEM);

    dim3 blk(256);

    // 1) prep: hs convert + RoPE table + weight transposes
    hs_convert_kernel<<<(MROWS*HQ/4 + 255)/256, blk>>>(hs, hsh, MROWS*HQ/4);
    rope_table_kernel<<<LQ*64/256, blk>>>();
    TDescs ds;
    ds.d[0] = { Wq, qw,  HQ,    HQ,    0    };
    ds.d[1] = { Wk, kw,  HQ,    HQ,    1024 };
    ds.d[2] = { Wv, vw,  HQ,    VDIMQ, 2048 };
    ds.d[3] = { Wg, gwt, HQ,    VDIMQ, 4096 };
    ds.d[4] = { Wo, ow,  VDIMQ, HQ,    6144 };
    transpose_multi<<<8192, blk>>>(ds);

    // 2) single merged projection launch (all 1-term): Q+K+V+G = 48 blocks
    qkvg_gemm<<<dim3(48, MROWS/128), blk, TCG_SMEM>>>();

    // 3) chunked-recurrent retention: states -> scan -> outputs
    chunk_state_kernel<<<dim3(NCH, 16), 512, ATTA_SMEM>>>();
    scan_kernel<<<dim3(64, 16), 512>>>();
    attn_chunk_kernel<<<dim3(2, NCH, 16), 512, ATTC_SMEM>>>();

    // 4) fused RMSNorm + swish gate (fp16 hi only)
    normgate_split_kernel<<<4096, blk>>>(gw);

    // 5) output projection (1-term)
    wo_gemm<<<dim3(HQ/128, MROWS/128), blk, TCG_SMEM>>>(out);
}